// round 2
// baseline (speedup 1.0000x reference)
#include <cuda_runtime.h>

#define Sx 2048
#define Bx 2
#define Ex 512
#define Hx 8
#define Ix 64
#define Mx 2048
#define Kx 4096          // M + S
#define QKV3 1536
#define FFx 2048
#define ROWS (Sx*Bx)     // 4096
#define KB_ (Kx*Bx)      // 8192
#define KSTR 68          // padded stride (16B aligned, conflict-reducing)
#define EPSF 1e-5f

// ---------------- scratch (static device arrays: no allocation) -------------
__device__ float g_qkv[(size_t)KB_ * QKV3];     // 50.3 MB
__device__ float g_r[(size_t)Kx * Ex];          // 8 MB
__device__ float g_attn[(size_t)ROWS * Ex];     // 8 MB
__device__ float g_tmp[(size_t)ROWS * Ex];      // 8 MB
__device__ float g_attnout[(size_t)ROWS * Ex];  // 8 MB
__device__ float g_ff1[(size_t)ROWS * FFx];     // 32 MB
__device__ float g_ff2[(size_t)ROWS * Ex];      // 8 MB

// ---------------- SGEMM: C(MxN) = A(MxK) * B(KxN), 128x128x8 tiles ----------
// EPI: 0=none, 1=+bias, 2=+bias+relu.  SPLITA: A rows gather from two tensors.
template<int EPI, bool SPLITA>
__global__ __launch_bounds__(256, 2) void sgemm128(
    const float* __restrict__ A0, const float* __restrict__ A1, int splitRow,
    const float* __restrict__ Bm, const float* __restrict__ bias,
    float* __restrict__ C, int Md, int Nd, int Kd)
{
    __shared__ __align__(16) float As[8][128];
    __shared__ __align__(16) float Bs[8][128];
    int tid = threadIdx.x;
    int tx = tid & 15, ty = tid >> 4;
    int bm = blockIdx.y * 128, bn = blockIdx.x * 128;
    int arow = tid >> 1, acol = (tid & 1) * 4;   // A tile load: 128 rows x 8 cols
    int brow = tid >> 5, bcol = (tid & 31) * 4;  // B tile load: 8 rows x 128 cols

    const float* Ap;
    {
        int grow = bm + arow;
        if (SPLITA && grow >= splitRow) Ap = A1 + (size_t)(grow - splitRow) * Kd;
        else                            Ap = A0 + (size_t)grow * Kd;
    }

    float acc[8][8];
#pragma unroll
    for (int i = 0; i < 8; i++)
#pragma unroll
        for (int j = 0; j < 8; j++) acc[i][j] = 0.f;

    for (int k0 = 0; k0 < Kd; k0 += 8) {
        float4 av = *(const float4*)(Ap + k0 + acol);
        As[acol + 0][arow] = av.x;
        As[acol + 1][arow] = av.y;
        As[acol + 2][arow] = av.z;
        As[acol + 3][arow] = av.w;
        *(float4*)&Bs[brow][bcol] =
            *(const float4*)(Bm + (size_t)(k0 + brow) * Nd + bn + bcol);
        __syncthreads();
#pragma unroll
        for (int kk = 0; kk < 8; kk++) {
            float4 a0 = *(const float4*)&As[kk][ty * 8];
            float4 a1 = *(const float4*)&As[kk][ty * 8 + 4];
            float4 b0 = *(const float4*)&Bs[kk][tx * 8];
            float4 b1 = *(const float4*)&Bs[kk][tx * 8 + 4];
            float af[8] = {a0.x, a0.y, a0.z, a0.w, a1.x, a1.y, a1.z, a1.w};
            float bf[8] = {b0.x, b0.y, b0.z, b0.w, b1.x, b1.y, b1.z, b1.w};
#pragma unroll
            for (int i = 0; i < 8; i++)
#pragma unroll
                for (int j = 0; j < 8; j++)
                    acc[i][j] += af[i] * bf[j];
        }
        __syncthreads();
    }

#pragma unroll
    for (int i = 0; i < 8; i++) {
        size_t row = (size_t)(bm + ty * 8 + i);
#pragma unroll
        for (int j = 0; j < 8; j += 4) {
            int col = bn + tx * 8 + j;
            float4 vo;
            vo.x = acc[i][j + 0]; vo.y = acc[i][j + 1];
            vo.z = acc[i][j + 2]; vo.w = acc[i][j + 3];
            if (EPI >= 1) {
                vo.x += bias[col + 0]; vo.y += bias[col + 1];
                vo.z += bias[col + 2]; vo.w += bias[col + 3];
            }
            if (EPI == 2) {
                vo.x = fmaxf(vo.x, 0.f); vo.y = fmaxf(vo.y, 0.f);
                vo.z = fmaxf(vo.z, 0.f); vo.w = fmaxf(vo.w, 0.f);
            }
            *(float4*)(C + row * Nd + col) = vo;
        }
    }
}

// ---------------- Flash attention with Transformer-XL relative shift --------
// score[s,k] = ((q+u)[s]·kk[k] + (q+v)[s]·r[k + S-1-s]) * 0.125, mask k > s+M.
// Per CTA: 64 queries for one (b,h). Key loop: AC GEMM 64x64x64 + BD band GEMM
// 64x128x64 (r rows jlo..jlo+127), combine on diagonal, online softmax, P·V.
__global__ __launch_bounds__(256, 1) void flash_kernel(
    const float* __restrict__ qkv, const float* __restrict__ rbuf,
    const float* __restrict__ u, const float* __restrict__ v,
    float* __restrict__ attn)
{
    extern __shared__ __align__(16) float sm[];
    float* Qu   = sm;                    // 64*64
    float* Qv   = Qu + 64 * 64;          // 64*64
    float* Ksh  = Qv + 64 * 64;          // 64*KSTR
    float* Vsh  = Ksh + 64 * KSTR;       // 64*KSTR
    float* Rsh  = Vsh + 64 * KSTR;       // 128*KSTR
    float* BDsh = Rsh + 128 * KSTR;      // 64*128 (also reused as P)

    int tid = threadIdx.x;
    int tx = tid & 15, ty = tid >> 4;
    int qt = (gridDim.x - 1) - blockIdx.x;  // heavy tiles scheduled first
    int b = blockIdx.y >> 3, h = blockIdx.y & 7;
    int s0 = qt * 64;
    int hoff = h * 64;

    for (int idx = tid; idx < 64 * 64; idx += 256) {
        int sR = idx >> 6, i = idx & 63;
        float qval = qkv[((size_t)(Mx + s0 + sR) * Bx + b) * QKV3 + hoff + i];
        Qu[sR * 64 + i] = qval + u[hoff + i];
        Qv[sR * 64 + i] = qval + v[hoff + i];
    }

    float m_r[4], l_r[4], O[4][4];
#pragma unroll
    for (int a = 0; a < 4; a++) {
        m_r[a] = -1e30f; l_r[a] = 0.f;
#pragma unroll
        for (int c = 0; c < 4; c++) O[a][c] = 0.f;
    }

    int nkt = s0 / 64 + Mx / 64 + 1;
    for (int kt = 0; kt < nkt; kt++) {
        int k0 = kt * 64;
        __syncthreads();   // smem reuse fence (covers Qu/Qv init on kt==0)
        for (int idx = tid; idx < 64 * 64; idx += 256) {
            int kr = idx >> 6, i = idx & 63;
            size_t base = ((size_t)(k0 + kr) * Bx + b) * QKV3 + hoff + i;
            Ksh[kr * KSTR + i] = qkv[base + 512];
            Vsh[kr * KSTR + i] = qkv[base + 1024];
        }
        int jlo = k0 + (Sx - 1) - s0 - 63;   // >= 0 always
        for (int idx = tid; idx < 128 * 64; idx += 256) {
            int d = idx >> 6, i = idx & 63;
            int j = jlo + d;
            if (j > Kx - 1) j = Kx - 1;      // only masked entries touch this
            Rsh[d * KSTR + i] = rbuf[(size_t)j * Ex + hoff + i];
        }
        __syncthreads();

        // AC GEMM: 4x4 per thread
        float ac[4][4];
#pragma unroll
        for (int a = 0; a < 4; a++)
#pragma unroll
            for (int c = 0; c < 4; c++) ac[a][c] = 0.f;
        for (int i = 0; i < 64; i += 4) {
            float4 qa[4], kb[4];
#pragma unroll
            for (int a = 0; a < 4; a++)
                qa[a] = *(const float4*)&Qu[(ty * 4 + a) * 64 + i];
#pragma unroll
            for (int c = 0; c < 4; c++)
                kb[c] = *(const float4*)&Ksh[(tx * 4 + c) * KSTR + i];
#pragma unroll
            for (int a = 0; a < 4; a++)
#pragma unroll
                for (int c = 0; c < 4; c++)
                    ac[a][c] += qa[a].x * kb[c].x + qa[a].y * kb[c].y
                              + qa[a].z * kb[c].z + qa[a].w * kb[c].w;
        }

        // BD band GEMM: 4x8 per thread over 128 diagonal-band columns
        float bd[4][8];
#pragma unroll
        for (int a = 0; a < 4; a++)
#pragma unroll
            for (int c = 0; c < 8; c++) bd[a][c] = 0.f;
        for (int i = 0; i < 64; i += 4) {
            float4 qa[4];
#pragma unroll
            for (int a = 0; a < 4; a++)
                qa[a] = *(const float4*)&Qv[(ty * 4 + a) * 64 + i];
            float4 rb[8];
#pragma unroll
            for (int c = 0; c < 8; c++)
                rb[c] = *(const float4*)&Rsh[(tx * 8 + c) * KSTR + i];
#pragma unroll
            for (int a = 0; a < 4; a++)
#pragma unroll
                for (int c = 0; c < 8; c++)
                    bd[a][c] += qa[a].x * rb[c].x + qa[a].y * rb[c].y
                              + qa[a].z * rb[c].z + qa[a].w * rb[c].w;
        }
#pragma unroll
        for (int a = 0; a < 4; a++)
#pragma unroll
            for (int c = 0; c < 8; c++)
                BDsh[(ty * 4 + a) * 128 + tx * 8 + c] = bd[a][c];
        __syncthreads();

        // combine along rel-shift diagonal + mask
        float sc[4][4];
#pragma unroll
        for (int a = 0; a < 4; a++) {
            int sR = ty * 4 + a;
#pragma unroll
            for (int c = 0; c < 4; c++) {
                int kc = tx * 4 + c;
                float val = (ac[a][c] + BDsh[sR * 128 + (kc - sR + 63)]) * 0.125f;
                if (k0 + kc > s0 + sR + Mx) val = -1e30f;
                sc[a][c] = val;
            }
        }
        __syncthreads();   // all BD reads done before P overwrites buffer

        // online softmax (row reduce over 16 lanes sharing ty)
#pragma unroll
        for (int a = 0; a < 4; a++) {
            float mx = fmaxf(fmaxf(sc[a][0], sc[a][1]), fmaxf(sc[a][2], sc[a][3]));
#pragma unroll
            for (int off = 8; off; off >>= 1)
                mx = fmaxf(mx, __shfl_xor_sync(0xffffffffu, mx, off));
            float mnew = fmaxf(m_r[a], mx);
            float corr = __expf(m_r[a] - mnew);
            float rs = 0.f;
#pragma unroll
            for (int c = 0; c < 4; c++) {
                float p = __expf(sc[a][c] - mnew);
                sc[a][c] = p; rs += p;
            }
#pragma unroll
            for (int off = 8; off; off >>= 1)
                rs += __shfl_xor_sync(0xffffffffu, rs, off);
            l_r[a] = l_r[a] * corr + rs;
            m_r[a] = mnew;
#pragma unroll
            for (int c = 0; c < 4; c++) O[a][c] *= corr;
            int sR = ty * 4 + a;
#pragma unroll
            for (int c = 0; c < 4; c++)
                BDsh[sR * 128 + tx * 4 + c] = sc[a][c];
        }
        __syncthreads();

        // P·V accumulate
        for (int i = 0; i < 64; i += 4) {
            float4 pa[4];
#pragma unroll
            for (int a = 0; a < 4; a++)
                pa[a] = *(const float4*)&BDsh[(ty * 4 + a) * 128 + i];
            float4 vb[4];
#pragma unroll
            for (int t = 0; t < 4; t++)
                vb[t] = *(const float4*)&Vsh[(i + t) * KSTR + tx * 4];
            const float* vbp = (const float*)vb;
#pragma unroll
            for (int a = 0; a < 4; a++)
#pragma unroll
                for (int c = 0; c < 4; c++)
                    O[a][c] += pa[a].x * vbp[0 * 4 + c] + pa[a].y * vbp[1 * 4 + c]
                             + pa[a].z * vbp[2 * 4 + c] + pa[a].w * vbp[3 * 4 + c];
        }
    }

#pragma unroll
    for (int a = 0; a < 4; a++) {
        int sg = s0 + ty * 4 + a;
        float inv = 1.0f / l_r[a];
#pragma unroll
        for (int c = 0; c < 4; c++)
            attn[((size_t)sg * Bx + b) * Ex + hoff + tx * 4 + c] = O[a][c] * inv;
    }
}

// ---------------- LayerNorm(X + Y) over last dim 512 ------------------------
__global__ void ln_add_kernel(const float* __restrict__ X, const float* __restrict__ Y,
                              const float* __restrict__ g, const float* __restrict__ bb,
                              float* __restrict__ out)
{
    __shared__ float red[4];
    int row = blockIdx.x;
    int tid = threadIdx.x;   // 128 threads, 4 floats each
    const float4* X4 = (const float4*)(X + (size_t)row * Ex);
    const float4* Y4 = (const float4*)(Y + (size_t)row * Ex);
    float4 x = X4[tid], y = Y4[tid];
    float4 vv = {x.x + y.x, x.y + y.y, x.z + y.z, x.w + y.w};
    float s = vv.x + vv.y + vv.z + vv.w;
#pragma unroll
    for (int off = 16; off; off >>= 1) s += __shfl_xor_sync(0xffffffffu, s, off);
    if ((tid & 31) == 0) red[tid >> 5] = s;
    __syncthreads();
    float mu = (red[0] + red[1] + red[2] + red[3]) * (1.f / 512.f);
    float d0 = vv.x - mu, d1 = vv.y - mu, d2 = vv.z - mu, d3 = vv.w - mu;
    float q = d0 * d0 + d1 * d1 + d2 * d2 + d3 * d3;
    __syncthreads();
#pragma unroll
    for (int off = 16; off; off >>= 1) q += __shfl_xor_sync(0xffffffffu, q, off);
    if ((tid & 31) == 0) red[tid >> 5] = q;
    __syncthreads();
    float var = (red[0] + red[1] + red[2] + red[3]) * (1.f / 512.f);
    float rs = rsqrtf(var + EPSF);
    const float4* g4 = (const float4*)g;
    const float4* b4 = (const float4*)bb;
    float4 gg = g4[tid], bv = b4[tid];
    float4 o;
    o.x = d0 * rs * gg.x + bv.x;
    o.y = d1 * rs * gg.y + bv.y;
    o.z = d2 * rs * gg.z + bv.z;
    o.w = d3 * rs * gg.w + bv.w;
    ((float4*)(out + (size_t)row * Ex))[tid] = o;
}

// ---------------------------------------------------------------------------
#define FLASH_SMEM ((2*64*64 + 2*64*KSTR + 128*KSTR + 64*128) * 4)

extern "C" void kernel_launch(void* const* d_in, const int* in_sizes, int n_in,
                              void* d_out, int out_size)
{
    const float* inputDec = (const float*)d_in[0];
    const float* posEmb   = (const float*)d_in[1];
    const float* u        = (const float*)d_in[2];
    const float* v        = (const float*)d_in[3];
    const float* memories = (const float*)d_in[4];
    const float* Wqkv     = (const float*)d_in[5];
    const float* Wr       = (const float*)d_in[6];
    const float* Wo       = (const float*)d_in[7];
    const float* ln1_g    = (const float*)d_in[8];
    const float* ln1_b    = (const float*)d_in[9];
    const float* W1       = (const float*)d_in[10];
    const float* b1       = (const float*)d_in[11];
    const float* W2       = (const float*)d_in[12];
    const float* b2       = (const float*)d_in[13];
    const float* ln2_g    = (const float*)d_in[14];
    const float* ln2_b    = (const float*)d_in[15];
    float* out = (float*)d_out;

    float *qkv, *rb, *attn, *tmp, *attnout, *ff1, *ff2;
    cudaGetSymbolAddress((void**)&qkv,     g_qkv);
    cudaGetSymbolAddress((void**)&rb,      g_r);
    cudaGetSymbolAddress((void**)&attn,    g_attn);
    cudaGetSymbolAddress((void**)&tmp,     g_tmp);
    cudaGetSymbolAddress((void**)&attnout, g_attnout);
    cudaGetSymbolAddress((void**)&ff1,     g_ff1);
    cudaGetSymbolAddress((void**)&ff2,     g_ff2);

    cudaFuncSetAttribute(flash_kernel,
                         cudaFuncAttributeMaxDynamicSharedMemorySize, FLASH_SMEM);

    // 1) qkv = concat(memories, inputDec) @ Wqkv
    sgemm128<0, true><<<dim3(QKV3 / 128, KB_ / 128), 256>>>(
        memories, inputDec, Mx * Bx, Wqkv, nullptr, qkv, KB_, QKV3, Ex);
    // 2) r = posEmbeddings @ Wr
    sgemm128<0, false><<<dim3(Ex / 128, Kx / 128), 256>>>(
        posEmb, nullptr, 0, Wr, nullptr, rb, Kx, Ex, Ex);
    // 3) fused rel-pos flash attention
    flash_kernel<<<dim3(Sx / 64, Bx * Hx), 256, FLASH_SMEM>>>(qkv, rb, u, v, attn);
    // 4) attn @ Wo
    sgemm128<0, false><<<dim3(Ex / 128, ROWS / 128), 256>>>(
        attn, nullptr, 0, Wo, nullptr, tmp, ROWS, Ex, Ex);
    // 5) attn_out = LN(inputDec + attnWo)
    ln_add_kernel<<<ROWS, 128>>>(inputDec, tmp, ln1_g, ln1_b, attnout);
    // 6) ff1 = relu(attn_out @ W1 + b1)
    sgemm128<2, false><<<dim3(FFx / 128, ROWS / 128), 256>>>(
        attnout, nullptr, 0, W1, b1, ff1, ROWS, FFx, Ex);
    // 7) ff2 = ff1 @ W2 + b2
    sgemm128<1, false><<<dim3(Ex / 128, ROWS / 128), 256>>>(
        ff1, nullptr, 0, W2, b2, ff2, ROWS, Ex, FFx);
    // 8) out = LN(attn_out + ff2)
    ln_add_kernel<<<ROWS, 128>>>(attnout, ff2, ln2_g, ln2_b, out);
}

// round 3
// speedup vs baseline: 7.3639x; 7.3639x over previous
#include <cuda_runtime.h>
#include <cstdint>

#define Sx 2048
#define Bx 2
#define Ex 512
#define Hx 8
#define Mx 2048
#define Kx 4096          // M + S
#define QKV3 1536
#define FFx 2048
#define ROWS (Sx*Bx)     // 4096
#define KB_ (Kx*Bx)      // 8192
#define EPSF 1e-5f

// ---------------- scratch (static device arrays: no allocation) -------------
__device__ __align__(128) float g_qkv[(size_t)KB_ * QKV3];
__device__ __align__(128) float g_r[(size_t)Kx * Ex];
__device__ __align__(128) float g_attn[(size_t)ROWS * Ex];
__device__ __align__(128) float g_tmp[(size_t)ROWS * Ex];
__device__ __align__(128) float g_attnout[(size_t)ROWS * Ex];
__device__ __align__(128) float g_attnout_r[(size_t)ROWS * Ex];
__device__ __align__(128) float g_ff1[(size_t)ROWS * FFx];
__device__ __align__(128) float g_ff2[(size_t)ROWS * Ex];
__device__ __align__(128) float g_mem_r[(size_t)Mx * Bx * Ex];
__device__ __align__(128) float g_inp_r[(size_t)Sx * Bx * Ex];
__device__ __align__(128) float g_pos_r[(size_t)Kx * Ex];
__device__ __align__(128) float g_wqkv_r[(size_t)Ex * QKV3];
__device__ __align__(128) float g_wr_r[(size_t)Ex * Ex];
__device__ __align__(128) float g_wo_r[(size_t)Ex * Ex];
__device__ __align__(128) float g_w1_r[(size_t)Ex * FFx];
__device__ __align__(128) float g_w2_r[(size_t)FFx * Ex];

// ---------------- helpers ---------------------------------------------------
__device__ __forceinline__ float f2tf(float x) {
    unsigned r;
    asm("cvt.rna.tf32.f32 %0, %1;" : "=r"(r) : "f"(x));
    return __uint_as_float(r);
}
__device__ __forceinline__ void mma8(float* d, const float* a, const float* b) {
    asm volatile(
        "mma.sync.aligned.m16n8k8.row.col.f32.tf32.tf32.f32 "
        "{%0,%1,%2,%3},{%4,%5,%6,%7},{%8,%9},{%0,%1,%2,%3};\n"
        : "+f"(d[0]), "+f"(d[1]), "+f"(d[2]), "+f"(d[3])
        : "r"(__float_as_uint(a[0])), "r"(__float_as_uint(a[1])),
          "r"(__float_as_uint(a[2])), "r"(__float_as_uint(a[3])),
          "r"(__float_as_uint(b[0])), "r"(__float_as_uint(b[1])));
}
__device__ __forceinline__ unsigned sptr(const void* p) {
    return (unsigned)__cvta_generic_to_shared(p);
}
__device__ __forceinline__ void cpa16(unsigned d, const float* s) {
    asm volatile("cp.async.cg.shared.global [%0], [%1], 16;\n" :: "r"(d), "l"(s));
}
__device__ __forceinline__ void cpcommit() { asm volatile("cp.async.commit_group;\n"); }
template<int N> __device__ __forceinline__ void cpwait() {
    asm volatile("cp.async.wait_group %0;\n" :: "n"(N));
}

// ---------------- tf32 rounding copy ----------------------------------------
__global__ void roundk(const float4* __restrict__ in, float4* __restrict__ out, int n4) {
    int i = blockIdx.x * 256 + threadIdx.x;
    if (i < n4) {
        float4 v = in[i];
        v.x = f2tf(v.x); v.y = f2tf(v.y); v.z = f2tf(v.z); v.w = f2tf(v.w);
        out[i] = v;
    }
}

// ---------------- TF32 GEMM: C(MxN)=A(MxK)*B(KxN), 128x128x32 ---------------
#define ASTR 36
#define BSTR 136
#define GEMM_SMEM ((2*128*ASTR + 2*32*BSTR) * 4)

template<int EPI, bool SPLITA, bool RND>
__global__ __launch_bounds__(256, 2) void tgemm(
    const float* __restrict__ A0, const float* __restrict__ A1, int splitRow,
    const float* __restrict__ Bm, const float* __restrict__ bias,
    float* __restrict__ C, int Nd, int Kd)
{
    extern __shared__ __align__(16) float sm[];
    float* As = sm;                  // [2][128][ASTR]
    float* Bs = sm + 2 * 128 * ASTR; // [2][32][BSTR]
    const int tid = threadIdx.x, lane = tid & 31, wid = tid >> 5;
    const int wm = wid >> 2, wn = wid & 3, g = lane >> 2, t = lane & 3;
    const int bm = blockIdx.y * 128, bn = blockIdx.x * 128;

    const float* asrc[4]; const float* bsrc[4];
    unsigned adst[4], bdst[4];
#pragma unroll
    for (int p = 0; p < 4; p++) {
        int id = tid + p * 256;
        int ar = id >> 3, ac4 = (id & 7) * 4;
        int grow = bm + ar;
        const float* base = (SPLITA && grow >= splitRow)
                            ? (A1 + (size_t)(grow - splitRow) * Kd)
                            : (A0 + (size_t)grow * Kd);
        asrc[p] = base + ac4;
        adst[p] = sptr(As + ar * ASTR + ac4);
        int br = id >> 5, bc4 = (id & 31) * 4;
        bsrc[p] = Bm + (size_t)br * Nd + bn + bc4;
        bdst[p] = sptr(Bs + br * BSTR + bc4);
    }
    const unsigned ABY = 128 * ASTR * 4, BBY = 32 * BSTR * 4;

    float acc[4][4][4];
#pragma unroll
    for (int i = 0; i < 4; i++)
#pragma unroll
        for (int j = 0; j < 4; j++)
#pragma unroll
            for (int r = 0; r < 4; r++) acc[i][j][r] = 0.f;

    // prologue: stage 0
    {
#pragma unroll
        for (int p = 0; p < 4; p++) cpa16(adst[p], asrc[p]);
#pragma unroll
        for (int p = 0; p < 4; p++) cpa16(bdst[p], bsrc[p]);
        cpcommit();
    }

    int nkt = Kd >> 5;
    for (int kt = 0; kt < nkt; kt++) {
        int p = kt & 1;
        if (kt + 1 < nkt) {
            int k0 = (kt + 1) << 5;
            unsigned ao = (p ^ 1) * ABY, bo = (p ^ 1) * BBY;
#pragma unroll
            for (int q = 0; q < 4; q++) cpa16(adst[q] + ao, asrc[q] + k0);
#pragma unroll
            for (int q = 0; q < 4; q++) cpa16(bdst[q] + bo, bsrc[q] + (size_t)k0 * Nd);
            cpcommit();
            cpwait<1>();
        } else cpwait<0>();
        __syncthreads();

        const float* Ab = As + p * 128 * ASTR + (wm * 64 + g) * ASTR;
        const float* Bb = Bs + p * 32 * BSTR + wn * 32 + g;
#pragma unroll
        for (int ks = 0; ks < 4; ks++) {
            float a[4][4], b[4][2];
#pragma unroll
            for (int mf = 0; mf < 4; mf++) {
                const float* pa = Ab + mf * 16 * ASTR + ks * 8 + t;
                a[mf][0] = pa[0];  a[mf][1] = pa[8 * ASTR];
                a[mf][2] = pa[4];  a[mf][3] = pa[8 * ASTR + 4];
            }
#pragma unroll
            for (int nf = 0; nf < 4; nf++) {
                const float* pb = Bb + (ks * 8 + t) * BSTR + nf * 8;
                b[nf][0] = pb[0]; b[nf][1] = pb[4 * BSTR];
            }
#pragma unroll
            for (int mf = 0; mf < 4; mf++)
#pragma unroll
                for (int nf = 0; nf < 4; nf++) mma8(acc[mf][nf], a[mf], b[nf]);
        }
        __syncthreads();
    }

#pragma unroll
    for (int mf = 0; mf < 4; mf++) {
        int r0 = bm + wm * 64 + mf * 16 + g;
#pragma unroll
        for (int nf = 0; nf < 4; nf++) {
            int c = bn + wn * 32 + nf * 8 + 2 * t;
            float v0 = acc[mf][nf][0], v1 = acc[mf][nf][1];
            float v2 = acc[mf][nf][2], v3 = acc[mf][nf][3];
            if (EPI >= 1) {
                float b0 = bias[c], b1v = bias[c + 1];
                v0 += b0; v1 += b1v; v2 += b0; v3 += b1v;
            }
            if (EPI == 2) {
                v0 = fmaxf(v0, 0.f); v1 = fmaxf(v1, 0.f);
                v2 = fmaxf(v2, 0.f); v3 = fmaxf(v3, 0.f);
            }
            if (RND) { v0 = f2tf(v0); v1 = f2tf(v1); v2 = f2tf(v2); v3 = f2tf(v3); }
            *(float2*)(C + (size_t)r0 * Nd + c)       = make_float2(v0, v1);
            *(float2*)(C + (size_t)(r0 + 8) * Nd + c) = make_float2(v2, v3);
        }
    }
}

// ---------------- Flash attention (TF32 mma) with XL rel-shift --------------
// score[s,k] = ((q+u)[s]·kk[k] + (q+v)[s]·r[k+S-1-s]) / 8, mask k > s+M.
#define QSTR 68
#define KST 68
#define VST 72
#define RST 68
#define BDS 132
#define OFF_QU 0
#define OFF_QV 4352
#define OFF_K  8704
#define OFF_V  17408
#define OFF_R  26624
#define OFF_BD 44032
#define FLASH_SMEM ((OFF_BD + 64*BDS) * 4)

__global__ __launch_bounds__(128, 1) void flash(
    const float* __restrict__ qkv, const float* __restrict__ rbuf,
    const float* __restrict__ u, const float* __restrict__ v,
    float* __restrict__ attn)
{
    extern __shared__ __align__(16) float sm[];
    float* Qu = sm + OFF_QU;  float* Qv = sm + OFF_QV;
    float* Ks = sm + OFF_K;   float* Vs = sm + OFF_V;
    float* Rs = sm + OFF_R;   float* BDb = sm + OFF_BD;  // BD band / P (warp-private rows)
    const int tid = threadIdx.x, lane = tid & 31, wid = tid >> 5;
    const int g = lane >> 2, t = lane & 3;
    const int qt = (gridDim.x - 1) - blockIdx.x;   // heavy tiles first
    const int b = blockIdx.y >> 3, h = blockIdx.y & 7;
    const int s0 = qt * 64, hoff = h * 64;
    const int w16 = wid * 16;

    // stage-0 cp.async for K/V/R
    auto issue = [&](int kt, int buf) {
        int k0 = kt * 64;
#pragma unroll
        for (int p = 0; p < 8; p++) {
            int id = tid + p * 128;
            int key = id >> 4, c = (id & 15) * 4;
            const float* src = qkv + ((size_t)(k0 + key) * Bx + b) * QKV3 + 512 + hoff + c;
            cpa16(sptr(Ks + buf * 64 * KST + key * KST + c), src);
            cpa16(sptr(Vs + buf * 64 * VST + key * VST + c), src + 512);
        }
        int jlo = k0 + (Sx - 1) - s0 - 63;
#pragma unroll
        for (int p = 0; p < 16; p++) {
            int id = tid + p * 128;
            int d = id >> 4, c = (id & 15) * 4;
            int j = jlo + d; if (j > Kx - 1) j = Kx - 1;   // clamped cells are masked
            cpa16(sptr(Rs + buf * 128 * RST + d * RST + c), rbuf + (size_t)j * Ex + hoff + c);
        }
        cpcommit();
    };
    issue(0, 0);

    // Q tiles (+u / +v), rounded once
    for (int idx = tid; idx < 64 * 64; idx += 128) {
        int sR = idx >> 6, i = idx & 63;
        float qv_ = qkv[((size_t)(Mx + s0 + sR) * Bx + b) * QKV3 + hoff + i];
        Qu[sR * QSTR + i] = f2tf(qv_ + u[hoff + i]);
        Qv[sR * QSTR + i] = f2tf(qv_ + v[hoff + i]);
    }

    float m0 = -1e30f, m1 = -1e30f, l0 = 0.f, l1 = 0.f;
    float O[8][4];
#pragma unroll
    for (int i = 0; i < 8; i++)
#pragma unroll
        for (int j = 0; j < 4; j++) O[i][j] = 0.f;

    const float* Aqu = Qu + (w16 + g) * QSTR;
    const float* Aqv = Qv + (w16 + g) * QSTR;
    float* BDrow = BDb + (w16 + g) * BDS;     // this thread's row g
    const int nkt = qt + 33;

    for (int kt = 0; kt < nkt; kt++) {
        int p = kt & 1;
        int k0 = kt * 64;
        if (kt + 1 < nkt) { issue(kt + 1, p ^ 1); cpwait<1>(); }
        else cpwait<0>();
        __syncthreads();
        const float* Kp = Ks + p * 64 * KST;
        const float* Vp = Vs + p * 64 * VST;
        const float* Rp = Rs + p * 128 * RST;

        // ---- BD band mma: 16 x 128 per warp -> smem
        {
            float bd[16][4];
#pragma unroll
            for (int nf = 0; nf < 16; nf++)
#pragma unroll
                for (int j = 0; j < 4; j++) bd[nf][j] = 0.f;
#pragma unroll
            for (int ks = 0; ks < 8; ks++) {
                float a[4];
                const float* pa = Aqv + ks * 8 + t;
                a[0] = pa[0]; a[1] = pa[8 * QSTR]; a[2] = pa[4]; a[3] = pa[8 * QSTR + 4];
#pragma unroll
                for (int nf = 0; nf < 16; nf++) {
                    const float* pb = Rp + (nf * 8 + g) * RST + ks * 8;
                    float bb[2] = {pb[t], pb[t + 4]};
                    mma8(bd[nf], a, bb);
                }
            }
#pragma unroll
            for (int nf = 0; nf < 16; nf++) {
                *(float2*)(BDrow + nf * 8 + 2 * t) = make_float2(bd[nf][0], bd[nf][1]);
                *(float2*)(BDrow + 8 * BDS + nf * 8 + 2 * t) = make_float2(bd[nf][2], bd[nf][3]);
            }
        }
        __syncwarp();

        // ---- AC mma: 16 x 64 per warp (kept in regs)
        float ac[8][4];
#pragma unroll
        for (int nf = 0; nf < 8; nf++)
#pragma unroll
            for (int j = 0; j < 4; j++) ac[nf][j] = 0.f;
#pragma unroll
        for (int ks = 0; ks < 8; ks++) {
            float a[4];
            const float* pa = Aqu + ks * 8 + t;
            a[0] = pa[0]; a[1] = pa[8 * QSTR]; a[2] = pa[4]; a[3] = pa[8 * QSTR + 4];
#pragma unroll
            for (int nf = 0; nf < 8; nf++) {
                const float* pb = Kp + (nf * 8 + g) * KST + ks * 8;
                float bb[2] = {pb[t], pb[t + 4]};
                mma8(ac[nf], a, bb);
            }
        }

        // ---- combine with BD diagonal + mask -> scores in ac[][]
        {
            int sR0 = w16 + g, sR1 = sR0 + 8;
            int lim0 = s0 + sR0 + Mx, lim1 = s0 + sR1 + Mx;
#pragma unroll
            for (int nf = 0; nf < 8; nf++) {
                int kc = nf * 8 + 2 * t;
                float v0 = (ac[nf][0] + BDrow[kc - sR0 + 63]) * 0.125f;
                float v1 = (ac[nf][1] + BDrow[kc + 1 - sR0 + 63]) * 0.125f;
                float v2 = (ac[nf][2] + BDrow[8 * BDS + kc - sR1 + 63]) * 0.125f;
                float v3 = (ac[nf][3] + BDrow[8 * BDS + kc + 1 - sR1 + 63]) * 0.125f;
                if (k0 + kc > lim0)     v0 = -1e30f;
                if (k0 + kc + 1 > lim0) v1 = -1e30f;
                if (k0 + kc > lim1)     v2 = -1e30f;
                if (k0 + kc + 1 > lim1) v3 = -1e30f;
                ac[nf][0] = v0; ac[nf][1] = v1; ac[nf][2] = v2; ac[nf][3] = v3;
            }
        }
        __syncwarp();

        // ---- online softmax (rows g and g+8; reduce over quad lanes t)
        {
            float mx0 = -1e30f, mx1 = -1e30f;
#pragma unroll
            for (int nf = 0; nf < 8; nf++) {
                mx0 = fmaxf(mx0, fmaxf(ac[nf][0], ac[nf][1]));
                mx1 = fmaxf(mx1, fmaxf(ac[nf][2], ac[nf][3]));
            }
            mx0 = fmaxf(mx0, __shfl_xor_sync(0xffffffffu, mx0, 1));
            mx0 = fmaxf(mx0, __shfl_xor_sync(0xffffffffu, mx0, 2));
            mx1 = fmaxf(mx1, __shfl_xor_sync(0xffffffffu, mx1, 1));
            mx1 = fmaxf(mx1, __shfl_xor_sync(0xffffffffu, mx1, 2));
            float mn0 = fmaxf(m0, mx0), mn1 = fmaxf(m1, mx1);
            float c0 = __expf(m0 - mn0), c1 = __expf(m1 - mn1);
            float rs0 = 0.f, rs1 = 0.f;
#pragma unroll
            for (int nf = 0; nf < 8; nf++) {
                float p0 = __expf(ac[nf][0] - mn0);
                float p1 = __expf(ac[nf][1] - mn0);
                float p2 = __expf(ac[nf][2] - mn1);
                float p3 = __expf(ac[nf][3] - mn1);
                rs0 += p0 + p1; rs1 += p2 + p3;
                *(float2*)(BDrow + nf * 8 + 2 * t) = make_float2(f2tf(p0), f2tf(p1));
                *(float2*)(BDrow + 8 * BDS + nf * 8 + 2 * t) = make_float2(f2tf(p2), f2tf(p3));
            }
            rs0 += __shfl_xor_sync(0xffffffffu, rs0, 1);
            rs0 += __shfl_xor_sync(0xffffffffu, rs0, 2);
            rs1 += __shfl_xor_sync(0xffffffffu, rs1, 1);
            rs1 += __shfl_xor_sync(0xffffffffu, rs1, 2);
            l0 = l0 * c0 + rs0; l1 = l1 * c1 + rs1;
            m0 = mn0; m1 = mn1;
#pragma unroll
            for (int nf = 0; nf < 8; nf++) {
                O[nf][0] *= c0; O[nf][1] *= c0; O[nf][2] *= c1; O[nf][3] *= c1;
            }
        }
        __syncwarp();

        // ---- P·V mma: P(16x64) from smem, V as B-frag
#pragma unroll
        for (int ks = 0; ks < 8; ks++) {
            float a[4];
            const float* pa = BDrow + ks * 8 + t;
            a[0] = pa[0]; a[1] = pa[8 * BDS]; a[2] = pa[4]; a[3] = pa[8 * BDS + 4];
#pragma unroll
            for (int nf = 0; nf < 8; nf++) {
                const float* pb = Vp + (ks * 8 + t) * VST + nf * 8 + g;
                float bb[2] = {pb[0], pb[4 * VST]};
                mma8(O[nf], a, bb);
            }
        }
        __syncthreads();   // all warps done with this stage's K/V/R before refill
    }

    // epilogue: normalize + round (feeds Wo GEMM as tf32 A operand)
    {
        float i0 = 1.0f / l0, i1 = 1.0f / l1;
        int sg0 = s0 + w16 + g;
#pragma unroll
        for (int nf = 0; nf < 8; nf++) {
            int c = hoff + nf * 8 + 2 * t;
            *(float2*)(attn + ((size_t)sg0 * Bx + b) * Ex + c) =
                make_float2(f2tf(O[nf][0] * i0), f2tf(O[nf][1] * i0));
            *(float2*)(attn + ((size_t)(sg0 + 8) * Bx + b) * Ex + c) =
                make_float2(f2tf(O[nf][2] * i1), f2tf(O[nf][3] * i1));
        }
    }
}

// ---------------- LayerNorm(X + Y); optional tf32-rounded second copy -------
__global__ void ln_add_kernel(const float* __restrict__ X, const float* __restrict__ Y,
                              const float* __restrict__ g, const float* __restrict__ bb,
                              float* __restrict__ out, float* __restrict__ out_r)
{
    __shared__ float red[4];
    int row = blockIdx.x;
    int tid = threadIdx.x;   // 128 threads, 4 floats each
    const float4* X4 = (const float4*)(X + (size_t)row * Ex);
    const float4* Y4 = (const float4*)(Y + (size_t)row * Ex);
    float4 x = X4[tid], y = Y4[tid];
    float4 vv = {x.x + y.x, x.y + y.y, x.z + y.z, x.w + y.w};
    float s = vv.x + vv.y + vv.z + vv.w;
#pragma unroll
    for (int off = 16; off; off >>= 1) s += __shfl_xor_sync(0xffffffffu, s, off);
    if ((tid & 31) == 0) red[tid >> 5] = s;
    __syncthreads();
    float mu = (red[0] + red[1] + red[2] + red[3]) * (1.f / 512.f);
    float d0 = vv.x - mu, d1 = vv.y - mu, d2 = vv.z - mu, d3 = vv.w - mu;
    float q = d0 * d0 + d1 * d1 + d2 * d2 + d3 * d3;
    __syncthreads();
#pragma unroll
    for (int off = 16; off; off >>= 1) q += __shfl_xor_sync(0xffffffffu, q, off);
    if ((tid & 31) == 0) red[tid >> 5] = q;
    __syncthreads();
    float var = (red[0] + red[1] + red[2] + red[3]) * (1.f / 512.f);
    float rs = rsqrtf(var + EPSF);
    float4 gg = ((const float4*)g)[tid], bv = ((const float4*)bb)[tid];
    float4 o;
    o.x = d0 * rs * gg.x + bv.x;
    o.y = d1 * rs * gg.y + bv.y;
    o.z = d2 * rs * gg.z + bv.z;
    o.w = d3 * rs * gg.w + bv.w;
    ((float4*)(out + (size_t)row * Ex))[tid] = o;
    if (out_r) {
        float4 orr = {f2tf(o.x), f2tf(o.y), f2tf(o.z), f2tf(o.w)};
        ((float4*)(out_r + (size_t)row * Ex))[tid] = orr;
    }
}

// ---------------------------------------------------------------------------
static inline void round_into(const float* src, float* dst, size_t n) {
    int n4 = (int)(n / 4);
    roundk<<<(n4 + 255) / 256, 256>>>((const float4*)src, (float4*)dst, n4);
}

extern "C" void kernel_launch(void* const* d_in, const int* in_sizes, int n_in,
                              void* d_out, int out_size)
{
    const float* inputDec = (const float*)d_in[0];
    const float* posEmb   = (const float*)d_in[1];
    const float* u        = (const float*)d_in[2];
    const float* v        = (const float*)d_in[3];
    const float* memories = (const float*)d_in[4];
    const float* Wqkv     = (const float*)d_in[5];
    const float* Wr       = (const float*)d_in[6];
    const float* Wo       = (const float*)d_in[7];
    const float* ln1_g    = (const float*)d_in[8];
    const float* ln1_b    = (const float*)d_in[9];
    const float* W1       = (const float*)d_in[10];
    const float* b1       = (const float*)d_in[11];
    const float* W2       = (const float*)d_in[12];
    const float* b2       = (const float*)d_in[13];
    const float* ln2_g    = (const float*)d_in[14];
    const float* ln2_b    = (const float*)d_in[15];
    float* out = (float*)d_out;

    float *qkv, *rb, *attn, *tmp, *attnout, *attnout_r, *ff1, *ff2;
    float *mem_r, *inp_r, *pos_r, *wqkv_r, *wr_r, *wo_r, *w1_r, *w2_r;
    cudaGetSymbolAddress((void**)&qkv,       g_qkv);
    cudaGetSymbolAddress((void**)&rb,        g_r);
    cudaGetSymbolAddress((void**)&attn,      g_attn);
    cudaGetSymbolAddress((void**)&tmp,       g_tmp);
    cudaGetSymbolAddress((void**)&attnout,   g_attnout);
    cudaGetSymbolAddress((void**)&attnout_r, g_attnout_r);
    cudaGetSymbolAddress((void**)&ff1,       g_ff1);
    cudaGetSymbolAddress((void**)&ff2,       g_ff2);
    cudaGetSymbolAddress((void**)&mem_r,     g_mem_r);
    cudaGetSymbolAddress((void**)&inp_r,     g_inp_r);
    cudaGetSymbolAddress((void**)&pos_r,     g_pos_r);
    cudaGetSymbolAddress((void**)&wqkv_r,    g_wqkv_r);
    cudaGetSymbolAddress((void**)&wr_r,      g_wr_r);
    cudaGetSymbolAddress((void**)&wo_r,      g_wo_r);
    cudaGetSymbolAddress((void**)&w1_r,      g_w1_r);
    cudaGetSymbolAddress((void**)&w2_r,      g_w2_r);

    cudaFuncSetAttribute(flash, cudaFuncAttributeMaxDynamicSharedMemorySize, FLASH_SMEM);
    cudaFuncSetAttribute(tgemm<0,true,true>,   cudaFuncAttributeMaxDynamicSharedMemorySize, GEMM_SMEM);
    cudaFuncSetAttribute(tgemm<0,false,true>,  cudaFuncAttributeMaxDynamicSharedMemorySize, GEMM_SMEM);
    cudaFuncSetAttribute(tgemm<0,false,false>, cudaFuncAttributeMaxDynamicSharedMemorySize, GEMM_SMEM);
    cudaFuncSetAttribute(tgemm<2,false,true>,  cudaFuncAttributeMaxDynamicSharedMemorySize, GEMM_SMEM);
    cudaFuncSetAttribute(tgemm<1,false,false>, cudaFuncAttributeMaxDynamicSharedMemorySize, GEMM_SMEM);

    // 0) round raw operands to tf32 (RNA)
    round_into(memories, mem_r,  (size_t)Mx * Bx * Ex);
    round_into(inputDec, inp_r,  (size_t)Sx * Bx * Ex);
    round_into(posEmb,   pos_r,  (size_t)Kx * Ex);
    round_into(Wqkv,     wqkv_r, (size_t)Ex * QKV3);
    round_into(Wr,       wr_r,   (size_t)Ex * Ex);
    round_into(Wo,       wo_r,   (size_t)Ex * Ex);
    round_into(W1,       w1_r,   (size_t)Ex * FFx);
    round_into(W2,       w2_r,   (size_t)FFx * Ex);

    // 1) qkv = concat(memories, inputDec) @ Wqkv   (rounded output)
    tgemm<0,true,true><<<dim3(QKV3/128, KB_/128), 256, GEMM_SMEM>>>(
        mem_r, inp_r, Mx * Bx, wqkv_r, nullptr, qkv, QKV3, Ex);
    // 2) r = posEmbeddings @ Wr                    (rounded output)
    tgemm<0,false,true><<<dim3(Ex/128, Kx/128), 256, GEMM_SMEM>>>(
        pos_r, nullptr, 0, wr_r, nullptr, rb, Ex, Ex);
    // 3) fused rel-pos flash attention (tensor cores)
    flash<<<dim3(Sx/64, Bx*Hx), 128, FLASH_SMEM>>>(qkv, rb, u, v, attn);
    // 4) attn @ Wo
    tgemm<0,false,false><<<dim3(Ex/128, ROWS/128), 256, GEMM_SMEM>>>(
        attn, nullptr, 0, wo_r, nullptr, tmp, Ex, Ex);
    // 5) attn_out = LN(inputDec + attnWo)  (+ rounded copy for FF1)
    ln_add_kernel<<<ROWS, 128>>>(inputDec, tmp, ln1_g, ln1_b, attnout, attnout_r);
    // 6) ff1 = relu(attn_out @ W1 + b1)            (rounded output)
    tgemm<2,false,true><<<dim3(FFx/128, ROWS/128), 256, GEMM_SMEM>>>(
        attnout_r, nullptr, 0, w1_r, b1, ff1, FFx, Ex);
    // 7) ff2 = ff1 @ W2 + b2
    tgemm<1,false,false><<<dim3(Ex/128, ROWS/128), 256, GEMM_SMEM>>>(
        ff1, nullptr, 0, w2_r, b2, ff2, Ex, FFx);
    // 8) out = LN(attn_out + ff2)
    ln_add_kernel<<<ROWS, 128>>>(attnout, ff2, ln2_g, ln2_b, out, nullptr);
}

// round 4
// speedup vs baseline: 8.6600x; 1.1760x over previous
#include <cuda_runtime.h>
#include <cstdint>

#define Sx 2048
#define Bx 2
#define Ex 512
#define Hx 8
#define Mx 2048
#define Kx 4096          // M + S
#define QKV3 1536
#define FFx 2048
#define ROWS (Sx*Bx)     // 4096
#define KB_ (Kx*Bx)      // 8192
#define EPSF 1e-5f

// ---------------- scratch (static device arrays: no allocation) -------------
__device__ __align__(128) float g_qkv[(size_t)KB_ * QKV3];
__device__ __align__(128) float g_r[(size_t)Kx * Ex];
__device__ __align__(128) float g_attn[(size_t)ROWS * Ex];
__device__ __align__(128) float g_tmp[(size_t)ROWS * Ex];
__device__ __align__(128) float g_attnout[(size_t)ROWS * Ex];
__device__ __align__(128) float g_attnout_r[(size_t)ROWS * Ex];
__device__ __align__(128) float g_ff1[(size_t)ROWS * FFx];
__device__ __align__(128) float g_ff2[(size_t)ROWS * Ex];
__device__ __align__(128) float g_mem_r[(size_t)Mx * Bx * Ex];
__device__ __align__(128) float g_inp_r[(size_t)Sx * Bx * Ex];
__device__ __align__(128) float g_pos_r[(size_t)Kx * Ex];
__device__ __align__(128) float g_wqkv_r[(size_t)Ex * QKV3];
__device__ __align__(128) float g_wr_r[(size_t)Ex * Ex];
__device__ __align__(128) float g_wo_r[(size_t)Ex * Ex];
__device__ __align__(128) float g_w1_r[(size_t)Ex * FFx];
__device__ __align__(128) float g_w2_r[(size_t)FFx * Ex];

// ---------------- helpers ---------------------------------------------------
__device__ __forceinline__ float f2tf(float x) {
    unsigned r;
    asm("cvt.rna.tf32.f32 %0, %1;" : "=r"(r) : "f"(x));
    return __uint_as_float(r);
}
__device__ __forceinline__ void mma8(float* d, const float* a, const float* b) {
    asm volatile(
        "mma.sync.aligned.m16n8k8.row.col.f32.tf32.tf32.f32 "
        "{%0,%1,%2,%3},{%4,%5,%6,%7},{%8,%9},{%0,%1,%2,%3};\n"
        : "+f"(d[0]), "+f"(d[1]), "+f"(d[2]), "+f"(d[3])
        : "r"(__float_as_uint(a[0])), "r"(__float_as_uint(a[1])),
          "r"(__float_as_uint(a[2])), "r"(__float_as_uint(a[3])),
          "r"(__float_as_uint(b[0])), "r"(__float_as_uint(b[1])));
}
__device__ __forceinline__ unsigned sptr(const void* p) {
    return (unsigned)__cvta_generic_to_shared(p);
}
__device__ __forceinline__ void cpa16(unsigned d, const float* s) {
    asm volatile("cp.async.cg.shared.global [%0], [%1], 16;\n" :: "r"(d), "l"(s));
}
__device__ __forceinline__ void cpcommit() { asm volatile("cp.async.commit_group;\n"); }
template<int N> __device__ __forceinline__ void cpwait() {
    asm volatile("cp.async.wait_group %0;\n" :: "n"(N));
}
__device__ __forceinline__ void barg(int id) {
    asm volatile("bar.sync %0, 128;" :: "r"(id) : "memory");
}

// ---------------- tf32 rounding, all tensors in one launch -------------------
struct RSegs { const float4* src[8]; float4* dst[8]; int n4[8]; };
__global__ void roundall(RSegs segs) {
    int seg = blockIdx.y;
    int i = blockIdx.x * 256 + threadIdx.x;
    if (i < segs.n4[seg]) {
        float4 v = segs.src[seg][i];
        v.x = f2tf(v.x); v.y = f2tf(v.y); v.z = f2tf(v.z); v.w = f2tf(v.w);
        segs.dst[seg][i] = v;
    }
}

// ---------------- TF32 GEMM: C(MxN)=A(MxK)*B(KxN), 128x128x32 ---------------
#define ASTR 36
#define BSTR 136
#define GEMM_SMEM ((2*128*ASTR + 2*32*BSTR) * 4)

template<int EPI, bool SPLITA, bool RND>
__global__ __launch_bounds__(256, 2) void tgemm(
    const float* __restrict__ A0, const float* __restrict__ A1, int splitRow,
    const float* __restrict__ Bm, const float* __restrict__ bias,
    float* __restrict__ C, int Nd, int Kd)
{
    extern __shared__ __align__(16) float sm[];
    float* As = sm;                  // [2][128][ASTR]
    float* Bs = sm + 2 * 128 * ASTR; // [2][32][BSTR]
    const int tid = threadIdx.x, lane = tid & 31, wid = tid >> 5;
    const int wm = wid >> 2, wn = wid & 3, g = lane >> 2, t = lane & 3;
    const int bm = blockIdx.y * 128, bn = blockIdx.x * 128;

    const float* asrc[4]; const float* bsrc[4];
    unsigned adst[4], bdst[4];
#pragma unroll
    for (int p = 0; p < 4; p++) {
        int id = tid + p * 256;
        int ar = id >> 3, ac4 = (id & 7) * 4;
        int grow = bm + ar;
        const float* base = (SPLITA && grow >= splitRow)
                            ? (A1 + (size_t)(grow - splitRow) * Kd)
                            : (A0 + (size_t)grow * Kd);
        asrc[p] = base + ac4;
        adst[p] = sptr(As + ar * ASTR + ac4);
        int br = id >> 5, bc4 = (id & 31) * 4;
        bsrc[p] = Bm + (size_t)br * Nd + bn + bc4;
        bdst[p] = sptr(Bs + br * BSTR + bc4);
    }
    const unsigned ABY = 128 * ASTR * 4, BBY = 32 * BSTR * 4;

    float acc[4][4][4];
#pragma unroll
    for (int i = 0; i < 4; i++)
#pragma unroll
        for (int j = 0; j < 4; j++)
#pragma unroll
            for (int r = 0; r < 4; r++) acc[i][j][r] = 0.f;

    {
#pragma unroll
        for (int p = 0; p < 4; p++) cpa16(adst[p], asrc[p]);
#pragma unroll
        for (int p = 0; p < 4; p++) cpa16(bdst[p], bsrc[p]);
        cpcommit();
    }

    int nkt = Kd >> 5;
    for (int kt = 0; kt < nkt; kt++) {
        int p = kt & 1;
        if (kt + 1 < nkt) {
            int k0 = (kt + 1) << 5;
            unsigned ao = (p ^ 1) * ABY, bo = (p ^ 1) * BBY;
#pragma unroll
            for (int q = 0; q < 4; q++) cpa16(adst[q] + ao, asrc[q] + k0);
#pragma unroll
            for (int q = 0; q < 4; q++) cpa16(bdst[q] + bo, bsrc[q] + (size_t)k0 * Nd);
            cpcommit();
            cpwait<1>();
        } else cpwait<0>();
        __syncthreads();

        const float* Ab = As + p * 128 * ASTR + (wm * 64 + g) * ASTR;
        const float* Bb = Bs + p * 32 * BSTR + wn * 32 + g;
#pragma unroll
        for (int ks = 0; ks < 4; ks++) {
            float a[4][4], b[4][2];
#pragma unroll
            for (int mf = 0; mf < 4; mf++) {
                const float* pa = Ab + mf * 16 * ASTR + ks * 8 + t;
                a[mf][0] = pa[0];  a[mf][1] = pa[8 * ASTR];
                a[mf][2] = pa[4];  a[mf][3] = pa[8 * ASTR + 4];
            }
#pragma unroll
            for (int nf = 0; nf < 4; nf++) {
                const float* pb = Bb + (ks * 8 + t) * BSTR + nf * 8;
                b[nf][0] = pb[0]; b[nf][1] = pb[4 * BSTR];
            }
#pragma unroll
            for (int mf = 0; mf < 4; mf++)
#pragma unroll
                for (int nf = 0; nf < 4; nf++) mma8(acc[mf][nf], a[mf], b[nf]);
        }
        __syncthreads();
    }

#pragma unroll
    for (int mf = 0; mf < 4; mf++) {
        int r0 = bm + wm * 64 + mf * 16 + g;
#pragma unroll
        for (int nf = 0; nf < 4; nf++) {
            int c = bn + wn * 32 + nf * 8 + 2 * t;
            float v0 = acc[mf][nf][0], v1 = acc[mf][nf][1];
            float v2 = acc[mf][nf][2], v3 = acc[mf][nf][3];
            if (EPI >= 1) {
                float b0 = bias[c], b1v = bias[c + 1];
                v0 += b0; v1 += b1v; v2 += b0; v3 += b1v;
            }
            if (EPI == 2) {
                v0 = fmaxf(v0, 0.f); v1 = fmaxf(v1, 0.f);
                v2 = fmaxf(v2, 0.f); v3 = fmaxf(v3, 0.f);
            }
            if (RND) { v0 = f2tf(v0); v1 = f2tf(v1); v2 = f2tf(v2); v3 = f2tf(v3); }
            *(float2*)(C + (size_t)r0 * Nd + c)       = make_float2(v0, v1);
            *(float2*)(C + (size_t)(r0 + 8) * Nd + c) = make_float2(v2, v3);
        }
    }
}

// ---------------- Flash attention (TF32 mma) with XL rel-shift --------------
// 256 threads, 2 key-split warp-groups: group 0 (warps 0-3) even k-tiles in
// buffer 0, group 1 (warps 4-7) odd k-tiles in buffer 1. Per-warp BD band is
// trimmed to the 80 columns its 16 query rows actually read (x = kc + 15 - rl).
// Final softmax-state merge through the per-warp scratch region.
#define QSTR 68
#define KST 68
#define VST 72
#define RST 68
#define BDW 84
#define OFF_QU 0
#define OFF_QV 4352
#define OFF_K  8704
#define OFF_V  17408
#define OFF_R  26624
#define OFF_BD 44032
#define FLASH_SMEM ((OFF_BD + 8*16*BDW) * 4)

__global__ __launch_bounds__(256, 1) void flash(
    const float* __restrict__ qkv, const float* __restrict__ rbuf,
    const float* __restrict__ u, const float* __restrict__ v,
    float* __restrict__ attn)
{
    extern __shared__ __align__(16) float sm[];
    float* Qu = sm + OFF_QU;  float* Qv = sm + OFF_QV;
    float* Ks = sm + OFF_K;   float* Vs = sm + OFF_V;
    float* Rs = sm + OFF_R;   float* BDb = sm + OFF_BD;
    const int tid = threadIdx.x, lane = tid & 31, wid = tid >> 5;
    const int g = lane >> 2, t = lane & 3;
    const int gr = wid >> 2, wg = wid & 3;     // group, warp-in-group
    const int gtid = tid & 127;
    const int qt = (gridDim.x - 1) - blockIdx.x;   // heavy tiles first
    const int b = blockIdx.y >> 3, h = blockIdx.y & 7;
    const int s0 = qt * 64, hoff = h * 64;

    // stage loads: group gr always into buffer gr
    auto issue = [&](int kt) {
        int k0 = kt * 64;
#pragma unroll
        for (int p = 0; p < 8; p++) {
            int id = gtid + p * 128;
            int key = id >> 4, c = (id & 15) * 4;
            const float* src = qkv + ((size_t)(k0 + key) * Bx + b) * QKV3 + 512 + hoff + c;
            cpa16(sptr(Ks + gr * 64 * KST + key * KST + c), src);
            cpa16(sptr(Vs + gr * 64 * VST + key * VST + c), src + 512);
        }
        int jlo = k0 + (Sx - 1) - s0 - 63;
#pragma unroll
        for (int p = 0; p < 16; p++) {
            int id = gtid + p * 128;
            int d = id >> 4, c = (id & 15) * 4;
            int j = jlo + d; if (j > Kx - 1) j = Kx - 1;   // clamped cells are masked
            cpa16(sptr(Rs + gr * 128 * RST + d * RST + c), rbuf + (size_t)j * Ex + hoff + c);
        }
        cpcommit();
    };
    issue(gr);   // group prologue stage

    // Q tiles (+u / +v), rounded once (all 256 threads)
    for (int idx = tid; idx < 64 * 64; idx += 256) {
        int sR = idx >> 6, i = idx & 63;
        float qv_ = qkv[((size_t)(Mx + s0 + sR) * Bx + b) * QKV3 + hoff + i];
        Qu[sR * QSTR + i] = f2tf(qv_ + u[hoff + i]);
        Qv[sR * QSTR + i] = f2tf(qv_ + v[hoff + i]);
    }
    __syncthreads();

    float m0 = -1e30f, m1 = -1e30f, l0 = 0.f, l1 = 0.f;
    float O[8][4];
#pragma unroll
    for (int i = 0; i < 8; i++)
#pragma unroll
        for (int j = 0; j < 4; j++) O[i][j] = 0.f;

    const float* Aqu = Qu + (wg * 16 + g) * QSTR;
    const float* Aqv = Qv + (wg * 16 + g) * QSTR;
    float* BDrow = BDb + (wid * 16 + g) * BDW;       // this thread's row g, own warp region
    const float* Kp = Ks + gr * 64 * KST;
    const float* Vp = Vs + gr * 64 * VST;
    const float* Rp = Rs + gr * 128 * RST;
    const int c_base = 48 - wg * 16;                 // warp band origin in R stage
    const int nkt = qt + 33;

    for (int kt = gr; kt < nkt; kt += 2) {
        int k0 = kt * 64;
        cpwait<0>();
        barg(gr + 1);   // group sees its stage data

        // ---- BD band mma: 16 x 80 per warp (trimmed) -> smem
        {
            float bd[10][4];
#pragma unroll
            for (int nf = 0; nf < 10; nf++)
#pragma unroll
                for (int j = 0; j < 4; j++) bd[nf][j] = 0.f;
#pragma unroll
            for (int ks = 0; ks < 8; ks++) {
                float a[4];
                const float* pa = Aqv + ks * 8 + t;
                a[0] = pa[0]; a[1] = pa[8 * QSTR]; a[2] = pa[4]; a[3] = pa[8 * QSTR + 4];
#pragma unroll
                for (int nf = 0; nf < 10; nf++) {
                    const float* pb = Rp + (c_base + nf * 8 + g) * RST + ks * 8;
                    float bb[2] = {pb[t], pb[t + 4]};
                    mma8(bd[nf], a, bb);
                }
            }
#pragma unroll
            for (int nf = 0; nf < 10; nf++) {
                *(float2*)(BDrow + nf * 8 + 2 * t) = make_float2(bd[nf][0], bd[nf][1]);
                *(float2*)(BDrow + 8 * BDW + nf * 8 + 2 * t) = make_float2(bd[nf][2], bd[nf][3]);
            }
        }
        __syncwarp();

        // ---- AC mma: 16 x 64 per warp (kept in regs)
        float ac[8][4];
#pragma unroll
        for (int nf = 0; nf < 8; nf++)
#pragma unroll
            for (int j = 0; j < 4; j++) ac[nf][j] = 0.f;
#pragma unroll
        for (int ks = 0; ks < 8; ks++) {
            float a[4];
            const float* pa = Aqu + ks * 8 + t;
            a[0] = pa[0]; a[1] = pa[8 * QSTR]; a[2] = pa[4]; a[3] = pa[8 * QSTR + 4];
#pragma unroll
            for (int nf = 0; nf < 8; nf++) {
                const float* pb = Kp + (nf * 8 + g) * KST + ks * 8;
                float bb[2] = {pb[t], pb[t + 4]};
                mma8(ac[nf], a, bb);
            }
        }

        // ---- combine with BD diagonal + mask (local band x = kc + 15 - rl)
        {
            int lim0 = s0 + wg * 16 + g + Mx, lim1 = lim0 + 8;
#pragma unroll
            for (int nf = 0; nf < 8; nf++) {
                int kc = nf * 8 + 2 * t;
                float v0 = (ac[nf][0] + BDrow[kc + 15 - g]) * 0.125f;
                float v1 = (ac[nf][1] + BDrow[kc + 16 - g]) * 0.125f;
                float v2 = (ac[nf][2] + BDrow[8 * BDW + kc + 7 - g]) * 0.125f;
                float v3 = (ac[nf][3] + BDrow[8 * BDW + kc + 8 - g]) * 0.125f;
                if (k0 + kc > lim0)     v0 = -1e30f;
                if (k0 + kc + 1 > lim0) v1 = -1e30f;
                if (k0 + kc > lim1)     v2 = -1e30f;
                if (k0 + kc + 1 > lim1) v3 = -1e30f;
                ac[nf][0] = v0; ac[nf][1] = v1; ac[nf][2] = v2; ac[nf][3] = v3;
            }
        }
        __syncwarp();

        // ---- online softmax (rows g, g+8; reduce over quad lanes)
        {
            float mx0 = -1e30f, mx1 = -1e30f;
#pragma unroll
            for (int nf = 0; nf < 8; nf++) {
                mx0 = fmaxf(mx0, fmaxf(ac[nf][0], ac[nf][1]));
                mx1 = fmaxf(mx1, fmaxf(ac[nf][2], ac[nf][3]));
            }
            mx0 = fmaxf(mx0, __shfl_xor_sync(0xffffffffu, mx0, 1));
            mx0 = fmaxf(mx0, __shfl_xor_sync(0xffffffffu, mx0, 2));
            mx1 = fmaxf(mx1, __shfl_xor_sync(0xffffffffu, mx1, 1));
            mx1 = fmaxf(mx1, __shfl_xor_sync(0xffffffffu, mx1, 2));
            float mn0 = fmaxf(m0, mx0), mn1 = fmaxf(m1, mx1);
            float c0 = __expf(m0 - mn0), c1 = __expf(m1 - mn1);
            float rs0 = 0.f, rs1 = 0.f;
#pragma unroll
            for (int nf = 0; nf < 8; nf++) {
                float p0 = __expf(ac[nf][0] - mn0);
                float p1 = __expf(ac[nf][1] - mn0);
                float p2 = __expf(ac[nf][2] - mn1);
                float p3 = __expf(ac[nf][3] - mn1);
                rs0 += p0 + p1; rs1 += p2 + p3;
                *(float2*)(BDrow + nf * 8 + 2 * t) = make_float2(f2tf(p0), f2tf(p1));
                *(float2*)(BDrow + 8 * BDW + nf * 8 + 2 * t) = make_float2(f2tf(p2), f2tf(p3));
            }
            rs0 += __shfl_xor_sync(0xffffffffu, rs0, 1);
            rs0 += __shfl_xor_sync(0xffffffffu, rs0, 2);
            rs1 += __shfl_xor_sync(0xffffffffu, rs1, 1);
            rs1 += __shfl_xor_sync(0xffffffffu, rs1, 2);
            l0 = l0 * c0 + rs0; l1 = l1 * c1 + rs1;
            m0 = mn0; m1 = mn1;
#pragma unroll
            for (int nf = 0; nf < 8; nf++) {
                O[nf][0] *= c0; O[nf][1] *= c0; O[nf][2] *= c1; O[nf][3] *= c1;
            }
        }
        __syncwarp();

        // ---- P·V mma
#pragma unroll
        for (int ks = 0; ks < 8; ks++) {
            float a[4];
            const float* pa = BDrow + ks * 8 + t;
            a[0] = pa[0]; a[1] = pa[8 * BDW]; a[2] = pa[4]; a[3] = pa[8 * BDW + 4];
#pragma unroll
            for (int nf = 0; nf < 8; nf++) {
                const float* pb = Vp + (ks * 8 + t) * VST + nf * 8 + g;
                float bb[2] = {pb[0], pb[4 * VST]};
                mma8(O[nf], a, bb);
            }
        }

        barg(gr + 1);   // group done with buffer before refilling it
        if (kt + 2 < nkt) issue(kt + 2);
    }

    // ---- merge the two groups' partial softmax states, write output --------
    if (wid >= 4) {   // group 1 publishes partials in its own scratch region
#pragma unroll
        for (int nf = 0; nf < 8; nf++) {
            *(float2*)(BDrow + nf * 8 + 2 * t) = make_float2(O[nf][0], O[nf][1]);
            *(float2*)(BDrow + 8 * BDW + nf * 8 + 2 * t) = make_float2(O[nf][2], O[nf][3]);
        }
        if (t == 0) {
            BDrow[80] = m0; BDrow[81] = l0;
            BDrow[8 * BDW + 80] = m1; BDrow[8 * BDW + 81] = l1;
        }
    }
    __syncthreads();
    if (wid < 4) {
        const float* Peer = BDb + ((wid + 4) * 16 + g) * BDW;
        float pm0 = Peer[80], pl0 = Peer[81];
        float pm1 = Peer[8 * BDW + 80], pl1 = Peer[8 * BDW + 81];
        float M0 = fmaxf(m0, pm0), M1 = fmaxf(m1, pm1);
        float a0 = __expf(m0 - M0), e0 = __expf(pm0 - M0);
        float a1 = __expf(m1 - M1), e1 = __expf(pm1 - M1);
        float i0 = 1.0f / (l0 * a0 + pl0 * e0);
        float i1 = 1.0f / (l1 * a1 + pl1 * e1);
        int sg0 = s0 + wid * 16 + g;
#pragma unroll
        for (int nf = 0; nf < 8; nf++) {
            int c = hoff + nf * 8 + 2 * t;
            float2 po0 = *(const float2*)(Peer + nf * 8 + 2 * t);
            float2 po1 = *(const float2*)(Peer + 8 * BDW + nf * 8 + 2 * t);
            *(float2*)(attn + ((size_t)sg0 * Bx + b) * Ex + c) =
                make_float2(f2tf((O[nf][0] * a0 + po0.x * e0) * i0),
                            f2tf((O[nf][1] * a0 + po0.y * e0) * i0));
            *(float2*)(attn + ((size_t)(sg0 + 8) * Bx + b) * Ex + c) =
                make_float2(f2tf((O[nf][2] * a1 + po1.x * e1) * i1),
                            f2tf((O[nf][3] * a1 + po1.y * e1) * i1));
        }
    }
}

// ---------------- LayerNorm(X + Y); optional tf32-rounded second copy -------
__global__ void ln_add_kernel(const float* __restrict__ X, const float* __restrict__ Y,
                              const float* __restrict__ g, const float* __restrict__ bb,
                              float* __restrict__ out, float* __restrict__ out_r)
{
    __shared__ float red[4];
    int row = blockIdx.x;
    int tid = threadIdx.x;   // 128 threads, 4 floats each
    const float4* X4 = (const float4*)(X + (size_t)row * Ex);
    const float4* Y4 = (const float4*)(Y + (size_t)row * Ex);
    float4 x = X4[tid], y = Y4[tid];
    float4 vv = {x.x + y.x, x.y + y.y, x.z + y.z, x.w + y.w};
    float s = vv.x + vv.y + vv.z + vv.w;
#pragma unroll
    for (int off = 16; off; off >>= 1) s += __shfl_xor_sync(0xffffffffu, s, off);
    if ((tid & 31) == 0) red[tid >> 5] = s;
    __syncthreads();
    float mu = (red[0] + red[1] + red[2] + red[3]) * (1.f / 512.f);
    float d0 = vv.x - mu, d1 = vv.y - mu, d2 = vv.z - mu, d3 = vv.w - mu;
    float q = d0 * d0 + d1 * d1 + d2 * d2 + d3 * d3;
    __syncthreads();
#pragma unroll
    for (int off = 16; off; off >>= 1) q += __shfl_xor_sync(0xffffffffu, q, off);
    if ((tid & 31) == 0) red[tid >> 5] = q;
    __syncthreads();
    float var = (red[0] + red[1] + red[2] + red[3]) * (1.f / 512.f);
    float rs = rsqrtf(var + EPSF);
    float4 gg = ((const float4*)g)[tid], bv = ((const float4*)bb)[tid];
    float4 o;
    o.x = d0 * rs * gg.x + bv.x;
    o.y = d1 * rs * gg.y + bv.y;
    o.z = d2 * rs * gg.z + bv.z;
    o.w = d3 * rs * gg.w + bv.w;
    ((float4*)(out + (size_t)row * Ex))[tid] = o;
    if (out_r) {
        float4 orr = {f2tf(o.x), f2tf(o.y), f2tf(o.z), f2tf(o.w)};
        ((float4*)(out_r + (size_t)row * Ex))[tid] = orr;
    }
}

// ---------------------------------------------------------------------------
extern "C" void kernel_launch(void* const* d_in, const int* in_sizes, int n_in,
                              void* d_out, int out_size)
{
    const float* inputDec = (const float*)d_in[0];
    const float* posEmb   = (const float*)d_in[1];
    const float* u        = (const float*)d_in[2];
    const float* v        = (const float*)d_in[3];
    const float* memories = (const float*)d_in[4];
    const float* Wqkv     = (const float*)d_in[5];
    const float* Wr       = (const float*)d_in[6];
    const float* Wo       = (const float*)d_in[7];
    const float* ln1_g    = (const float*)d_in[8];
    const float* ln1_b    = (const float*)d_in[9];
    const float* W1       = (const float*)d_in[10];
    const float* b1       = (const float*)d_in[11];
    const float* W2       = (const float*)d_in[12];
    const float* b2       = (const float*)d_in[13];
    const float* ln2_g    = (const float*)d_in[14];
    const float* ln2_b    = (const float*)d_in[15];
    float* out = (float*)d_out;

    float *qkv, *rb, *attn, *tmp, *attnout, *attnout_r, *ff1, *ff2;
    float *mem_r, *inp_r, *pos_r, *wqkv_r, *wr_r, *wo_r, *w1_r, *w2_r;
    cudaGetSymbolAddress((void**)&qkv,       g_qkv);
    cudaGetSymbolAddress((void**)&rb,        g_r);
    cudaGetSymbolAddress((void**)&attn,      g_attn);
    cudaGetSymbolAddress((void**)&tmp,       g_tmp);
    cudaGetSymbolAddress((void**)&attnout,   g_attnout);
    cudaGetSymbolAddress((void**)&attnout_r, g_attnout_r);
    cudaGetSymbolAddress((void**)&ff1,       g_ff1);
    cudaGetSymbolAddress((void**)&ff2,       g_ff2);
    cudaGetSymbolAddress((void**)&mem_r,     g_mem_r);
    cudaGetSymbolAddress((void**)&inp_r,     g_inp_r);
    cudaGetSymbolAddress((void**)&pos_r,     g_pos_r);
    cudaGetSymbolAddress((void**)&wqkv_r,    g_wqkv_r);
    cudaGetSymbolAddress((void**)&wr_r,      g_wr_r);
    cudaGetSymbolAddress((void**)&wo_r,      g_wo_r);
    cudaGetSymbolAddress((void**)&w1_r,      g_w1_r);
    cudaGetSymbolAddress((void**)&w2_r,      g_w2_r);

    cudaFuncSetAttribute(flash, cudaFuncAttributeMaxDynamicSharedMemorySize, FLASH_SMEM);
    cudaFuncSetAttribute(tgemm<0,true,true>,   cudaFuncAttributeMaxDynamicSharedMemorySize, GEMM_SMEM);
    cudaFuncSetAttribute(tgemm<0,false,true>,  cudaFuncAttributeMaxDynamicSharedMemorySize, GEMM_SMEM);
    cudaFuncSetAttribute(tgemm<0,false,false>, cudaFuncAttributeMaxDynamicSharedMemorySize, GEMM_SMEM);
    cudaFuncSetAttribute(tgemm<2,false,true>,  cudaFuncAttributeMaxDynamicSharedMemorySize, GEMM_SMEM);
    cudaFuncSetAttribute(tgemm<1,false,false>, cudaFuncAttributeMaxDynamicSharedMemorySize, GEMM_SMEM);

    // 0) round raw operands to tf32 (RNA) — one launch, 8 segments
    {
        RSegs rs;
        const float* srcs[8] = {memories, inputDec, posEmb, Wqkv, Wr, Wo, W1, W2};
        float* dsts[8] = {mem_r, inp_r, pos_r, wqkv_r, wr_r, wo_r, w1_r, w2_r};
        size_t ns[8] = {(size_t)Mx*Bx*Ex, (size_t)Sx*Bx*Ex, (size_t)Kx*Ex,
                        (size_t)Ex*QKV3, (size_t)Ex*Ex, (size_t)Ex*Ex,
                        (size_t)Ex*FFx, (size_t)FFx*Ex};
        int maxb = 0;
        for (int i = 0; i < 8; i++) {
            rs.src[i] = (const float4*)srcs[i];
            rs.dst[i] = (float4*)dsts[i];
            rs.n4[i] = (int)(ns[i] / 4);
            int bl = (rs.n4[i] + 255) / 256;
            if (bl > maxb) maxb = bl;
        }
        roundall<<<dim3(maxb, 8), 256>>>(rs);
    }

    // 1) qkv = concat(memories, inputDec) @ Wqkv   (rounded output)
    tgemm<0,true,true><<<dim3(QKV3/128, KB_/128), 256, GEMM_SMEM>>>(
        mem_r, inp_r, Mx * Bx, wqkv_r, nullptr, qkv, QKV3, Ex);
    // 2) r = posEmbeddings @ Wr                    (rounded output)
    tgemm<0,false,true><<<dim3(Ex/128, Kx/128), 256, GEMM_SMEM>>>(
        pos_r, nullptr, 0, wr_r, nullptr, rb, Ex, Ex);
    // 3) fused rel-pos flash attention (tensor cores, 2 key-split groups)
    flash<<<dim3(Sx/64, Bx*Hx), 256, FLASH_SMEM>>>(qkv, rb, u, v, attn);
    // 4) attn @ Wo
    tgemm<0,false,false><<<dim3(Ex/128, ROWS/128), 256, GEMM_SMEM>>>(
        attn, nullptr, 0, wo_r, nullptr, tmp, Ex, Ex);
    // 5) attn_out = LN(inputDec + attnWo)  (+ rounded copy for FF1)
    ln_add_kernel<<<ROWS, 128>>>(inputDec, tmp, ln1_g, ln1_b, attnout, attnout_r);
    // 6) ff1 = relu(attn_out @ W1 + b1)            (rounded output)
    tgemm<2,false,true><<<dim3(FFx/128, ROWS/128), 256, GEMM_SMEM>>>(
        attnout_r, nullptr, 0, w1_r, b1, ff1, FFx, Ex);
    // 7) ff2 = ff1 @ W2 + b2
    tgemm<1,false,false><<<dim3(Ex/128, ROWS/128), 256, GEMM_SMEM>>>(
        ff1, nullptr, 0, w2_r, b2, ff2, Ex, FFx);
    // 8) out = LN(attn_out + ff2)
    ln_add_kernel<<<ROWS, 128>>>(attnout, ff2, ln2_g, ln2_b, out, nullptr);
}

// round 5
// speedup vs baseline: 12.0222x; 1.3882x over previous
#include <cuda_runtime.h>
#include <cuda_fp16.h>
#include <cstdint>

#define Sx 2048
#define Bx 2
#define Ex 512
#define Hx 8
#define Mx 2048
#define Kx 4096          // M + S
#define QKV3 1536
#define FFx 2048
#define ROWS (Sx*Bx)     // 4096
#define KB_ (Kx*Bx)      // 8192
#define EPSF 1e-5f

// ---------------- scratch (static device arrays: no allocation) -------------
__device__ __align__(128) __half g_qkv[(size_t)KB_ * QKV3];
__device__ __align__(128) __half g_rb[(size_t)Kx * Ex];
__device__ __align__(128) __half g_attn[(size_t)ROWS * Ex];
__device__ __align__(128) float  g_tmp[(size_t)ROWS * Ex];
__device__ __align__(128) float  g_attnout[(size_t)ROWS * Ex];
__device__ __align__(128) __half g_attnout_h[(size_t)ROWS * Ex];
__device__ __align__(128) __half g_ff1[(size_t)ROWS * FFx];
__device__ __align__(128) float  g_ff2[(size_t)ROWS * Ex];
__device__ __align__(128) __half g_mem_h[(size_t)Mx * Bx * Ex];
__device__ __align__(128) __half g_inp_h[(size_t)Sx * Bx * Ex];
__device__ __align__(128) __half g_pos_h[(size_t)Kx * Ex];
__device__ __align__(128) __half g_wqkv_t[(size_t)QKV3 * Ex];
__device__ __align__(128) __half g_wr_t[(size_t)Ex * Ex];
__device__ __align__(128) __half g_wo_t[(size_t)Ex * Ex];
__device__ __align__(128) __half g_w1_t[(size_t)FFx * Ex];
__device__ __align__(128) __half g_w2_t[(size_t)Ex * FFx];

// ---------------- helpers ---------------------------------------------------
__device__ __forceinline__ void mma16(float* d, const unsigned* a, const unsigned* b) {
    asm volatile(
        "mma.sync.aligned.m16n8k16.row.col.f32.f16.f16.f32 "
        "{%0,%1,%2,%3},{%4,%5,%6,%7},{%8,%9},{%0,%1,%2,%3};\n"
        : "+f"(d[0]), "+f"(d[1]), "+f"(d[2]), "+f"(d[3])
        : "r"(a[0]), "r"(a[1]), "r"(a[2]), "r"(a[3]), "r"(b[0]), "r"(b[1]));
}
__device__ __forceinline__ unsigned sptr(const void* p) {
    return (unsigned)__cvta_generic_to_shared(p);
}
__device__ __forceinline__ void cpa16(unsigned d, const void* s) {
    asm volatile("cp.async.cg.shared.global [%0], [%1], 16;\n" :: "r"(d), "l"(s));
}
__device__ __forceinline__ void cpcommit() { asm volatile("cp.async.commit_group;\n"); }
template<int N> __device__ __forceinline__ void cpwait() {
    asm volatile("cp.async.wait_group %0;\n" :: "n"(N));
}
__device__ __forceinline__ void barg(int id) {
    asm volatile("bar.sync %0, 128;" :: "r"(id) : "memory");
}
__device__ __forceinline__ unsigned ldu32(const __half* p) { return *(const unsigned*)p; }
__device__ __forceinline__ unsigned packh(__half a, __half b) {
    __half2 h = __halves2half2(a, b);
    return *(unsigned*)&h;
}

// ---------------- fp32 -> fp16 conversion, 3 segments in one launch ---------
struct CSegs { const float4* src[3]; uint2* dst[3]; int n4[3]; };
__global__ void cvtall(CSegs segs) {
    int seg = blockIdx.y;
    int i = blockIdx.x * 256 + threadIdx.x;
    if (i < segs.n4[seg]) {
        float4 v = segs.src[seg][i];
        __half2 h01 = __floats2half2_rn(v.x, v.y);
        __half2 h23 = __floats2half2_rn(v.z, v.w);
        segs.dst[seg][i] = make_uint2(*(unsigned*)&h01, *(unsigned*)&h23);
    }
}

// ---------------- weight transpose + fp16 convert: Wt[n][k] = W[k][n] -------
__global__ void transw(const float* __restrict__ W, __half* __restrict__ Wt,
                       int K, int N) {
    __shared__ float t[32][33];
    int k0 = blockIdx.y * 32, n0 = blockIdx.x * 32;
    int tx = threadIdx.x, ty = threadIdx.y;   // 32 x 8
#pragma unroll
    for (int j = 0; j < 4; j++)
        t[ty + j * 8][tx] = W[(size_t)(k0 + ty + j * 8) * N + n0 + tx];
    __syncthreads();
#pragma unroll
    for (int j = 0; j < 4; j++)
        Wt[(size_t)(n0 + ty + j * 8) * K + k0 + tx] = __float2half_rn(t[tx][ty + j * 8]);
}

// ---------------- FP16 GEMM: C(MxN)=A(MxK)*Bt(NxK)^T, 128x128x32 ------------
#define AH 40          // smem row stride in halfs (80B, 16B-mult, conflict-free)
#define GEMM_SMEM (4*128*AH*2)   // A(2 buf) + B(2 buf), halfs

template<int EPI, bool SPLITA, bool OUTH>
__global__ __launch_bounds__(256, 2) void tgemm(
    const __half* __restrict__ A0, const __half* __restrict__ A1, int splitRow,
    const __half* __restrict__ Bt, const float* __restrict__ bias,
    void* __restrict__ Cv, int Nd, int Kd)
{
    extern __shared__ __align__(16) __half sh[];
    __half* As = sh;                   // [2][128][AH]
    __half* Bs = sh + 2 * 128 * AH;    // [2][128][AH]
    const int tid = threadIdx.x, lane = tid & 31, wid = tid >> 5;
    const int wm = wid >> 2, wn = wid & 3, g = lane >> 2, t = lane & 3;
    const int bm = blockIdx.y * 128, bn = blockIdx.x * 128;

    const __half* asrc[2]; const __half* bsrc[2];
    unsigned adst[2], bdst[2];
#pragma unroll
    for (int p = 0; p < 2; p++) {
        int id = tid + p * 256;
        int r = id >> 2, c8 = (id & 3) * 8;
        int grow = bm + r;
        const __half* abase = (SPLITA && grow >= splitRow)
                              ? (A1 + (size_t)(grow - splitRow) * Kd)
                              : (A0 + (size_t)grow * Kd);
        asrc[p] = abase + c8;
        adst[p] = sptr(As + r * AH + c8);
        bsrc[p] = Bt + (size_t)(bn + r) * Kd + c8;
        bdst[p] = sptr(Bs + r * AH + c8);
    }
    const unsigned BUF = 128 * AH * 2;   // bytes per buffer

    float acc[4][4][4];
#pragma unroll
    for (int i = 0; i < 4; i++)
#pragma unroll
        for (int j = 0; j < 4; j++)
#pragma unroll
            for (int r = 0; r < 4; r++) acc[i][j][r] = 0.f;

    {
#pragma unroll
        for (int p = 0; p < 2; p++) { cpa16(adst[p], asrc[p]); cpa16(bdst[p], bsrc[p]); }
        cpcommit();
    }

    int nkt = Kd >> 5;
    for (int kt = 0; kt < nkt; kt++) {
        int pb = kt & 1;
        if (kt + 1 < nkt) {
            int k0 = (kt + 1) << 5;
            unsigned off = (pb ^ 1) * BUF;
#pragma unroll
            for (int p = 0; p < 2; p++) {
                cpa16(adst[p] + off, asrc[p] + k0);
                cpa16(bdst[p] + off, bsrc[p] + k0);
            }
            cpcommit();
            cpwait<1>();
        } else cpwait<0>();
        __syncthreads();

        const __half* Ab = As + pb * 128 * AH + (wm * 64 + g) * AH;
        const __half* Bb = Bs + pb * 128 * AH + (wn * 32 + g) * AH;
#pragma unroll
        for (int ks = 0; ks < 2; ks++) {
            unsigned a[4][4], b[4][2];
            int k2 = ks * 16 + 2 * t;
#pragma unroll
            for (int mf = 0; mf < 4; mf++) {
                const __half* pa = Ab + mf * 16 * AH + k2;
                a[mf][0] = ldu32(pa);
                a[mf][1] = ldu32(pa + 8 * AH);
                a[mf][2] = ldu32(pa + 8);
                a[mf][3] = ldu32(pa + 8 * AH + 8);
            }
#pragma unroll
            for (int nf = 0; nf < 4; nf++) {
                const __half* pbp = Bb + nf * 8 * AH + k2;
                b[nf][0] = ldu32(pbp);
                b[nf][1] = ldu32(pbp + 8);
            }
#pragma unroll
            for (int mf = 0; mf < 4; mf++)
#pragma unroll
                for (int nf = 0; nf < 4; nf++) mma16(acc[mf][nf], a[mf], b[nf]);
        }
        __syncthreads();
    }

#pragma unroll
    for (int mf = 0; mf < 4; mf++) {
        int r0 = bm + wm * 64 + mf * 16 + g;
#pragma unroll
        for (int nf = 0; nf < 4; nf++) {
            int c = bn + wn * 32 + nf * 8 + 2 * t;
            float v0 = acc[mf][nf][0], v1 = acc[mf][nf][1];
            float v2 = acc[mf][nf][2], v3 = acc[mf][nf][3];
            if (EPI >= 1) {
                float b0 = bias[c], b1v = bias[c + 1];
                v0 += b0; v1 += b1v; v2 += b0; v3 += b1v;
            }
            if (EPI == 2) {
                v0 = fmaxf(v0, 0.f); v1 = fmaxf(v1, 0.f);
                v2 = fmaxf(v2, 0.f); v3 = fmaxf(v3, 0.f);
            }
            if (OUTH) {
                __half* C = (__half*)Cv;
                __half2 h0 = __floats2half2_rn(v0, v1);
                __half2 h1 = __floats2half2_rn(v2, v3);
                *(__half2*)(C + (size_t)r0 * Nd + c)       = h0;
                *(__half2*)(C + (size_t)(r0 + 8) * Nd + c) = h1;
            } else {
                float* C = (float*)Cv;
                *(float2*)(C + (size_t)r0 * Nd + c)       = make_float2(v0, v1);
                *(float2*)(C + (size_t)(r0 + 8) * Nd + c) = make_float2(v2, v3);
            }
        }
    }
}

// ---------------- Flash attention (FP16 mma) with XL rel-shift --------------
// Same structure as R4 (2 key-split warp-groups, trimmed BD band, final merge)
// but fp16 operands + m16n8k16. C-fragment layout identical to m16n8k8, so all
// diagonal/mask/softmax/merge logic carries over.
#define FST 72                    // half stride for Q/K/V/R/P rows (144B)
#define BDW 84                    // fp32 band stride (80 band + 2 stats)
#define OFF_QU 0
#define OFF_QV 9216
#define OFF_K  18432
#define OFF_V  36864
#define OFF_R  55296
#define OFF_BD 92160
#define OFF_P  135168
#define FLASH_SMEM 153600

__global__ __launch_bounds__(256, 1) void flash(
    const __half* __restrict__ qkv, const __half* __restrict__ rbuf,
    const float* __restrict__ u, const float* __restrict__ v,
    __half* __restrict__ attn)
{
    extern __shared__ __align__(16) char smc[];
    __half* Qu = (__half*)(smc + OFF_QU);
    __half* Qv = (__half*)(smc + OFF_QV);
    __half* Ks = (__half*)(smc + OFF_K);
    __half* Vs = (__half*)(smc + OFF_V);
    __half* Rs = (__half*)(smc + OFF_R);
    float*  BDb = (float*)(smc + OFF_BD);
    __half* Pb = (__half*)(smc + OFF_P);
    const int tid = threadIdx.x, lane = tid & 31, wid = tid >> 5;
    const int g = lane >> 2, t = lane & 3;
    const int gr = wid >> 2, wg = wid & 3;     // group, warp-in-group
    const int gtid = tid & 127;
    const int qt = (gridDim.x - 1) - blockIdx.x;   // heavy tiles first
    const int b = blockIdx.y >> 3, h = blockIdx.y & 7;
    const int s0 = qt * 64, hoff = h * 64;

    // stage loads: group gr into buffer gr (single buffer per group)
    auto issue = [&](int kt) {
        int k0 = kt * 64;
#pragma unroll
        for (int p = 0; p < 4; p++) {
            int id = gtid + p * 128;
            int key = id >> 3, c = (id & 7) * 8;
            const __half* src = qkv + ((size_t)(k0 + key) * Bx + b) * QKV3 + 512 + hoff + c;
            cpa16(sptr(Ks + gr * 64 * FST + key * FST + c), src);
            cpa16(sptr(Vs + gr * 64 * FST + key * FST + c), src + 512);
        }
        int jlo = k0 + (Sx - 1) - s0 - 63;
#pragma unroll
        for (int p = 0; p < 8; p++) {
            int id = gtid + p * 128;
            int d = id >> 3, c = (id & 7) * 8;
            int j = jlo + d; if (j > Kx - 1) j = Kx - 1;   // clamped cells are masked
            cpa16(sptr(Rs + gr * 128 * FST + d * FST + c), rbuf + (size_t)j * Ex + hoff + c);
        }
        cpcommit();
    };
    issue(gr);

    // Q tiles (+u / +v) -> fp16
    for (int idx = tid; idx < 64 * 64; idx += 256) {
        int sR = idx >> 6, i = idx & 63;
        float qv_ = __half2float(qkv[((size_t)(Mx + s0 + sR) * Bx + b) * QKV3 + hoff + i]);
        Qu[sR * FST + i] = __float2half_rn(qv_ + u[hoff + i]);
        Qv[sR * FST + i] = __float2half_rn(qv_ + v[hoff + i]);
    }
    __syncthreads();

    float m0 = -1e30f, m1 = -1e30f, l0 = 0.f, l1 = 0.f;
    float O[8][4];
#pragma unroll
    for (int i = 0; i < 8; i++)
#pragma unroll
        for (int j = 0; j < 4; j++) O[i][j] = 0.f;

    const __half* Aqu = Qu + (wg * 16 + g) * FST;
    const __half* Aqv = Qv + (wg * 16 + g) * FST;
    float* BDrow = BDb + (wid * 16 + g) * BDW;
    __half* Prow = Pb + (wid * 16 + g) * FST;
    const __half* Kp = Ks + gr * 64 * FST;
    const __half* Vp = Vs + gr * 64 * FST;
    const __half* Rp = Rs + gr * 128 * FST;
    const int c_base = 48 - wg * 16;               // warp band origin in R stage
    const int nkt = qt + 33;

    for (int kt = gr; kt < nkt; kt += 2) {
        int k0 = kt * 64;
        cpwait<0>();
        barg(gr + 1);

        // ---- BD band mma: 16 x 80 per warp -> fp32 smem
        {
            float bd[10][4];
#pragma unroll
            for (int nf = 0; nf < 10; nf++)
#pragma unroll
                for (int j = 0; j < 4; j++) bd[nf][j] = 0.f;
#pragma unroll
            for (int ks = 0; ks < 4; ks++) {
                int k2 = ks * 16 + 2 * t;
                unsigned a[4];
                a[0] = ldu32(Aqv + k2);
                a[1] = ldu32(Aqv + 8 * FST + k2);
                a[2] = ldu32(Aqv + k2 + 8);
                a[3] = ldu32(Aqv + 8 * FST + k2 + 8);
#pragma unroll
                for (int nf = 0; nf < 10; nf++) {
                    const __half* pb = Rp + (c_base + nf * 8 + g) * FST + k2;
                    unsigned bb[2] = {ldu32(pb), ldu32(pb + 8)};
                    mma16(bd[nf], a, bb);
                }
            }
#pragma unroll
            for (int nf = 0; nf < 10; nf++) {
                *(float2*)(BDrow + nf * 8 + 2 * t) = make_float2(bd[nf][0], bd[nf][1]);
                *(float2*)(BDrow + 8 * BDW + nf * 8 + 2 * t) = make_float2(bd[nf][2], bd[nf][3]);
            }
        }
        __syncwarp();

        // ---- AC mma: 16 x 64 per warp
        float ac[8][4];
#pragma unroll
        for (int nf = 0; nf < 8; nf++)
#pragma unroll
            for (int j = 0; j < 4; j++) ac[nf][j] = 0.f;
#pragma unroll
        for (int ks = 0; ks < 4; ks++) {
            int k2 = ks * 16 + 2 * t;
            unsigned a[4];
            a[0] = ldu32(Aqu + k2);
            a[1] = ldu32(Aqu + 8 * FST + k2);
            a[2] = ldu32(Aqu + k2 + 8);
            a[3] = ldu32(Aqu + 8 * FST + k2 + 8);
#pragma unroll
            for (int nf = 0; nf < 8; nf++) {
                const __half* pb = Kp + (nf * 8 + g) * FST + k2;
                unsigned bb[2] = {ldu32(pb), ldu32(pb + 8)};
                mma16(ac[nf], a, bb);
            }
        }

        // ---- combine with BD diagonal + mask (local band x = kc + 15 - g)
        {
            int lim0 = s0 + wg * 16 + g + Mx, lim1 = lim0 + 8;
#pragma unroll
            for (int nf = 0; nf < 8; nf++) {
                int kc = nf * 8 + 2 * t;
                float v0 = (ac[nf][0] + BDrow[kc + 15 - g]) * 0.125f;
                float v1 = (ac[nf][1] + BDrow[kc + 16 - g]) * 0.125f;
                float v2 = (ac[nf][2] + BDrow[8 * BDW + kc + 7 - g]) * 0.125f;
                float v3 = (ac[nf][3] + BDrow[8 * BDW + kc + 8 - g]) * 0.125f;
                if (k0 + kc > lim0)     v0 = -1e30f;
                if (k0 + kc + 1 > lim0) v1 = -1e30f;
                if (k0 + kc > lim1)     v2 = -1e30f;
                if (k0 + kc + 1 > lim1) v3 = -1e30f;
                ac[nf][0] = v0; ac[nf][1] = v1; ac[nf][2] = v2; ac[nf][3] = v3;
            }
        }

        // ---- online softmax (rows g, g+8; reduce over quad lanes)
        {
            float mx0 = -1e30f, mx1 = -1e30f;
#pragma unroll
            for (int nf = 0; nf < 8; nf++) {
                mx0 = fmaxf(mx0, fmaxf(ac[nf][0], ac[nf][1]));
                mx1 = fmaxf(mx1, fmaxf(ac[nf][2], ac[nf][3]));
            }
            mx0 = fmaxf(mx0, __shfl_xor_sync(0xffffffffu, mx0, 1));
            mx0 = fmaxf(mx0, __shfl_xor_sync(0xffffffffu, mx0, 2));
            mx1 = fmaxf(mx1, __shfl_xor_sync(0xffffffffu, mx1, 1));
            mx1 = fmaxf(mx1, __shfl_xor_sync(0xffffffffu, mx1, 2));
            float mn0 = fmaxf(m0, mx0), mn1 = fmaxf(m1, mx1);
            float c0 = __expf(m0 - mn0), c1 = __expf(m1 - mn1);
            float rs0 = 0.f, rs1 = 0.f;
#pragma unroll
            for (int nf = 0; nf < 8; nf++) {
                float p0 = __expf(ac[nf][0] - mn0);
                float p1 = __expf(ac[nf][1] - mn0);
                float p2 = __expf(ac[nf][2] - mn1);
                float p3 = __expf(ac[nf][3] - mn1);
                rs0 += p0 + p1; rs1 += p2 + p3;
                *(__half2*)(Prow + nf * 8 + 2 * t) = __floats2half2_rn(p0, p1);
                *(__half2*)(Prow + 8 * FST + nf * 8 + 2 * t) = __floats2half2_rn(p2, p3);
            }
            rs0 += __shfl_xor_sync(0xffffffffu, rs0, 1);
            rs0 += __shfl_xor_sync(0xffffffffu, rs0, 2);
            rs1 += __shfl_xor_sync(0xffffffffu, rs1, 1);
            rs1 += __shfl_xor_sync(0xffffffffu, rs1, 2);
            l0 = l0 * c0 + rs0; l1 = l1 * c1 + rs1;
            m0 = mn0; m1 = mn1;
#pragma unroll
            for (int nf = 0; nf < 8; nf++) {
                O[nf][0] *= c0; O[nf][1] *= c0; O[nf][2] *= c1; O[nf][3] *= c1;
            }
        }
        __syncwarp();

        // ---- P·V mma: A = P (fp16 smem), B = V via LDS.16 transpose packs
#pragma unroll
        for (int ks = 0; ks < 4; ks++) {
            int k2 = ks * 16 + 2 * t;
            unsigned a[4];
            a[0] = ldu32(Prow + k2);
            a[1] = ldu32(Prow + 8 * FST + k2);
            a[2] = ldu32(Prow + k2 + 8);
            a[3] = ldu32(Prow + 8 * FST + k2 + 8);
#pragma unroll
            for (int nf = 0; nf < 8; nf++) {
                int n = nf * 8 + g;
                const __half* vb = Vp + k2 * FST + n;
                unsigned bb[2];
                bb[0] = packh(vb[0], vb[FST]);
                bb[1] = packh(vb[8 * FST], vb[9 * FST]);
                mma16(O[nf], a, bb);
            }
        }

        barg(gr + 1);   // group done with buffer before refill
        if (kt + 2 < nkt) issue(kt + 2);
    }

    // ---- merge the two groups' partial softmax states, write output --------
    if (wid >= 4) {
#pragma unroll
        for (int nf = 0; nf < 8; nf++) {
            *(float2*)(BDrow + nf * 8 + 2 * t) = make_float2(O[nf][0], O[nf][1]);
            *(float2*)(BDrow + 8 * BDW + nf * 8 + 2 * t) = make_float2(O[nf][2], O[nf][3]);
        }
        if (t == 0) {
            BDrow[80] = m0; BDrow[81] = l0;
            BDrow[8 * BDW + 80] = m1; BDrow[8 * BDW + 81] = l1;
        }
    }
    __syncthreads();
    if (wid < 4) {
        const float* Peer = BDb + ((wid + 4) * 16 + g) * BDW;
        float pm0 = Peer[80], pl0 = Peer[81];
        float pm1 = Peer[8 * BDW + 80], pl1 = Peer[8 * BDW + 81];
        float M0 = fmaxf(m0, pm0), M1 = fmaxf(m1, pm1);
        float a0 = __expf(m0 - M0), e0 = __expf(pm0 - M0);
        float a1 = __expf(m1 - M1), e1 = __expf(pm1 - M1);
        float i0 = 1.0f / (l0 * a0 + pl0 * e0);
        float i1 = 1.0f / (l1 * a1 + pl1 * e1);
        int sg0 = s0 + wid * 16 + g;
#pragma unroll
        for (int nf = 0; nf < 8; nf++) {
            int c = hoff + nf * 8 + 2 * t;
            float2 po0 = *(const float2*)(Peer + nf * 8 + 2 * t);
            float2 po1 = *(const float2*)(Peer + 8 * BDW + nf * 8 + 2 * t);
            *(__half2*)(attn + ((size_t)sg0 * Bx + b) * Ex + c) =
                __floats2half2_rn((O[nf][0] * a0 + po0.x * e0) * i0,
                                  (O[nf][1] * a0 + po0.y * e0) * i0);
            *(__half2*)(attn + ((size_t)(sg0 + 8) * Bx + b) * Ex + c) =
                __floats2half2_rn((O[nf][2] * a1 + po1.x * e1) * i1,
                                  (O[nf][3] * a1 + po1.y * e1) * i1);
        }
    }
}

// ---------------- LayerNorm(X + Y); optional fp16 second copy ---------------
__global__ void ln_add_kernel(const float* __restrict__ X, const float* __restrict__ Y,
                              const float* __restrict__ g, const float* __restrict__ bb,
                              float* __restrict__ out, __half* __restrict__ out_h)
{
    __shared__ float red[4];
    int row = blockIdx.x;
    int tid = threadIdx.x;   // 128 threads, 4 floats each
    const float4* X4 = (const float4*)(X + (size_t)row * Ex);
    const float4* Y4 = (const float4*)(Y + (size_t)row * Ex);
    float4 x = X4[tid], y = Y4[tid];
    float4 vv = {x.x + y.x, x.y + y.y, x.z + y.z, x.w + y.w};
    float s = vv.x + vv.y + vv.z + vv.w;
#pragma unroll
    for (int off = 16; off; off >>= 1) s += __shfl_xor_sync(0xffffffffu, s, off);
    if ((tid & 31) == 0) red[tid >> 5] = s;
    __syncthreads();
    float mu = (red[0] + red[1] + red[2] + red[3]) * (1.f / 512.f);
    float d0 = vv.x - mu, d1 = vv.y - mu, d2 = vv.z - mu, d3 = vv.w - mu;
    float q = d0 * d0 + d1 * d1 + d2 * d2 + d3 * d3;
    __syncthreads();
#pragma unroll
    for (int off = 16; off; off >>= 1) q += __shfl_xor_sync(0xffffffffu, q, off);
    if ((tid & 31) == 0) red[tid >> 5] = q;
    __syncthreads();
    float var = (red[0] + red[1] + red[2] + red[3]) * (1.f / 512.f);
    float rs = rsqrtf(var + EPSF);
    float4 gg = ((const float4*)g)[tid], bv = ((const float4*)bb)[tid];
    float4 o;
    o.x = d0 * rs * gg.x + bv.x;
    o.y = d1 * rs * gg.y + bv.y;
    o.z = d2 * rs * gg.z + bv.z;
    o.w = d3 * rs * gg.w + bv.w;
    ((float4*)(out + (size_t)row * Ex))[tid] = o;
    if (out_h) {
        __half2* oh = (__half2*)(out_h + (size_t)row * Ex);
        oh[tid * 2]     = __floats2half2_rn(o.x, o.y);
        oh[tid * 2 + 1] = __floats2half2_rn(o.z, o.w);
    }
}

// ---------------------------------------------------------------------------
extern "C" void kernel_launch(void* const* d_in, const int* in_sizes, int n_in,
                              void* d_out, int out_size)
{
    const float* inputDec = (const float*)d_in[0];
    const float* posEmb   = (const float*)d_in[1];
    const float* u        = (const float*)d_in[2];
    const float* v        = (const float*)d_in[3];
    const float* memories = (const float*)d_in[4];
    const float* Wqkv     = (const float*)d_in[5];
    const float* Wr       = (const float*)d_in[6];
    const float* Wo       = (const float*)d_in[7];
    const float* ln1_g    = (const float*)d_in[8];
    const float* ln1_b    = (const float*)d_in[9];
    const float* W1       = (const float*)d_in[10];
    const float* b1       = (const float*)d_in[11];
    const float* W2       = (const float*)d_in[12];
    const float* b2       = (const float*)d_in[13];
    const float* ln2_g    = (const float*)d_in[14];
    const float* ln2_b    = (const float*)d_in[15];
    float* out = (float*)d_out;

    __half *qkv, *rb, *attn, *attnout_h, *ff1;
    __half *mem_h, *inp_h, *pos_h, *wqkv_t, *wr_t, *wo_t, *w1_t, *w2_t;
    float *tmp, *attnout, *ff2;
    cudaGetSymbolAddress((void**)&qkv,       g_qkv);
    cudaGetSymbolAddress((void**)&rb,        g_rb);
    cudaGetSymbolAddress((void**)&attn,      g_attn);
    cudaGetSymbolAddress((void**)&tmp,       g_tmp);
    cudaGetSymbolAddress((void**)&attnout,   g_attnout);
    cudaGetSymbolAddress((void**)&attnout_h, g_attnout_h);
    cudaGetSymbolAddress((void**)&ff1,       g_ff1);
    cudaGetSymbolAddress((void**)&ff2,       g_ff2);
    cudaGetSymbolAddress((void**)&mem_h,     g_mem_h);
    cudaGetSymbolAddress((void**)&inp_h,     g_inp_h);
    cudaGetSymbolAddress((void**)&pos_h,     g_pos_h);
    cudaGetSymbolAddress((void**)&wqkv_t,    g_wqkv_t);
    cudaGetSymbolAddress((void**)&wr_t,      g_wr_t);
    cudaGetSymbolAddress((void**)&wo_t,      g_wo_t);
    cudaGetSymbolAddress((void**)&w1_t,      g_w1_t);
    cudaGetSymbolAddress((void**)&w2_t,      g_w2_t);

    cudaFuncSetAttribute(flash, cudaFuncAttributeMaxDynamicSharedMemorySize, FLASH_SMEM);
    cudaFuncSetAttribute(tgemm<0,true,true>,   cudaFuncAttributeMaxDynamicSharedMemorySize, GEMM_SMEM);
    cudaFuncSetAttribute(tgemm<0,false,true>,  cudaFuncAttributeMaxDynamicSharedMemorySize, GEMM_SMEM);
    cudaFuncSetAttribute(tgemm<0,false,false>, cudaFuncAttributeMaxDynamicSharedMemorySize, GEMM_SMEM);
    cudaFuncSetAttribute(tgemm<2,false,true>,  cudaFuncAttributeMaxDynamicSharedMemorySize, GEMM_SMEM);
    cudaFuncSetAttribute(tgemm<1,false,false>, cudaFuncAttributeMaxDynamicSharedMemorySize, GEMM_SMEM);

    // 0a) activations fp32 -> fp16 (one launch, 3 segments)
    {
        CSegs cs;
        cs.src[0] = (const float4*)memories; cs.dst[0] = (uint2*)mem_h;
        cs.n4[0] = (int)((size_t)Mx * Bx * Ex / 4);
        cs.src[1] = (const float4*)inputDec; cs.dst[1] = (uint2*)inp_h;
        cs.n4[1] = (int)((size_t)Sx * Bx * Ex / 4);
        cs.src[2] = (const float4*)posEmb;   cs.dst[2] = (uint2*)pos_h;
        cs.n4[2] = (int)((size_t)Kx * Ex / 4);
        int maxb = 0;
        for (int i = 0; i < 3; i++) { int bl = (cs.n4[i] + 255) / 256; if (bl > maxb) maxb = bl; }
        cvtall<<<dim3(maxb, 3), 256>>>(cs);
    }
    // 0b) weights fp32 -> fp16 transposed [N][K]
    transw<<<dim3(QKV3/32, Ex/32), dim3(32,8)>>>(Wqkv, wqkv_t, Ex, QKV3);
    transw<<<dim3(Ex/32,   Ex/32), dim3(32,8)>>>(Wr,   wr_t,   Ex, Ex);
    transw<<<dim3(Ex/32,   Ex/32), dim3(32,8)>>>(Wo,   wo_t,   Ex, Ex);
    transw<<<dim3(FFx/32,  Ex/32), dim3(32,8)>>>(W1,   w1_t,   Ex, FFx);
    transw<<<dim3(Ex/32,  FFx/32), dim3(32,8)>>>(W2,   w2_t,   FFx, Ex);

    // 1) qkv = concat(memories, inputDec) @ Wqkv   -> half
    tgemm<0,true,true><<<dim3(QKV3/128, KB_/128), 256, GEMM_SMEM>>>(
        mem_h, inp_h, Mx * Bx, wqkv_t, nullptr, qkv, QKV3, Ex);
    // 2) r = posEmbeddings @ Wr                    -> half
    tgemm<0,false,true><<<dim3(Ex/128, Kx/128), 256, GEMM_SMEM>>>(
        pos_h, nullptr, 0, wr_t, nullptr, rb, Ex, Ex);
    // 3) fused rel-pos flash attention (fp16 tensor cores)
    flash<<<dim3(Sx/64, Bx*Hx), 256, FLASH_SMEM>>>(qkv, rb, u, v, attn);
    // 4) attn @ Wo                                 -> fp32
    tgemm<0,false,false><<<dim3(Ex/128, ROWS/128), 256, GEMM_SMEM>>>(
        attn, nullptr, 0, wo_t, nullptr, tmp, Ex, Ex);
    // 5) attn_out = LN(inputDec + attnWo)  (+ fp16 copy for FF1)
    ln_add_kernel<<<ROWS, 128>>>(inputDec, tmp, ln1_g, ln1_b, attnout, attnout_h);
    // 6) ff1 = relu(attn_out @ W1 + b1)            -> half
    tgemm<2,false,true><<<dim3(FFx/128, ROWS/128), 256, GEMM_SMEM>>>(
        attnout_h, nullptr, 0, w1_t, b1, ff1, FFx, Ex);
    // 7) ff2 = ff1 @ W2 + b2                       -> fp32
    tgemm<1,false,false><<<dim3(Ex/128, ROWS/128), 256, GEMM_SMEM>>>(
        ff1, nullptr, 0, w2_t, b2, ff2, Ex, FFx);
    // 8) out = LN(attn_out + ff2)
    ln_add_kernel<<<ROWS, 128>>>(attnout, ff2, ln2_g, ln2_b, out, nullptr);
}

// round 6
// speedup vs baseline: 12.0626x; 1.0034x over previous
#include <cuda_runtime.h>
#include <cuda_fp16.h>
#include <cstdint>

#define Sx 2048
#define Bx 2
#define Ex 512
#define Hx 8
#define Mx 2048
#define Kx 4096          // M + S
#define QKV3 1536
#define FFx 2048
#define ROWS (Sx*Bx)     // 4096
#define KB_ (Kx*Bx)      // 8192
#define EPSF 1e-5f
#define SCL 0.18033688f  // 0.125 * log2(e): softmax done in base-2 domain

// ---------------- scratch (static device arrays: no allocation) -------------
__device__ __align__(128) __half g_qkv[(size_t)KB_ * QKV3];
__device__ __align__(128) __half g_rb[(size_t)Kx * Ex];
__device__ __align__(128) __half g_vt[(size_t)Bx * Ex * Kx];
__device__ __align__(128) __half g_attn[(size_t)ROWS * Ex];
__device__ __align__(128) float  g_tmp[(size_t)ROWS * Ex];
__device__ __align__(128) float  g_attnout[(size_t)ROWS * Ex];
__device__ __align__(128) __half g_attnout_h[(size_t)ROWS * Ex];
__device__ __align__(128) __half g_ff1[(size_t)ROWS * FFx];
__device__ __align__(128) float  g_ff2[(size_t)ROWS * Ex];
__device__ __align__(128) __half g_mem_h[(size_t)Mx * Bx * Ex];
__device__ __align__(128) __half g_inp_h[(size_t)Sx * Bx * Ex];
__device__ __align__(128) __half g_pos_h[(size_t)Kx * Ex];
__device__ __align__(128) __half g_wqkv_t[(size_t)QKV3 * Ex];
__device__ __align__(128) __half g_wr_t[(size_t)Ex * Ex];
__device__ __align__(128) __half g_wo_t[(size_t)Ex * Ex];
__device__ __align__(128) __half g_w1_t[(size_t)FFx * Ex];
__device__ __align__(128) __half g_w2_t[(size_t)Ex * FFx];

// ---------------- helpers ---------------------------------------------------
__device__ __forceinline__ void mma16(float* d, const unsigned* a, const unsigned* b) {
    asm volatile(
        "mma.sync.aligned.m16n8k16.row.col.f32.f16.f16.f32 "
        "{%0,%1,%2,%3},{%4,%5,%6,%7},{%8,%9},{%0,%1,%2,%3};\n"
        : "+f"(d[0]), "+f"(d[1]), "+f"(d[2]), "+f"(d[3])
        : "r"(a[0]), "r"(a[1]), "r"(a[2]), "r"(a[3]), "r"(b[0]), "r"(b[1]));
}
__device__ __forceinline__ void ldmx4(unsigned* r, unsigned a) {
    asm volatile("ldmatrix.sync.aligned.m8n8.x4.shared.b16 {%0,%1,%2,%3}, [%4];"
        : "=r"(r[0]), "=r"(r[1]), "=r"(r[2]), "=r"(r[3]) : "r"(a));
}
__device__ __forceinline__ float ex2f(float x) {
    float r; asm("ex2.approx.f32 %0, %1;" : "=f"(r) : "f"(x)); return r;
}
__device__ __forceinline__ unsigned sptr(const void* p) {
    return (unsigned)__cvta_generic_to_shared(p);
}
__device__ __forceinline__ void cpa16(unsigned d, const void* s) {
    asm volatile("cp.async.cg.shared.global [%0], [%1], 16;\n" :: "r"(d), "l"(s));
}
__device__ __forceinline__ void cpcommit() { asm volatile("cp.async.commit_group;\n"); }
template<int N> __device__ __forceinline__ void cpwait() {
    asm volatile("cp.async.wait_group %0;\n" :: "n"(N));
}
__device__ __forceinline__ void barg(int id) {
    asm volatile("bar.sync %0, 128;" :: "r"(id) : "memory");
}
__device__ __forceinline__ unsigned ldu32(const __half* p) { return *(const unsigned*)p; }

// ---------------- fp32 -> fp16 conversion, 3 segments in one launch ---------
struct CSegs { const float4* src[3]; uint2* dst[3]; int n4[3]; };
__global__ void cvtall(CSegs segs) {
    int seg = blockIdx.y;
    int i = blockIdx.x * 256 + threadIdx.x;
    if (i < segs.n4[seg]) {
        float4 v = segs.src[seg][i];
        __half2 h01 = __floats2half2_rn(v.x, v.y);
        __half2 h23 = __floats2half2_rn(v.z, v.w);
        segs.dst[seg][i] = make_uint2(*(unsigned*)&h01, *(unsigned*)&h23);
    }
}

// ---------------- weight transpose + fp16 convert: Wt[n][k] = W[k][n] -------
__global__ void transw(const float* __restrict__ W, __half* __restrict__ Wt,
                       int K, int N) {
    __shared__ float t[32][33];
    int k0 = blockIdx.y * 32, n0 = blockIdx.x * 32;
    int tx = threadIdx.x, ty = threadIdx.y;   // 32 x 8
#pragma unroll
    for (int j = 0; j < 4; j++)
        t[ty + j * 8][tx] = W[(size_t)(k0 + ty + j * 8) * N + n0 + tx];
    __syncthreads();
#pragma unroll
    for (int j = 0; j < 4; j++)
        Wt[(size_t)(n0 + ty + j * 8) * K + k0 + tx] = __float2half_rn(t[tx][ty + j * 8]);
}

// ---------------- V transpose: vt[b*512+c][key] = qkv_V[key][b][c] ----------
__global__ void vtrans(const __half* __restrict__ qkv, __half* __restrict__ vt) {
    __shared__ __half t[32][40];
    int b = blockIdx.z;
    int key0 = blockIdx.x * 32, c0 = blockIdx.y * 32;
    int tx = threadIdx.x, ty = threadIdx.y;   // 32 x 8
#pragma unroll
    for (int j = 0; j < 4; j++)
        t[ty + j * 8][tx] =
            qkv[((size_t)(key0 + ty + j * 8) * Bx + b) * QKV3 + 1024 + c0 + tx];
    __syncthreads();
#pragma unroll
    for (int j = 0; j < 4; j++)
        vt[((size_t)(b * Ex + c0 + ty + j * 8)) * Kx + key0 + tx] = t[tx][ty + j * 8];
}

// ---------------- FP16 GEMM: C(MxN)=A(MxK)*Bt(NxK)^T, 128x128x32 ------------
#define AH 40
#define GEMM_SMEM (4*128*AH*2)

template<int EPI, bool SPLITA, bool OUTH>
__global__ __launch_bounds__(256, 2) void tgemm(
    const __half* __restrict__ A0, const __half* __restrict__ A1, int splitRow,
    const __half* __restrict__ Bt, const float* __restrict__ bias,
    void* __restrict__ Cv, int Nd, int Kd)
{
    extern __shared__ __align__(16) __half sh[];
    __half* As = sh;
    __half* Bs = sh + 2 * 128 * AH;
    const int tid = threadIdx.x, lane = tid & 31, wid = tid >> 5;
    const int wm = wid >> 2, wn = wid & 3, g = lane >> 2, t = lane & 3;
    const int bm = blockIdx.y * 128, bn = blockIdx.x * 128;

    const __half* asrc[2]; const __half* bsrc[2];
    unsigned adst[2], bdst[2];
#pragma unroll
    for (int p = 0; p < 2; p++) {
        int id = tid + p * 256;
        int r = id >> 2, c8 = (id & 3) * 8;
        int grow = bm + r;
        const __half* abase = (SPLITA && grow >= splitRow)
                              ? (A1 + (size_t)(grow - splitRow) * Kd)
                              : (A0 + (size_t)grow * Kd);
        asrc[p] = abase + c8;
        adst[p] = sptr(As + r * AH + c8);
        bsrc[p] = Bt + (size_t)(bn + r) * Kd + c8;
        bdst[p] = sptr(Bs + r * AH + c8);
    }
    const unsigned BUF = 128 * AH * 2;

    float acc[4][4][4];
#pragma unroll
    for (int i = 0; i < 4; i++)
#pragma unroll
        for (int j = 0; j < 4; j++)
#pragma unroll
            for (int r = 0; r < 4; r++) acc[i][j][r] = 0.f;

    {
#pragma unroll
        for (int p = 0; p < 2; p++) { cpa16(adst[p], asrc[p]); cpa16(bdst[p], bsrc[p]); }
        cpcommit();
    }

    int nkt = Kd >> 5;
    for (int kt = 0; kt < nkt; kt++) {
        int pb = kt & 1;
        if (kt + 1 < nkt) {
            int k0 = (kt + 1) << 5;
            unsigned off = (pb ^ 1) * BUF;
#pragma unroll
            for (int p = 0; p < 2; p++) {
                cpa16(adst[p] + off, asrc[p] + k0);
                cpa16(bdst[p] + off, bsrc[p] + k0);
            }
            cpcommit();
            cpwait<1>();
        } else cpwait<0>();
        __syncthreads();

        const __half* Ab = As + pb * 128 * AH + (wm * 64 + g) * AH;
        const __half* Bb = Bs + pb * 128 * AH + (wn * 32 + g) * AH;
#pragma unroll
        for (int ks = 0; ks < 2; ks++) {
            unsigned a[4][4], b[4][2];
            int k2 = ks * 16 + 2 * t;
#pragma unroll
            for (int mf = 0; mf < 4; mf++) {
                const __half* pa = Ab + mf * 16 * AH + k2;
                a[mf][0] = ldu32(pa);
                a[mf][1] = ldu32(pa + 8 * AH);
                a[mf][2] = ldu32(pa + 8);
                a[mf][3] = ldu32(pa + 8 * AH + 8);
            }
#pragma unroll
            for (int nf = 0; nf < 4; nf++) {
                const __half* pbp = Bb + nf * 8 * AH + k2;
                b[nf][0] = ldu32(pbp);
                b[nf][1] = ldu32(pbp + 8);
            }
#pragma unroll
            for (int mf = 0; mf < 4; mf++)
#pragma unroll
                for (int nf = 0; nf < 4; nf++) mma16(acc[mf][nf], a[mf], b[nf]);
        }
        __syncthreads();
    }

#pragma unroll
    for (int mf = 0; mf < 4; mf++) {
        int r0 = bm + wm * 64 + mf * 16 + g;
#pragma unroll
        for (int nf = 0; nf < 4; nf++) {
            int c = bn + wn * 32 + nf * 8 + 2 * t;
            float v0 = acc[mf][nf][0], v1 = acc[mf][nf][1];
            float v2 = acc[mf][nf][2], v3 = acc[mf][nf][3];
            if (EPI >= 1) {
                float b0 = bias[c], b1v = bias[c + 1];
                v0 += b0; v1 += b1v; v2 += b0; v3 += b1v;
            }
            if (EPI == 2) {
                v0 = fmaxf(v0, 0.f); v1 = fmaxf(v1, 0.f);
                v2 = fmaxf(v2, 0.f); v3 = fmaxf(v3, 0.f);
            }
            if (OUTH) {
                __half* C = (__half*)Cv;
                *(__half2*)(C + (size_t)r0 * Nd + c)       = __floats2half2_rn(v0, v1);
                *(__half2*)(C + (size_t)(r0 + 8) * Nd + c) = __floats2half2_rn(v2, v3);
            } else {
                float* C = (float*)Cv;
                *(float2*)(C + (size_t)r0 * Nd + c)       = make_float2(v0, v1);
                *(float2*)(C + (size_t)(r0 + 8) * Nd + c) = make_float2(v2, v3);
            }
        }
    }
}

// ---------------- Flash attention (FP16 mma + ldmatrix) ---------------------
#define FST 72
#define BDW 84
#define OFF_QU 0
#define OFF_QV 9216
#define OFF_K  18432
#define OFF_V  36864
#define OFF_R  55296
#define OFF_BD 92160
#define OFF_P  135168
#define FLASH_SMEM 153600
#define PRSTRIDE 2304      // 16 * FST * 2 bytes: B-frag pair stride

__global__ __launch_bounds__(256, 1) void flash(
    const __half* __restrict__ qkv, const __half* __restrict__ rbuf,
    const __half* __restrict__ vt,
    const float* __restrict__ u, const float* __restrict__ v,
    __half* __restrict__ attn)
{
    extern __shared__ __align__(16) char smc[];
    __half* Qu = (__half*)(smc + OFF_QU);
    __half* Qv = (__half*)(smc + OFF_QV);
    __half* Ks = (__half*)(smc + OFF_K);
    __half* Vs = (__half*)(smc + OFF_V);
    __half* Rs = (__half*)(smc + OFF_R);
    float*  BDb = (float*)(smc + OFF_BD);
    __half* Pb = (__half*)(smc + OFF_P);
    const int tid = threadIdx.x, lane = tid & 31, wid = tid >> 5;
    const int g = lane >> 2, t = lane & 3;
    const int gr = wid >> 2, wg = wid & 3;
    const int gtid = tid & 127;
    const int qt = (gridDim.x - 1) - blockIdx.x;
    const int b = blockIdx.y >> 3, h = blockIdx.y & 7;
    const int s0 = qt * 64, hoff = h * 64;

    auto issue = [&](int kt) {
        int k0 = kt * 64;
#pragma unroll
        for (int p = 0; p < 4; p++) {
            int id = gtid + p * 128;
            int row = id >> 3, c = (id & 7) * 8;
            const __half* ksrc = qkv + ((size_t)(k0 + row) * Bx + b) * QKV3 + 512 + hoff + c;
            cpa16(sptr(Ks + gr * 64 * FST + row * FST + c), ksrc);
            cpa16(sptr(Vs + gr * 64 * FST + row * FST + c),
                  vt + ((size_t)(b * Ex + hoff + row)) * Kx + k0 + c);
        }
        int jlo = k0 + (Sx - 1) - s0 - 63;
#pragma unroll
        for (int p = 0; p < 8; p++) {
            int id = gtid + p * 128;
            int d = id >> 3, c = (id & 7) * 8;
            int j = jlo + d; if (j > Kx - 1) j = Kx - 1;
            cpa16(sptr(Rs + gr * 128 * FST + d * FST + c), rbuf + (size_t)j * Ex + hoff + c);
        }
        cpcommit();
    };
    issue(gr);

    for (int idx = tid; idx < 64 * 64; idx += 256) {
        int sR = idx >> 6, i = idx & 63;
        float qv_ = __half2float(qkv[((size_t)(Mx + s0 + sR) * Bx + b) * QKV3 + hoff + i]);
        Qu[sR * FST + i] = __float2half_rn(qv_ + u[hoff + i]);
        Qv[sR * FST + i] = __float2half_rn(qv_ + v[hoff + i]);
    }
    __syncthreads();

    float m0 = -1e30f, m1 = -1e30f, l0 = 0.f, l1 = 0.f;
    float O[8][4];
#pragma unroll
    for (int i = 0; i < 8; i++)
#pragma unroll
        for (int j = 0; j < 4; j++) O[i][j] = 0.f;

    float* BDrow = BDb + (wid * 16 + g) * BDW;
    __half* Prow = Pb + (wid * 16 + g) * FST;
    const __half* Kp = Ks + gr * 64 * FST;
    const __half* Vp = Vs + gr * 64 * FST;
    const __half* Rp = Rs + gr * 128 * FST;
    const int c_base = 48 - wg * 16;
    const int nkt = qt + 33;

    // ---- ldmatrix per-lane base addresses (bytes) ----
    const int r_in = lane & 7;
    const int a_row8 = ((lane >> 3) & 1) * 8;   // A: rows +8 group
    const int a_k8 = (lane >> 4) * 8;           // A: k +8 group
    const int b_nf8 = (lane >> 4) * 8;          // B: second-nf group
    const int b_k8 = ((lane >> 3) & 1) * 8;     // B: k +8 group
    const unsigned qu_a = sptr(Qu + (wg * 16 + r_in + a_row8) * FST + a_k8);
    const unsigned qv_a = sptr(Qv + (wg * 16 + r_in + a_row8) * FST + a_k8);
    const unsigned p_a  = sptr(Pb + (wid * 16 + r_in + a_row8) * FST + a_k8);
    const unsigned k_b  = sptr(Kp + (b_nf8 + r_in) * FST + b_k8);
    const unsigned r_b  = sptr(Rp + (c_base + b_nf8 + r_in) * FST + b_k8);
    const unsigned v_b  = sptr(Vp + (b_nf8 + r_in) * FST + b_k8);

    for (int kt = gr; kt < nkt; kt += 2) {
        int k0 = kt * 64;
        cpwait<0>();
        barg(gr + 1);

        // ---- BD band mma: 16 x 80 per warp -> fp32 smem
        {
            float bd[10][4];
#pragma unroll
            for (int nf = 0; nf < 10; nf++)
#pragma unroll
                for (int j = 0; j < 4; j++) bd[nf][j] = 0.f;
#pragma unroll
            for (int ks = 0; ks < 4; ks++) {
                unsigned a[4];
                ldmx4(a, qv_a + ks * 32);
#pragma unroll
                for (int pr = 0; pr < 5; pr++) {
                    unsigned bb[4];
                    ldmx4(bb, r_b + pr * PRSTRIDE + ks * 32);
                    mma16(bd[2 * pr],     a, bb);
                    mma16(bd[2 * pr + 1], a, bb + 2);
                }
            }
#pragma unroll
            for (int nf = 0; nf < 10; nf++) {
                *(float2*)(BDrow + nf * 8 + 2 * t) = make_float2(bd[nf][0], bd[nf][1]);
                *(float2*)(BDrow + 8 * BDW + nf * 8 + 2 * t) = make_float2(bd[nf][2], bd[nf][3]);
            }
        }
        __syncwarp();

        // ---- AC mma: 16 x 64 per warp
        float ac[8][4];
#pragma unroll
        for (int nf = 0; nf < 8; nf++)
#pragma unroll
            for (int j = 0; j < 4; j++) ac[nf][j] = 0.f;
#pragma unroll
        for (int ks = 0; ks < 4; ks++) {
            unsigned a[4];
            ldmx4(a, qu_a + ks * 32);
#pragma unroll
            for (int pr = 0; pr < 4; pr++) {
                unsigned bb[4];
                ldmx4(bb, k_b + pr * PRSTRIDE + ks * 32);
                mma16(ac[2 * pr],     a, bb);
                mma16(ac[2 * pr + 1], a, bb + 2);
            }
        }

        // ---- combine with BD diagonal + mask; scale into base-2 domain
        {
            int lim0 = s0 + wg * 16 + g + Mx, lim1 = lim0 + 8;
#pragma unroll
            for (int nf = 0; nf < 8; nf++) {
                int kc = nf * 8 + 2 * t;
                float v0 = (ac[nf][0] + BDrow[kc + 15 - g]) * SCL;
                float v1 = (ac[nf][1] + BDrow[kc + 16 - g]) * SCL;
                float v2 = (ac[nf][2] + BDrow[8 * BDW + kc + 7 - g]) * SCL;
                float v3 = (ac[nf][3] + BDrow[8 * BDW + kc + 8 - g]) * SCL;
                if (k0 + kc > lim0)     v0 = -1e30f;
                if (k0 + kc + 1 > lim0) v1 = -1e30f;
                if (k0 + kc > lim1)     v2 = -1e30f;
                if (k0 + kc + 1 > lim1) v3 = -1e30f;
                ac[nf][0] = v0; ac[nf][1] = v1; ac[nf][2] = v2; ac[nf][3] = v3;
            }
        }

        // ---- online softmax (base-2), rows g and g+8
        {
            float mx0 = -1e30f, mx1 = -1e30f;
#pragma unroll
            for (int nf = 0; nf < 8; nf++) {
                mx0 = fmaxf(mx0, fmaxf(ac[nf][0], ac[nf][1]));
                mx1 = fmaxf(mx1, fmaxf(ac[nf][2], ac[nf][3]));
            }
            mx0 = fmaxf(mx0, __shfl_xor_sync(0xffffffffu, mx0, 1));
            mx0 = fmaxf(mx0, __shfl_xor_sync(0xffffffffu, mx0, 2));
            mx1 = fmaxf(mx1, __shfl_xor_sync(0xffffffffu, mx1, 1));
            mx1 = fmaxf(mx1, __shfl_xor_sync(0xffffffffu, mx1, 2));
            float mn0 = fmaxf(m0, mx0), mn1 = fmaxf(m1, mx1);
            float c0 = ex2f(m0 - mn0), c1 = ex2f(m1 - mn1);
            float rs0 = 0.f, rs1 = 0.f;
#pragma unroll
            for (int nf = 0; nf < 8; nf++) {
                float p0 = ex2f(ac[nf][0] - mn0);
                float p1 = ex2f(ac[nf][1] - mn0);
                float p2 = ex2f(ac[nf][2] - mn1);
                float p3 = ex2f(ac[nf][3] - mn1);
                rs0 += p0 + p1; rs1 += p2 + p3;
                *(__half2*)(Prow + nf * 8 + 2 * t) = __floats2half2_rn(p0, p1);
                *(__half2*)(Prow + 8 * FST + nf * 8 + 2 * t) = __floats2half2_rn(p2, p3);
            }
            rs0 += __shfl_xor_sync(0xffffffffu, rs0, 1);
            rs0 += __shfl_xor_sync(0xffffffffu, rs0, 2);
            rs1 += __shfl_xor_sync(0xffffffffu, rs1, 1);
            rs1 += __shfl_xor_sync(0xffffffffu, rs1, 2);
            l0 = l0 * c0 + rs0; l1 = l1 * c1 + rs1;
            m0 = mn0; m1 = mn1;
#pragma unroll
            for (int nf = 0; nf < 8; nf++) {
                O[nf][0] *= c0; O[nf][1] *= c0; O[nf][2] *= c1; O[nf][3] *= c1;
            }
        }
        __syncwarp();

        // ---- P·V mma: A = P (ldmatrix), B = transposed V (ldmatrix)
#pragma unroll
        for (int ks = 0; ks < 4; ks++) {
            unsigned a[4];
            ldmx4(a, p_a + ks * 32);
#pragma unroll
            for (int pr = 0; pr < 4; pr++) {
                unsigned bb[4];
                ldmx4(bb, v_b + pr * PRSTRIDE + ks * 32);
                mma16(O[2 * pr],     a, bb);
                mma16(O[2 * pr + 1], a, bb + 2);
            }
        }

        barg(gr + 1);
        if (kt + 2 < nkt) issue(kt + 2);
    }

    // ---- merge the two groups' partial softmax states, write output --------
    if (wid >= 4) {
#pragma unroll
        for (int nf = 0; nf < 8; nf++) {
            *(float2*)(BDrow + nf * 8 + 2 * t) = make_float2(O[nf][0], O[nf][1]);
            *(float2*)(BDrow + 8 * BDW + nf * 8 + 2 * t) = make_float2(O[nf][2], O[nf][3]);
        }
        if (t == 0) {
            BDrow[80] = m0; BDrow[81] = l0;
            BDrow[8 * BDW + 80] = m1; BDrow[8 * BDW + 81] = l1;
        }
    }
    __syncthreads();
    if (wid < 4) {
        const float* Peer = BDb + ((wid + 4) * 16 + g) * BDW;
        float pm0 = Peer[80], pl0 = Peer[81];
        float pm1 = Peer[8 * BDW + 80], pl1 = Peer[8 * BDW + 81];
        float M0 = fmaxf(m0, pm0), M1 = fmaxf(m1, pm1);
        float a0 = ex2f(m0 - M0), e0 = ex2f(pm0 - M0);
        float a1 = ex2f(m1 - M1), e1 = ex2f(pm1 - M1);
        float i0 = 1.0f / (l0 * a0 + pl0 * e0);
        float i1 = 1.0f / (l1 * a1 + pl1 * e1);
        int sg0 = s0 + wid * 16 + g;
#pragma unroll
        for (int nf = 0; nf < 8; nf++) {
            int c = hoff + nf * 8 + 2 * t;
            float2 po0 = *(const float2*)(Peer + nf * 8 + 2 * t);
            float2 po1 = *(const float2*)(Peer + 8 * BDW + nf * 8 + 2 * t);
            *(__half2*)(attn + ((size_t)sg0 * Bx + b) * Ex + c) =
                __floats2half2_rn((O[nf][0] * a0 + po0.x * e0) * i0,
                                  (O[nf][1] * a0 + po0.y * e0) * i0);
            *(__half2*)(attn + ((size_t)(sg0 + 8) * Bx + b) * Ex + c) =
                __floats2half2_rn((O[nf][2] * a1 + po1.x * e1) * i1,
                                  (O[nf][3] * a1 + po1.y * e1) * i1);
        }
    }
}

// ---------------- LayerNorm(X + Y); optional fp16 second copy ---------------
__global__ void ln_add_kernel(const float* __restrict__ X, const float* __restrict__ Y,
                              const float* __restrict__ g, const float* __restrict__ bb,
                              float* __restrict__ out, __half* __restrict__ out_h)
{
    __shared__ float red[4];
    int row = blockIdx.x;
    int tid = threadIdx.x;
    const float4* X4 = (const float4*)(X + (size_t)row * Ex);
    const float4* Y4 = (const float4*)(Y + (size_t)row * Ex);
    float4 x = X4[tid], y = Y4[tid];
    float4 vv = {x.x + y.x, x.y + y.y, x.z + y.z, x.w + y.w};
    float s = vv.x + vv.y + vv.z + vv.w;
#pragma unroll
    for (int off = 16; off; off >>= 1) s += __shfl_xor_sync(0xffffffffu, s, off);
    if ((tid & 31) == 0) red[tid >> 5] = s;
    __syncthreads();
    float mu = (red[0] + red[1] + red[2] + red[3]) * (1.f / 512.f);
    float d0 = vv.x - mu, d1 = vv.y - mu, d2 = vv.z - mu, d3 = vv.w - mu;
    float q = d0 * d0 + d1 * d1 + d2 * d2 + d3 * d3;
    __syncthreads();
#pragma unroll
    for (int off = 16; off; off >>= 1) q += __shfl_xor_sync(0xffffffffu, q, off);
    if ((tid & 31) == 0) red[tid >> 5] = q;
    __syncthreads();
    float var = (red[0] + red[1] + red[2] + red[3]) * (1.f / 512.f);
    float rs = rsqrtf(var + EPSF);
    float4 gg = ((const float4*)g)[tid], bv = ((const float4*)bb)[tid];
    float4 o;
    o.x = d0 * rs * gg.x + bv.x;
    o.y = d1 * rs * gg.y + bv.y;
    o.z = d2 * rs * gg.z + bv.z;
    o.w = d3 * rs * gg.w + bv.w;
    ((float4*)(out + (size_t)row * Ex))[tid] = o;
    if (out_h) {
        __half2* oh = (__half2*)(out_h + (size_t)row * Ex);
        oh[tid * 2]     = __floats2half2_rn(o.x, o.y);
        oh[tid * 2 + 1] = __floats2half2_rn(o.z, o.w);
    }
}

// ---------------------------------------------------------------------------
extern "C" void kernel_launch(void* const* d_in, const int* in_sizes, int n_in,
                              void* d_out, int out_size)
{
    const float* inputDec = (const float*)d_in[0];
    const float* posEmb   = (const float*)d_in[1];
    const float* u        = (const float*)d_in[2];
    const float* v        = (const float*)d_in[3];
    const float* memories = (const float*)d_in[4];
    const float* Wqkv     = (const float*)d_in[5];
    const float* Wr       = (const float*)d_in[6];
    const float* Wo       = (const float*)d_in[7];
    const float* ln1_g    = (const float*)d_in[8];
    const float* ln1_b    = (const float*)d_in[9];
    const float* W1       = (const float*)d_in[10];
    const float* b1       = (const float*)d_in[11];
    const float* W2       = (const float*)d_in[12];
    const float* b2       = (const float*)d_in[13];
    const float* ln2_g    = (const float*)d_in[14];
    const float* ln2_b    = (const float*)d_in[15];
    float* out = (float*)d_out;

    __half *qkv, *rb, *vt, *attn, *attnout_h, *ff1;
    __half *mem_h, *inp_h, *pos_h, *wqkv_t, *wr_t, *wo_t, *w1_t, *w2_t;
    float *tmp, *attnout, *ff2;
    cudaGetSymbolAddress((void**)&qkv,       g_qkv);
    cudaGetSymbolAddress((void**)&rb,        g_rb);
    cudaGetSymbolAddress((void**)&vt,        g_vt);
    cudaGetSymbolAddress((void**)&attn,      g_attn);
    cudaGetSymbolAddress((void**)&tmp,       g_tmp);
    cudaGetSymbolAddress((void**)&attnout,   g_attnout);
    cudaGetSymbolAddress((void**)&attnout_h, g_attnout_h);
    cudaGetSymbolAddress((void**)&ff1,       g_ff1);
    cudaGetSymbolAddress((void**)&ff2,       g_ff2);
    cudaGetSymbolAddress((void**)&mem_h,     g_mem_h);
    cudaGetSymbolAddress((void**)&inp_h,     g_inp_h);
    cudaGetSymbolAddress((void**)&pos_h,     g_pos_h);
    cudaGetSymbolAddress((void**)&wqkv_t,    g_wqkv_t);
    cudaGetSymbolAddress((void**)&wr_t,      g_wr_t);
    cudaGetSymbolAddress((void**)&wo_t,      g_wo_t);
    cudaGetSymbolAddress((void**)&w1_t,      g_w1_t);
    cudaGetSymbolAddress((void**)&w2_t,      g_w2_t);

    cudaFuncSetAttribute(flash, cudaFuncAttributeMaxDynamicSharedMemorySize, FLASH_SMEM);
    cudaFuncSetAttribute(tgemm<0,true,true>,   cudaFuncAttributeMaxDynamicSharedMemorySize, GEMM_SMEM);
    cudaFuncSetAttribute(tgemm<0,false,true>,  cudaFuncAttributeMaxDynamicSharedMemorySize, GEMM_SMEM);
    cudaFuncSetAttribute(tgemm<0,false,false>, cudaFuncAttributeMaxDynamicSharedMemorySize, GEMM_SMEM);
    cudaFuncSetAttribute(tgemm<2,false,true>,  cudaFuncAttributeMaxDynamicSharedMemorySize, GEMM_SMEM);
    cudaFuncSetAttribute(tgemm<1,false,false>, cudaFuncAttributeMaxDynamicSharedMemorySize, GEMM_SMEM);

    // 0a) activations fp32 -> fp16
    {
        CSegs cs;
        cs.src[0] = (const float4*)memories; cs.dst[0] = (uint2*)mem_h;
        cs.n4[0] = (int)((size_t)Mx * Bx * Ex / 4);
        cs.src[1] = (const float4*)inputDec; cs.dst[1] = (uint2*)inp_h;
        cs.n4[1] = (int)((size_t)Sx * Bx * Ex / 4);
        cs.src[2] = (const float4*)posEmb;   cs.dst[2] = (uint2*)pos_h;
        cs.n4[2] = (int)((size_t)Kx * Ex / 4);
        int maxb = 0;
        for (int i = 0; i < 3; i++) { int bl = (cs.n4[i] + 255) / 256; if (bl > maxb) maxb = bl; }
        cvtall<<<dim3(maxb, 3), 256>>>(cs);
    }
    // 0b) weights fp32 -> fp16 transposed [N][K]
    transw<<<dim3(QKV3/32, Ex/32), dim3(32,8)>>>(Wqkv, wqkv_t, Ex, QKV3);
    transw<<<dim3(Ex/32,   Ex/32), dim3(32,8)>>>(Wr,   wr_t,   Ex, Ex);
    transw<<<dim3(Ex/32,   Ex/32), dim3(32,8)>>>(Wo,   wo_t,   Ex, Ex);
    transw<<<dim3(FFx/32,  Ex/32), dim3(32,8)>>>(W1,   w1_t,   Ex, FFx);
    transw<<<dim3(Ex/32,  FFx/32), dim3(32,8)>>>(W2,   w2_t,   FFx, Ex);

    // 1) qkv = concat(memories, inputDec) @ Wqkv   -> half
    tgemm<0,true,true><<<dim3(QKV3/128, KB_/128), 256, GEMM_SMEM>>>(
        mem_h, inp_h, Mx * Bx, wqkv_t, nullptr, qkv, QKV3, Ex);
    // 2) r = posEmbeddings @ Wr                    -> half
    tgemm<0,false,true><<<dim3(Ex/128, Kx/128), 256, GEMM_SMEM>>>(
        pos_h, nullptr, 0, wr_t, nullptr, rb, Ex, Ex);
    // 2b) transpose V region of qkv -> vt[hd][key]
    vtrans<<<dim3(Kx/32, Ex/32, Bx), dim3(32,8)>>>(qkv, vt);
    // 3) fused rel-pos flash attention (fp16 mma + ldmatrix)
    flash<<<dim3(Sx/64, Bx*Hx), 256, FLASH_SMEM>>>(qkv, rb, vt, u, v, attn);
    // 4) attn @ Wo                                 -> fp32
    tgemm<0,false,false><<<dim3(Ex/128, ROWS/128), 256, GEMM_SMEM>>>(
        attn, nullptr, 0, wo_t, nullptr, tmp, Ex, Ex);
    // 5) attn_out = LN(inputDec + attnWo)  (+ fp16 copy for FF1)
    ln_add_kernel<<<ROWS, 128>>>(inputDec, tmp, ln1_g, ln1_b, attnout, attnout_h);
    // 6) ff1 = relu(attn_out @ W1 + b1)            -> half
    tgemm<2,false,true><<<dim3(FFx/128, ROWS/128), 256, GEMM_SMEM>>>(
        attnout_h, nullptr, 0, w1_t, b1, ff1, FFx, Ex);
    // 7) ff2 = ff1 @ W2 + b2                       -> fp32
    tgemm<1,false,false><<<dim3(Ex/128, ROWS/128), 256, GEMM_SMEM>>>(
        ff1, nullptr, 0, w2_t, b2, ff2, Ex, FFx);
    // 8) out = LN(attn_out + ff2)
    ln_add_kernel<<<ROWS, 128>>>(attnout, ff2, ln2_g, ln2_b, out, nullptr);
}

// round 7
// speedup vs baseline: 12.8497x; 1.0652x over previous
#include <cuda_runtime.h>
#include <cuda_fp16.h>
#include <cstdint>

#define Sx 2048
#define Bx 2
#define Ex 512
#define Hx 8
#define Mx 2048
#define Kx 4096          // M + S
#define QKV3 1536
#define FFx 2048
#define ROWS (Sx*Bx)     // 4096
#define KB_ (Kx*Bx)      // 8192
#define EPSF 1e-5f
#define SCL 0.18033688f  // 0.125 * log2(e): softmax in base-2 domain

// ---------------- scratch (static device arrays: no allocation) -------------
__device__ __align__(128) __half g_qkv[(size_t)KB_ * QKV3];
__device__ __align__(128) __half g_rb[(size_t)Kx * Ex];
__device__ __align__(128) __half g_vt[(size_t)Bx * Ex * Kx];
__device__ __align__(128) __half g_attn[(size_t)ROWS * Ex];
__device__ __align__(128) float  g_tmp[(size_t)ROWS * Ex];
__device__ __align__(128) float  g_attnout[(size_t)ROWS * Ex];
__device__ __align__(128) __half g_attnout_h[(size_t)ROWS * Ex];
__device__ __align__(128) __half g_ff1[(size_t)ROWS * FFx];
__device__ __align__(128) float  g_ff2[(size_t)ROWS * Ex];
__device__ __align__(128) __half g_mem_h[(size_t)Mx * Bx * Ex];
__device__ __align__(128) __half g_inp_h[(size_t)Sx * Bx * Ex];
__device__ __align__(128) __half g_pos_h[(size_t)Kx * Ex];
__device__ __align__(128) __half g_wqkv_t[(size_t)QKV3 * Ex];
__device__ __align__(128) __half g_wr_t[(size_t)Ex * Ex];
__device__ __align__(128) __half g_wo_t[(size_t)Ex * Ex];
__device__ __align__(128) __half g_w1_t[(size_t)FFx * Ex];
__device__ __align__(128) __half g_w2_t[(size_t)Ex * FFx];

// ---------------- helpers ---------------------------------------------------
__device__ __forceinline__ void mma16(float* d, const unsigned* a, const unsigned* b) {
    asm volatile(
        "mma.sync.aligned.m16n8k16.row.col.f32.f16.f16.f32 "
        "{%0,%1,%2,%3},{%4,%5,%6,%7},{%8,%9},{%0,%1,%2,%3};\n"
        : "+f"(d[0]), "+f"(d[1]), "+f"(d[2]), "+f"(d[3])
        : "r"(a[0]), "r"(a[1]), "r"(a[2]), "r"(a[3]), "r"(b[0]), "r"(b[1]));
}
__device__ __forceinline__ void ldmx4(unsigned* r, unsigned a) {
    asm volatile("ldmatrix.sync.aligned.m8n8.x4.shared.b16 {%0,%1,%2,%3}, [%4];"
        : "=r"(r[0]), "=r"(r[1]), "=r"(r[2]), "=r"(r[3]) : "r"(a));
}
__device__ __forceinline__ float ex2f(float x) {
    float r; asm("ex2.approx.f32 %0, %1;" : "=f"(r) : "f"(x)); return r;
}
__device__ __forceinline__ unsigned sptr(const void* p) {
    return (unsigned)__cvta_generic_to_shared(p);
}
__device__ __forceinline__ void cpa16(unsigned d, const void* s) {
    asm volatile("cp.async.cg.shared.global [%0], [%1], 16;\n" :: "r"(d), "l"(s));
}
__device__ __forceinline__ void cpcommit() { asm volatile("cp.async.commit_group;\n"); }
template<int N> __device__ __forceinline__ void cpwait() {
    asm volatile("cp.async.wait_group %0;\n" :: "n"(N));
}
__device__ __forceinline__ void barg(int id) {
    asm volatile("bar.sync %0, 128;" :: "r"(id) : "memory");
}
__device__ __forceinline__ unsigned packh2(float a, float b) {
    __half2 h = __floats2half2_rn(a, b);
    return *(unsigned*)&h;
}

// ---------------- fp32 -> fp16 conversion, 3 segments in one launch ---------
struct CSegs { const float4* src[3]; uint2* dst[3]; int n4[3]; };
__global__ void cvtall(CSegs segs) {
    int seg = blockIdx.y;
    int i = blockIdx.x * 256 + threadIdx.x;
    if (i < segs.n4[seg]) {
        float4 v = segs.src[seg][i];
        __half2 h01 = __floats2half2_rn(v.x, v.y);
        __half2 h23 = __floats2half2_rn(v.z, v.w);
        segs.dst[seg][i] = make_uint2(*(unsigned*)&h01, *(unsigned*)&h23);
    }
}

// ------- weight transpose + fp16 convert, ALL 5 weights, one launch ---------
struct TSegs { const float* W[5]; __half* Wt[5]; int K[5], N[5], tilesN[5], cum[6]; };
__global__ void transw_all(TSegs s) {
    int bid = blockIdx.x;
    int seg = 0;
#pragma unroll
    for (int i = 0; i < 5; i++) if (bid >= s.cum[i + 1]) seg = i + 1;
    int lt = bid - s.cum[seg];
    int K = s.K[seg], N = s.N[seg];
    int n0 = (lt % s.tilesN[seg]) * 32, k0 = (lt / s.tilesN[seg]) * 32;
    const float* W = s.W[seg];
    __half* Wt = s.Wt[seg];
    __shared__ float t[32][33];
    int tx = threadIdx.x, ty = threadIdx.y;   // 32 x 8
#pragma unroll
    for (int j = 0; j < 4; j++)
        t[ty + j * 8][tx] = W[(size_t)(k0 + ty + j * 8) * N + n0 + tx];
    __syncthreads();
#pragma unroll
    for (int j = 0; j < 4; j++)
        Wt[(size_t)(n0 + ty + j * 8) * K + k0 + tx] = __float2half_rn(t[tx][ty + j * 8]);
}

// ---------------- V transpose: vt[b*512+c][key] = qkv_V[key][b][c] ----------
__global__ void vtrans(const __half* __restrict__ qkv, __half* __restrict__ vt) {
    __shared__ __half t[32][40];
    int b = blockIdx.z;
    int key0 = blockIdx.x * 32, c0 = blockIdx.y * 32;
    int tx = threadIdx.x, ty = threadIdx.y;   // 32 x 8
#pragma unroll
    for (int j = 0; j < 4; j++)
        t[ty + j * 8][tx] =
            qkv[((size_t)(key0 + ty + j * 8) * Bx + b) * QKV3 + 1024 + c0 + tx];
    __syncthreads();
#pragma unroll
    for (int j = 0; j < 4; j++)
        vt[((size_t)(b * Ex + c0 + ty + j * 8)) * Kx + key0 + tx] = t[tx][ty + j * 8];
}

// ---------------- FP16 GEMM: C(MxN)=A(MxK)*Bt(NxK)^T, 128x128x32 ------------
#define AH 40
#define GEMM_SMEM (4*128*AH*2)

template<int EPI, bool SPLITA, bool OUTH>
__global__ __launch_bounds__(256, 2) void tgemm(
    const __half* __restrict__ A0, const __half* __restrict__ A1, int splitRow,
    const __half* __restrict__ Bt, const float* __restrict__ bias,
    void* __restrict__ Cv, int Nd, int Kd)
{
    extern __shared__ __align__(16) __half sh[];
    __half* As = sh;
    __half* Bs = sh + 2 * 128 * AH;
    const int tid = threadIdx.x, lane = tid & 31, wid = tid >> 5;
    const int wm = wid >> 2, wn = wid & 3, g = lane >> 2, t = lane & 3;
    const int bm = blockIdx.y * 128, bn = blockIdx.x * 128;

    const __half* asrc[2]; const __half* bsrc[2];
    unsigned adst[2], bdst[2];
#pragma unroll
    for (int p = 0; p < 2; p++) {
        int id = tid + p * 256;
        int r = id >> 2, c8 = (id & 3) * 8;
        int grow = bm + r;
        const __half* abase = (SPLITA && grow >= splitRow)
                              ? (A1 + (size_t)(grow - splitRow) * Kd)
                              : (A0 + (size_t)grow * Kd);
        asrc[p] = abase + c8;
        adst[p] = sptr(As + r * AH + c8);
        bsrc[p] = Bt + (size_t)(bn + r) * Kd + c8;
        bdst[p] = sptr(Bs + r * AH + c8);
    }
    const unsigned BUF = 128 * AH * 2;

    // ldmatrix lane constants
    const int r_in = lane & 7;
    const int a_row8 = ((lane >> 3) & 1) * 8;
    const int a_k8 = (lane >> 4) * 8;
    const int b_nf8 = (lane >> 4) * 8;
    const int b_k8 = ((lane >> 3) & 1) * 8;
    const unsigned aAddr0 = sptr(As + (wm * 64 + r_in + a_row8) * AH + a_k8);
    const unsigned bAddr0 = sptr(Bs + (wn * 32 + b_nf8 + r_in) * AH + b_k8);

    float acc[4][4][4];
#pragma unroll
    for (int i = 0; i < 4; i++)
#pragma unroll
        for (int j = 0; j < 4; j++)
#pragma unroll
            for (int r = 0; r < 4; r++) acc[i][j][r] = 0.f;

    {
#pragma unroll
        for (int p = 0; p < 2; p++) { cpa16(adst[p], asrc[p]); cpa16(bdst[p], bsrc[p]); }
        cpcommit();
    }

    int nkt = Kd >> 5;
    for (int kt = 0; kt < nkt; kt++) {
        int pb = kt & 1;
        if (kt + 1 < nkt) {
            int k0 = (kt + 1) << 5;
            unsigned off = (pb ^ 1) * BUF;
#pragma unroll
            for (int p = 0; p < 2; p++) {
                cpa16(adst[p] + off, asrc[p] + k0);
                cpa16(bdst[p] + off, bsrc[p] + k0);
            }
            cpcommit();
            cpwait<1>();
        } else cpwait<0>();
        __syncthreads();

        unsigned aAddr = aAddr0 + pb * BUF;
        unsigned bAddr = bAddr0 + pb * BUF;
#pragma unroll
        for (int ks = 0; ks < 2; ks++) {
            unsigned a4[4][4], b4[2][4];
#pragma unroll
            for (int mf = 0; mf < 4; mf++)
                ldmx4(a4[mf], aAddr + mf * (16 * AH * 2) + ks * 32);
#pragma unroll
            for (int n2 = 0; n2 < 2; n2++)
                ldmx4(b4[n2], bAddr + n2 * (16 * AH * 2) + ks * 32);
#pragma unroll
            for (int mf = 0; mf < 4; mf++)
#pragma unroll
                for (int n2 = 0; n2 < 2; n2++) {
                    mma16(acc[mf][2 * n2],     a4[mf], b4[n2]);
                    mma16(acc[mf][2 * n2 + 1], a4[mf], b4[n2] + 2);
                }
        }
        __syncthreads();
    }

#pragma unroll
    for (int mf = 0; mf < 4; mf++) {
        int r0 = bm + wm * 64 + mf * 16 + g;
#pragma unroll
        for (int nf = 0; nf < 4; nf++) {
            int c = bn + wn * 32 + nf * 8 + 2 * t;
            float v0 = acc[mf][nf][0], v1 = acc[mf][nf][1];
            float v2 = acc[mf][nf][2], v3 = acc[mf][nf][3];
            if (EPI >= 1) {
                float b0 = bias[c], b1v = bias[c + 1];
                v0 += b0; v1 += b1v; v2 += b0; v3 += b1v;
            }
            if (EPI == 2) {
                v0 = fmaxf(v0, 0.f); v1 = fmaxf(v1, 0.f);
                v2 = fmaxf(v2, 0.f); v3 = fmaxf(v3, 0.f);
            }
            if (OUTH) {
                __half* C = (__half*)Cv;
                *(__half2*)(C + (size_t)r0 * Nd + c)       = __floats2half2_rn(v0, v1);
                *(__half2*)(C + (size_t)(r0 + 8) * Nd + c) = __floats2half2_rn(v2, v3);
            } else {
                float* C = (float*)Cv;
                *(float2*)(C + (size_t)r0 * Nd + c)       = make_float2(v0, v1);
                *(float2*)(C + (size_t)(r0 + 8) * Nd + c) = make_float2(v2, v3);
            }
        }
    }
}

// ---------------- Flash attention (FP16 mma + ldmatrix, P in regs) ----------
#define FST 72
#define BDW 84
#define OFF_QU 0
#define OFF_QV 9216
#define OFF_K  18432
#define OFF_V  36864
#define OFF_R  55296
#define OFF_BD 92160
#define FLASH_SMEM 135168
#define PRSTRIDE 2304      // 16 * FST * 2 bytes

__global__ __launch_bounds__(256, 1) void flash(
    const __half* __restrict__ qkv, const __half* __restrict__ rbuf,
    const __half* __restrict__ vt,
    const float* __restrict__ u, const float* __restrict__ v,
    __half* __restrict__ attn)
{
    extern __shared__ __align__(16) char smc[];
    __half* Qu = (__half*)(smc + OFF_QU);
    __half* Qv = (__half*)(smc + OFF_QV);
    __half* Ks = (__half*)(smc + OFF_K);
    __half* Vs = (__half*)(smc + OFF_V);
    __half* Rs = (__half*)(smc + OFF_R);
    float*  BDb = (float*)(smc + OFF_BD);
    const int tid = threadIdx.x, lane = tid & 31, wid = tid >> 5;
    const int g = lane >> 2, t = lane & 3;
    const int gr = wid >> 2, wg = wid & 3;
    const int gtid = tid & 127;
    const int qt = (gridDim.x - 1) - blockIdx.x;
    const int b = blockIdx.y >> 3, h = blockIdx.y & 7;
    const int s0 = qt * 64, hoff = h * 64;

    auto issue = [&](int kt) {
        int k0 = kt * 64;
#pragma unroll
        for (int p = 0; p < 4; p++) {
            int id = gtid + p * 128;
            int row = id >> 3, c = (id & 7) * 8;
            const __half* ksrc = qkv + ((size_t)(k0 + row) * Bx + b) * QKV3 + 512 + hoff + c;
            cpa16(sptr(Ks + gr * 64 * FST + row * FST + c), ksrc);
            cpa16(sptr(Vs + gr * 64 * FST + row * FST + c),
                  vt + ((size_t)(b * Ex + hoff + row)) * Kx + k0 + c);
        }
        int jlo = k0 + (Sx - 1) - s0 - 63;
#pragma unroll
        for (int p = 0; p < 8; p++) {
            int id = gtid + p * 128;
            int d = id >> 3, c = (id & 7) * 8;
            int j = jlo + d; if (j > Kx - 1) j = Kx - 1;
            cpa16(sptr(Rs + gr * 128 * FST + d * FST + c), rbuf + (size_t)j * Ex + hoff + c);
        }
        cpcommit();
    };
    issue(gr);

    for (int idx = tid; idx < 64 * 64; idx += 256) {
        int sR = idx >> 6, i = idx & 63;
        float qv_ = __half2float(qkv[((size_t)(Mx + s0 + sR) * Bx + b) * QKV3 + hoff + i]);
        Qu[sR * FST + i] = __float2half_rn(qv_ + u[hoff + i]);
        Qv[sR * FST + i] = __float2half_rn(qv_ + v[hoff + i]);
    }
    __syncthreads();

    float m0 = -1e30f, m1 = -1e30f, l0 = 0.f, l1 = 0.f;
    float O[8][4];
#pragma unroll
    for (int i = 0; i < 8; i++)
#pragma unroll
        for (int j = 0; j < 4; j++) O[i][j] = 0.f;

    float* BDrow = BDb + (wid * 16 + g) * BDW;
    const __half* Kp = Ks + gr * 64 * FST;
    const __half* Vp = Vs + gr * 64 * FST;
    const __half* Rp = Rs + gr * 128 * FST;
    const int c_base = 48 - wg * 16;
    const int nkt = qt + 33;

    const int r_in = lane & 7;
    const int a_row8 = ((lane >> 3) & 1) * 8;
    const int a_k8 = (lane >> 4) * 8;
    const int b_nf8 = (lane >> 4) * 8;
    const int b_k8 = ((lane >> 3) & 1) * 8;
    const unsigned qu_a = sptr(Qu + (wg * 16 + r_in + a_row8) * FST + a_k8);
    const unsigned qv_a = sptr(Qv + (wg * 16 + r_in + a_row8) * FST + a_k8);
    const unsigned k_b  = sptr(Kp + (b_nf8 + r_in) * FST + b_k8);
    const unsigned r_b  = sptr(Rp + (c_base + b_nf8 + r_in) * FST + b_k8);
    const unsigned v_b  = sptr(Vp + (b_nf8 + r_in) * FST + b_k8);

    for (int kt = gr; kt < nkt; kt += 2) {
        int k0 = kt * 64;
        cpwait<0>();
        barg(gr + 1);

        // ---- BD band mma: 16 x 80 per warp -> fp32 smem
        {
            float bd[10][4];
#pragma unroll
            for (int nf = 0; nf < 10; nf++)
#pragma unroll
                for (int j = 0; j < 4; j++) bd[nf][j] = 0.f;
#pragma unroll
            for (int ks = 0; ks < 4; ks++) {
                unsigned a[4];
                ldmx4(a, qv_a + ks * 32);
#pragma unroll
                for (int pr = 0; pr < 5; pr++) {
                    unsigned bb[4];
                    ldmx4(bb, r_b + pr * PRSTRIDE + ks * 32);
                    mma16(bd[2 * pr],     a, bb);
                    mma16(bd[2 * pr + 1], a, bb + 2);
                }
            }
#pragma unroll
            for (int nf = 0; nf < 10; nf++) {
                *(float2*)(BDrow + nf * 8 + 2 * t) = make_float2(bd[nf][0], bd[nf][1]);
                *(float2*)(BDrow + 8 * BDW + nf * 8 + 2 * t) = make_float2(bd[nf][2], bd[nf][3]);
            }
        }
        __syncwarp();

        // ---- AC mma: 16 x 64 per warp
        float ac[8][4];
#pragma unroll
        for (int nf = 0; nf < 8; nf++)
#pragma unroll
            for (int j = 0; j < 4; j++) ac[nf][j] = 0.f;
#pragma unroll
        for (int ks = 0; ks < 4; ks++) {
            unsigned a[4];
            ldmx4(a, qu_a + ks * 32);
#pragma unroll
            for (int pr = 0; pr < 4; pr++) {
                unsigned bb[4];
                ldmx4(bb, k_b + pr * PRSTRIDE + ks * 32);
                mma16(ac[2 * pr],     a, bb);
                mma16(ac[2 * pr + 1], a, bb + 2);
            }
        }

        // ---- combine with BD diagonal + mask; scale into base-2 domain
        {
            int lim0 = s0 + wg * 16 + g + Mx, lim1 = lim0 + 8;
#pragma unroll
            for (int nf = 0; nf < 8; nf++) {
                int kc = nf * 8 + 2 * t;
                float v0 = (ac[nf][0] + BDrow[kc + 15 - g]) * SCL;
                float v1 = (ac[nf][1] + BDrow[kc + 16 - g]) * SCL;
                float v2 = (ac[nf][2] + BDrow[8 * BDW + kc + 7 - g]) * SCL;
                float v3 = (ac[nf][3] + BDrow[8 * BDW + kc + 8 - g]) * SCL;
                if (k0 + kc > lim0)     v0 = -1e30f;
                if (k0 + kc + 1 > lim0) v1 = -1e30f;
                if (k0 + kc > lim1)     v2 = -1e30f;
                if (k0 + kc + 1 > lim1) v3 = -1e30f;
                ac[nf][0] = v0; ac[nf][1] = v1; ac[nf][2] = v2; ac[nf][3] = v3;
            }
        }

        // ---- online softmax (base-2); P packed directly into A-fragments
        unsigned pk0[8], pk1[8];
        {
            float mx0 = -1e30f, mx1 = -1e30f;
#pragma unroll
            for (int nf = 0; nf < 8; nf++) {
                mx0 = fmaxf(mx0, fmaxf(ac[nf][0], ac[nf][1]));
                mx1 = fmaxf(mx1, fmaxf(ac[nf][2], ac[nf][3]));
            }
            mx0 = fmaxf(mx0, __shfl_xor_sync(0xffffffffu, mx0, 1));
            mx0 = fmaxf(mx0, __shfl_xor_sync(0xffffffffu, mx0, 2));
            mx1 = fmaxf(mx1, __shfl_xor_sync(0xffffffffu, mx1, 1));
            mx1 = fmaxf(mx1, __shfl_xor_sync(0xffffffffu, mx1, 2));
            float mn0 = fmaxf(m0, mx0), mn1 = fmaxf(m1, mx1);
            float c0 = ex2f(m0 - mn0), c1 = ex2f(m1 - mn1);
            float rs0 = 0.f, rs1 = 0.f;
#pragma unroll
            for (int nf = 0; nf < 8; nf++) {
                float p0 = ex2f(ac[nf][0] - mn0);
                float p1 = ex2f(ac[nf][1] - mn0);
                float p2 = ex2f(ac[nf][2] - mn1);
                float p3 = ex2f(ac[nf][3] - mn1);
                rs0 += p0 + p1; rs1 += p2 + p3;
                pk0[nf] = packh2(p0, p1);
                pk1[nf] = packh2(p2, p3);
            }
            rs0 += __shfl_xor_sync(0xffffffffu, rs0, 1);
            rs0 += __shfl_xor_sync(0xffffffffu, rs0, 2);
            rs1 += __shfl_xor_sync(0xffffffffu, rs1, 1);
            rs1 += __shfl_xor_sync(0xffffffffu, rs1, 2);
            l0 = l0 * c0 + rs0; l1 = l1 * c1 + rs1;
            m0 = mn0; m1 = mn1;
#pragma unroll
            for (int nf = 0; nf < 8; nf++) {
                O[nf][0] *= c0; O[nf][1] *= c0; O[nf][2] *= c1; O[nf][3] *= c1;
            }
        }

        // ---- P·V mma: A = P straight from registers (C-frag == A-frag)
#pragma unroll
        for (int ks = 0; ks < 4; ks++) {
            unsigned a[4] = {pk0[2 * ks], pk1[2 * ks], pk0[2 * ks + 1], pk1[2 * ks + 1]};
#pragma unroll
            for (int pr = 0; pr < 4; pr++) {
                unsigned bb[4];
                ldmx4(bb, v_b + pr * PRSTRIDE + ks * 32);
                mma16(O[2 * pr],     a, bb);
                mma16(O[2 * pr + 1], a, bb + 2);
            }
        }

        barg(gr + 1);
        if (kt + 2 < nkt) issue(kt + 2);
    }

    // ---- merge the two groups' partial softmax states, write output --------
    if (wid >= 4) {
#pragma unroll
        for (int nf = 0; nf < 8; nf++) {
            *(float2*)(BDrow + nf * 8 + 2 * t) = make_float2(O[nf][0], O[nf][1]);
            *(float2*)(BDrow + 8 * BDW + nf * 8 + 2 * t) = make_float2(O[nf][2], O[nf][3]);
        }
        if (t == 0) {
            BDrow[80] = m0; BDrow[81] = l0;
            BDrow[8 * BDW + 80] = m1; BDrow[8 * BDW + 81] = l1;
        }
    }
    __syncthreads();
    if (wid < 4) {
        const float* Peer = BDb + ((wid + 4) * 16 + g) * BDW;
        float pm0 = Peer[80], pl0 = Peer[81];
        float pm1 = Peer[8 * BDW + 80], pl1 = Peer[8 * BDW + 81];
        float M0 = fmaxf(m0, pm0), M1 = fmaxf(m1, pm1);
        float a0 = ex2f(m0 - M0), e0 = ex2f(pm0 - M0);
        float a1 = ex2f(m1 - M1), e1 = ex2f(pm1 - M1);
        float i0 = 1.0f / (l0 * a0 + pl0 * e0);
        float i1 = 1.0f / (l1 * a1 + pl1 * e1);
        int sg0 = s0 + wid * 16 + g;
#pragma unroll
        for (int nf = 0; nf < 8; nf++) {
            int c = hoff + nf * 8 + 2 * t;
            float2 po0 = *(const float2*)(Peer + nf * 8 + 2 * t);
            float2 po1 = *(const float2*)(Peer + 8 * BDW + nf * 8 + 2 * t);
            *(__half2*)(attn + ((size_t)sg0 * Bx + b) * Ex + c) =
                __floats2half2_rn((O[nf][0] * a0 + po0.x * e0) * i0,
                                  (O[nf][1] * a0 + po0.y * e0) * i0);
            *(__half2*)(attn + ((size_t)(sg0 + 8) * Bx + b) * Ex + c) =
                __floats2half2_rn((O[nf][2] * a1 + po1.x * e1) * i1,
                                  (O[nf][3] * a1 + po1.y * e1) * i1);
        }
    }
}

// ---------------- LayerNorm(X + Y); optional fp16 second copy ---------------
__global__ void ln_add_kernel(const float* __restrict__ X, const float* __restrict__ Y,
                              const float* __restrict__ g, const float* __restrict__ bb,
                              float* __restrict__ out, __half* __restrict__ out_h)
{
    __shared__ float red[4];
    int row = blockIdx.x;
    int tid = threadIdx.x;
    const float4* X4 = (const float4*)(X + (size_t)row * Ex);
    const float4* Y4 = (const float4*)(Y + (size_t)row * Ex);
    float4 x = X4[tid], y = Y4[tid];
    float4 vv = {x.x + y.x, x.y + y.y, x.z + y.z, x.w + y.w};
    float s = vv.x + vv.y + vv.z + vv.w;
#pragma unroll
    for (int off = 16; off; off >>= 1) s += __shfl_xor_sync(0xffffffffu, s, off);
    if ((tid & 31) == 0) red[tid >> 5] = s;
    __syncthreads();
    float mu = (red[0] + red[1] + red[2] + red[3]) * (1.f / 512.f);
    float d0 = vv.x - mu, d1 = vv.y - mu, d2 = vv.z - mu, d3 = vv.w - mu;
    float q = d0 * d0 + d1 * d1 + d2 * d2 + d3 * d3;
    __syncthreads();
#pragma unroll
    for (int off = 16; off; off >>= 1) q += __shfl_xor_sync(0xffffffffu, q, off);
    if ((tid & 31) == 0) red[tid >> 5] = q;
    __syncthreads();
    float var = (red[0] + red[1] + red[2] + red[3]) * (1.f / 512.f);
    float rs = rsqrtf(var + EPSF);
    float4 gg = ((const float4*)g)[tid], bv = ((const float4*)bb)[tid];
    float4 o;
    o.x = d0 * rs * gg.x + bv.x;
    o.y = d1 * rs * gg.y + bv.y;
    o.z = d2 * rs * gg.z + bv.z;
    o.w = d3 * rs * gg.w + bv.w;
    ((float4*)(out + (size_t)row * Ex))[tid] = o;
    if (out_h) {
        __half2* oh = (__half2*)(out_h + (size_t)row * Ex);
        oh[tid * 2]     = __floats2half2_rn(o.x, o.y);
        oh[tid * 2 + 1] = __floats2half2_rn(o.z, o.w);
    }
}

// ---------------------------------------------------------------------------
extern "C" void kernel_launch(void* const* d_in, const int* in_sizes, int n_in,
                              void* d_out, int out_size)
{
    const float* inputDec = (const float*)d_in[0];
    const float* posEmb   = (const float*)d_in[1];
    const float* u        = (const float*)d_in[2];
    const float* v        = (const float*)d_in[3];
    const float* memories = (const float*)d_in[4];
    const float* Wqkv     = (const float*)d_in[5];
    const float* Wr       = (const float*)d_in[6];
    const float* Wo       = (const float*)d_in[7];
    const float* ln1_g    = (const float*)d_in[8];
    const float* ln1_b    = (const float*)d_in[9];
    const float* W1       = (const float*)d_in[10];
    const float* b1       = (const float*)d_in[11];
    const float* W2       = (const float*)d_in[12];
    const float* b2       = (const float*)d_in[13];
    const float* ln2_g    = (const float*)d_in[14];
    const float* ln2_b    = (const float*)d_in[15];
    float* out = (float*)d_out;

    __half *qkv, *rb, *vt, *attn, *attnout_h, *ff1;
    __half *mem_h, *inp_h, *pos_h, *wqkv_t, *wr_t, *wo_t, *w1_t, *w2_t;
    float *tmp, *attnout, *ff2;
    cudaGetSymbolAddress((void**)&qkv,       g_qkv);
    cudaGetSymbolAddress((void**)&rb,        g_rb);
    cudaGetSymbolAddress((void**)&vt,        g_vt);
    cudaGetSymbolAddress((void**)&attn,      g_attn);
    cudaGetSymbolAddress((void**)&tmp,       g_tmp);
    cudaGetSymbolAddress((void**)&attnout,   g_attnout);
    cudaGetSymbolAddress((void**)&attnout_h, g_attnout_h);
    cudaGetSymbolAddress((void**)&ff1,       g_ff1);
    cudaGetSymbolAddress((void**)&ff2,       g_ff2);
    cudaGetSymbolAddress((void**)&mem_h,     g_mem_h);
    cudaGetSymbolAddress((void**)&inp_h,     g_inp_h);
    cudaGetSymbolAddress((void**)&pos_h,     g_pos_h);
    cudaGetSymbolAddress((void**)&wqkv_t,    g_wqkv_t);
    cudaGetSymbolAddress((void**)&wr_t,      g_wr_t);
    cudaGetSymbolAddress((void**)&wo_t,      g_wo_t);
    cudaGetSymbolAddress((void**)&w1_t,      g_w1_t);
    cudaGetSymbolAddress((void**)&w2_t,      g_w2_t);

    cudaFuncSetAttribute(flash, cudaFuncAttributeMaxDynamicSharedMemorySize, FLASH_SMEM);
    cudaFuncSetAttribute(tgemm<0,true,true>,   cudaFuncAttributeMaxDynamicSharedMemorySize, GEMM_SMEM);
    cudaFuncSetAttribute(tgemm<0,false,true>,  cudaFuncAttributeMaxDynamicSharedMemorySize, GEMM_SMEM);
    cudaFuncSetAttribute(tgemm<0,false,false>, cudaFuncAttributeMaxDynamicSharedMemorySize, GEMM_SMEM);
    cudaFuncSetAttribute(tgemm<2,false,true>,  cudaFuncAttributeMaxDynamicSharedMemorySize, GEMM_SMEM);
    cudaFuncSetAttribute(tgemm<1,false,false>, cudaFuncAttributeMaxDynamicSharedMemorySize, GEMM_SMEM);

    // 0a) activations fp32 -> fp16 (launch #1)
    {
        CSegs cs;
        cs.src[0] = (const float4*)memories; cs.dst[0] = (uint2*)mem_h;
        cs.n4[0] = (int)((size_t)Mx * Bx * Ex / 4);
        cs.src[1] = (const float4*)inputDec; cs.dst[1] = (uint2*)inp_h;
        cs.n4[1] = (int)((size_t)Sx * Bx * Ex / 4);
        cs.src[2] = (const float4*)posEmb;   cs.dst[2] = (uint2*)pos_h;
        cs.n4[2] = (int)((size_t)Kx * Ex / 4);
        int maxb = 0;
        for (int i = 0; i < 3; i++) { int bl = (cs.n4[i] + 255) / 256; if (bl > maxb) maxb = bl; }
        cvtall<<<dim3(maxb, 3), 256>>>(cs);
    }
    // 0b) all 5 weight transposes in ONE launch (launch #2)
    {
        TSegs ts;
        const float* Ws[5] = {Wqkv, Wr, Wo, W1, W2};
        __half* Wts[5] = {wqkv_t, wr_t, wo_t, w1_t, w2_t};
        int Ks[5] = {Ex, Ex, Ex, Ex, FFx};
        int Ns[5] = {QKV3, Ex, Ex, FFx, Ex};
        int c = 0;
        ts.cum[0] = 0;
        for (int i = 0; i < 5; i++) {
            ts.W[i] = Ws[i]; ts.Wt[i] = Wts[i];
            ts.K[i] = Ks[i]; ts.N[i] = Ns[i];
            ts.tilesN[i] = Ns[i] / 32;
            c += (Ks[i] / 32) * (Ns[i] / 32);
            ts.cum[i + 1] = c;
        }
        transw_all<<<c, dim3(32, 8)>>>(ts);
    }

    // 1) qkv GEMM (launch #3)
    tgemm<0,true,true><<<dim3(QKV3/128, KB_/128), 256, GEMM_SMEM>>>(
        mem_h, inp_h, Mx * Bx, wqkv_t, nullptr, qkv, QKV3, Ex);
    // 2) r GEMM (launch #4)
    tgemm<0,false,true><<<dim3(Ex/128, Kx/128), 256, GEMM_SMEM>>>(
        pos_h, nullptr, 0, wr_t, nullptr, rb, Ex, Ex);
    // 2b) V transpose (launch #5)
    vtrans<<<dim3(Kx/32, Ex/32, Bx), dim3(32,8)>>>(qkv, vt);
    // 3) flash attention (launch #6 — ncu -s 5 -c 1 profiles THIS)
    flash<<<dim3(Sx/64, Bx*Hx), 256, FLASH_SMEM>>>(qkv, rb, vt, u, v, attn);
    // 4) attn @ Wo
    tgemm<0,false,false><<<dim3(Ex/128, ROWS/128), 256, GEMM_SMEM>>>(
        attn, nullptr, 0, wo_t, nullptr, tmp, Ex, Ex);
    // 5) attn_out = LN(inputDec + attnWo)
    ln_add_kernel<<<ROWS, 128>>>(inputDec, tmp, ln1_g, ln1_b, attnout, attnout_h);
    // 6) ff1 = relu(attn_out @ W1 + b1)
    tgemm<2,false,true><<<dim3(FFx/128, ROWS/128), 256, GEMM_SMEM>>>(
        attnout_h, nullptr, 0, w1_t, b1, ff1, FFx, Ex);
    // 7) ff2 = ff1 @ W2 + b2
    tgemm<1,false,false><<<dim3(Ex/128, ROWS/128), 256, GEMM_SMEM>>>(
        ff1, nullptr, 0, w2_t, b2, ff2, Ex, FFx);
    // 8) out = LN(attn_out + ff2)
    ln_add_kernel<<<ROWS, 128>>>(attnout, ff2, ln2_g, ln2_b, out, nullptr);
}

// round 10
// speedup vs baseline: 13.2834x; 1.0338x over previous
#include <cuda_runtime.h>
#include <cuda_fp16.h>
#include <cstdint>

#define Sx 2048
#define Bx 2
#define Ex 512
#define Hx 8
#define Mx 2048
#define Kx 4096          // M + S
#define QKV3 1536
#define FFx 2048
#define ROWS (Sx*Bx)     // 4096
#define KB_ (Kx*Bx)      // 8192
#define EPSF 1e-5f
#define SCL 0.18033688f  // 0.125 * log2(e): softmax in base-2 domain

// ---------------- scratch (static device arrays: no allocation) -------------
__device__ __align__(128) __half g_qkv[(size_t)KB_ * QKV3];
__device__ __align__(128) __half g_rb[(size_t)Kx * Ex];
__device__ __align__(128) __half g_vt[(size_t)Bx * Ex * Kx];
__device__ __align__(128) __half g_attn[(size_t)ROWS * Ex];
__device__ __align__(128) float  g_tmp[(size_t)ROWS * Ex];
__device__ __align__(128) float  g_attnout[(size_t)ROWS * Ex];
__device__ __align__(128) __half g_attnout_h[(size_t)ROWS * Ex];
__device__ __align__(128) __half g_ff1[(size_t)ROWS * FFx];
__device__ __align__(128) float  g_ff2[(size_t)ROWS * Ex];
__device__ __align__(128) __half g_mem_h[(size_t)Mx * Bx * Ex];
__device__ __align__(128) __half g_inp_h[(size_t)Sx * Bx * Ex];
__device__ __align__(128) __half g_pos_h[(size_t)Kx * Ex];
__device__ __align__(128) __half g_wqkv_t[(size_t)QKV3 * Ex];
__device__ __align__(128) __half g_wr_t[(size_t)Ex * Ex];
__device__ __align__(128) __half g_wo_t[(size_t)Ex * Ex];
__device__ __align__(128) __half g_w1_t[(size_t)FFx * Ex];
__device__ __align__(128) __half g_w2_t[(size_t)Ex * FFx];

// ---------------- helpers ---------------------------------------------------
__device__ __forceinline__ void mma16(float* d, const unsigned* a, const unsigned* b) {
    asm volatile(
        "mma.sync.aligned.m16n8k16.row.col.f32.f16.f16.f32 "
        "{%0,%1,%2,%3},{%4,%5,%6,%7},{%8,%9},{%0,%1,%2,%3};\n"
        : "+f"(d[0]), "+f"(d[1]), "+f"(d[2]), "+f"(d[3])
        : "r"(a[0]), "r"(a[1]), "r"(a[2]), "r"(a[3]), "r"(b[0]), "r"(b[1]));
}
__device__ __forceinline__ void ldmx4(unsigned* r, unsigned a) {
    asm volatile("ldmatrix.sync.aligned.m8n8.x4.shared.b16 {%0,%1,%2,%3}, [%4];"
        : "=r"(r[0]), "=r"(r[1]), "=r"(r[2]), "=r"(r[3]) : "r"(a));
}
__device__ __forceinline__ float ex2f(float x) {
    float r; asm("ex2.approx.f32 %0, %1;" : "=f"(r) : "f"(x)); return r;
}
__device__ __forceinline__ unsigned sptr(const void* p) {
    return (unsigned)__cvta_generic_to_shared(p);
}
__device__ __forceinline__ void cpa16(unsigned d, const void* s) {
    asm volatile("cp.async.cg.shared.global [%0], [%1], 16;\n" :: "r"(d), "l"(s));
}
__device__ __forceinline__ void cpcommit() { asm volatile("cp.async.commit_group;\n"); }
template<int N> __device__ __forceinline__ void cpwait() {
    asm volatile("cp.async.wait_group %0;\n" :: "n"(N));
}
__device__ __forceinline__ void barg(int id) {
    asm volatile("bar.sync %0, 128;" :: "r"(id) : "memory");
}
__device__ __forceinline__ unsigned packh2(float a, float b) {
    __half2 h = __floats2half2_rn(a, b);
    return *(unsigned*)&h;
}

// ---------------- fp32 -> fp16 conversion, 3 segments in one launch ---------
struct CSegs { const float4* src[3]; uint2* dst[3]; int n4[3]; };
__global__ void cvtall(CSegs segs) {
    int seg = blockIdx.y;
    int i = blockIdx.x * 256 + threadIdx.x;
    if (i < segs.n4[seg]) {
        float4 v = segs.src[seg][i];
        __half2 h01 = __floats2half2_rn(v.x, v.y);
        __half2 h23 = __floats2half2_rn(v.z, v.w);
        segs.dst[seg][i] = make_uint2(*(unsigned*)&h01, *(unsigned*)&h23);
    }
}

// ------- weight transpose + fp16 convert, ALL 5 weights, one launch ---------
struct TSegs { const float* W[5]; __half* Wt[5]; int K[5], N[5], tilesN[5], cum[6]; };
__global__ void transw_all(TSegs s) {
    int bid = blockIdx.x;
    int seg = 0;
#pragma unroll
    for (int i = 0; i < 5; i++) if (bid >= s.cum[i + 1]) seg = i + 1;
    int lt = bid - s.cum[seg];
    int K = s.K[seg], N = s.N[seg];
    int n0 = (lt % s.tilesN[seg]) * 32, k0 = (lt / s.tilesN[seg]) * 32;
    const float* W = s.W[seg];
    __half* Wt = s.Wt[seg];
    __shared__ float t[32][33];
    int tx = threadIdx.x, ty = threadIdx.y;   // 32 x 8
#pragma unroll
    for (int j = 0; j < 4; j++)
        t[ty + j * 8][tx] = W[(size_t)(k0 + ty + j * 8) * N + n0 + tx];
    __syncthreads();
#pragma unroll
    for (int j = 0; j < 4; j++)
        Wt[(size_t)(n0 + ty + j * 8) * K + k0 + tx] = __float2half_rn(t[tx][ty + j * 8]);
}

// ---------------- V transpose: vt[b*512+c][key] = qkv_V[key][b][c] ----------
__global__ void vtrans(const __half* __restrict__ qkv, __half* __restrict__ vt) {
    __shared__ __half t[32][40];
    int b = blockIdx.z;
    int key0 = blockIdx.x * 32, c0 = blockIdx.y * 32;
    int tx = threadIdx.x, ty = threadIdx.y;   // 32 x 8
#pragma unroll
    for (int j = 0; j < 4; j++)
        t[ty + j * 8][tx] =
            qkv[((size_t)(key0 + ty + j * 8) * Bx + b) * QKV3 + 1024 + c0 + tx];
    __syncthreads();
#pragma unroll
    for (int j = 0; j < 4; j++)
        vt[((size_t)(b * Ex + c0 + ty + j * 8)) * Kx + key0 + tx] = t[tx][ty + j * 8];
}

// ------- FP16 GEMM: C(MxN)=A(MxK)*Bt(NxK)^T, 128x128x32, 4-stage pipe ------
#define AH 40
#define GSTG 4
#define GBUF (128*AH*2)          // bytes per operand per stage
#define GEMM_SMEM (2*GSTG*GBUF)  // A stages + B stages

template<int EPI, bool SPLITA, bool OUTH>
__global__ __launch_bounds__(256, 2) void tgemm(
    const __half* __restrict__ A0, const __half* __restrict__ A1, int splitRow,
    const __half* __restrict__ Bt, const float* __restrict__ bias,
    void* __restrict__ Cv, int Nd, int Kd)
{
    extern __shared__ __align__(16) __half sh[];
    __half* As = sh;                      // [GSTG][128][AH]
    __half* Bs = sh + GSTG * 128 * AH;    // [GSTG][128][AH]
    const int tid = threadIdx.x, lane = tid & 31, wid = tid >> 5;
    const int wm = wid >> 2, wn = wid & 3, g = lane >> 2, t = lane & 3;
    const int bm = blockIdx.y * 128, bn = blockIdx.x * 128;

    const __half* asrc[2]; const __half* bsrc[2];
    unsigned adst[2], bdst[2];
#pragma unroll
    for (int p = 0; p < 2; p++) {
        int id = tid + p * 256;
        int r = id >> 2, c8 = (id & 3) * 8;
        int grow = bm + r;
        const __half* abase = (SPLITA && grow >= splitRow)
                              ? (A1 + (size_t)(grow - splitRow) * Kd)
                              : (A0 + (size_t)grow * Kd);
        asrc[p] = abase + c8;
        adst[p] = sptr(As + r * AH + c8);
        bsrc[p] = Bt + (size_t)(bn + r) * Kd + c8;
        bdst[p] = sptr(Bs + r * AH + c8);
    }

    // ldmatrix lane constants
    const int r_in = lane & 7;
    const int a_row8 = ((lane >> 3) & 1) * 8;
    const int a_k8 = (lane >> 4) * 8;
    const int b_nf8 = (lane >> 4) * 8;
    const int b_k8 = ((lane >> 3) & 1) * 8;
    const unsigned aAddr0 = sptr(As + (wm * 64 + r_in + a_row8) * AH + a_k8);
    const unsigned bAddr0 = sptr(Bs + (wn * 32 + b_nf8 + r_in) * AH + b_k8);

    float acc[4][4][4];
#pragma unroll
    for (int i = 0; i < 4; i++)
#pragma unroll
        for (int j = 0; j < 4; j++)
#pragma unroll
            for (int r = 0; r < 4; r++) acc[i][j][r] = 0.f;

    auto issue = [&](int stage) {
        unsigned off = (unsigned)(stage % GSTG) * GBUF;
        int k0 = stage << 5;
#pragma unroll
        for (int p = 0; p < 2; p++) {
            cpa16(adst[p] + off, asrc[p] + k0);
            cpa16(bdst[p] + off, bsrc[p] + k0);
        }
        cpcommit();
    };

    int nkt = Kd >> 5;   // >= 16 for all our shapes
#pragma unroll
    for (int s = 0; s < GSTG - 1; s++) issue(s);

    for (int kt = 0; kt < nkt; kt++) {
        cpwait<GSTG - 2>();
        __syncthreads();
        // prefetch into the buffer consumed at kt-1 (safe: barrier above)
        if (kt + GSTG - 1 < nkt) issue(kt + GSTG - 1);

        unsigned off = (unsigned)(kt % GSTG) * GBUF;
        unsigned aAddr = aAddr0 + off;
        unsigned bAddr = bAddr0 + off;
#pragma unroll
        for (int ks = 0; ks < 2; ks++) {
            unsigned a4[4][4], b4[2][4];
#pragma unroll
            for (int mf = 0; mf < 4; mf++)
                ldmx4(a4[mf], aAddr + mf * (16 * AH * 2) + ks * 32);
#pragma unroll
            for (int n2 = 0; n2 < 2; n2++)
                ldmx4(b4[n2], bAddr + n2 * (16 * AH * 2) + ks * 32);
#pragma unroll
            for (int mf = 0; mf < 4; mf++)
#pragma unroll
                for (int n2 = 0; n2 < 2; n2++) {
                    mma16(acc[mf][2 * n2],     a4[mf], b4[n2]);
                    mma16(acc[mf][2 * n2 + 1], a4[mf], b4[n2] + 2);
                }
        }
    }

#pragma unroll
    for (int mf = 0; mf < 4; mf++) {
        int r0 = bm + wm * 64 + mf * 16 + g;
#pragma unroll
        for (int nf = 0; nf < 4; nf++) {
            int c = bn + wn * 32 + nf * 8 + 2 * t;
            float v0 = acc[mf][nf][0], v1 = acc[mf][nf][1];
            float v2 = acc[mf][nf][2], v3 = acc[mf][nf][3];
            if (EPI >= 1) {
                float b0 = bias[c], b1v = bias[c + 1];
                v0 += b0; v1 += b1v; v2 += b0; v3 += b1v;
            }
            if (EPI == 2) {
                v0 = fmaxf(v0, 0.f); v1 = fmaxf(v1, 0.f);
                v2 = fmaxf(v2, 0.f); v3 = fmaxf(v3, 0.f);
            }
            if (OUTH) {
                __half* C = (__half*)Cv;
                *(__half2*)(C + (size_t)r0 * Nd + c)       = __floats2half2_rn(v0, v1);
                *(__half2*)(C + (size_t)(r0 + 8) * Nd + c) = __floats2half2_rn(v2, v3);
            } else {
                float* C = (float*)Cv;
                *(float2*)(C + (size_t)r0 * Nd + c)       = make_float2(v0, v1);
                *(float2*)(C + (size_t)(r0 + 8) * Nd + c) = make_float2(v2, v3);
            }
        }
    }
}

// ---------------- Flash attention (R7 proven version: fp32 BD, 1 CTA/SM) ----
#define FST 72
#define BDW 84
#define OFF_QU 0
#define OFF_QV 9216
#define OFF_K  18432
#define OFF_V  36864
#define OFF_R  55296
#define OFF_BD 92160
#define FLASH_SMEM 135168
#define PRSTRIDE 2304      // 16 * FST * 2 bytes

__global__ __launch_bounds__(256, 1) void flash(
    const __half* __restrict__ qkv, const __half* __restrict__ rbuf,
    const __half* __restrict__ vt,
    const float* __restrict__ u, const float* __restrict__ v,
    __half* __restrict__ attn)
{
    extern __shared__ __align__(16) char smc[];
    __half* Qu = (__half*)(smc + OFF_QU);
    __half* Qv = (__half*)(smc + OFF_QV);
    __half* Ks = (__half*)(smc + OFF_K);
    __half* Vs = (__half*)(smc + OFF_V);
    __half* Rs = (__half*)(smc + OFF_R);
    float*  BDb = (float*)(smc + OFF_BD);
    const int tid = threadIdx.x, lane = tid & 31, wid = tid >> 5;
    const int g = lane >> 2, t = lane & 3;
    const int gr = wid >> 2, wg = wid & 3;
    const int gtid = tid & 127;
    const int qt = (gridDim.x - 1) - blockIdx.x;
    const int b = blockIdx.y >> 3, h = blockIdx.y & 7;
    const int s0 = qt * 64, hoff = h * 64;

    auto issue = [&](int kt) {
        int k0 = kt * 64;
#pragma unroll
        for (int p = 0; p < 4; p++) {
            int id = gtid + p * 128;
            int row = id >> 3, c = (id & 7) * 8;
            const __half* ksrc = qkv + ((size_t)(k0 + row) * Bx + b) * QKV3 + 512 + hoff + c;
            cpa16(sptr(Ks + gr * 64 * FST + row * FST + c), ksrc);
            cpa16(sptr(Vs + gr * 64 * FST + row * FST + c),
                  vt + ((size_t)(b * Ex + hoff + row)) * Kx + k0 + c);
        }
        int jlo = k0 + (Sx - 1) - s0 - 63;
#pragma unroll
        for (int p = 0; p < 8; p++) {
            int id = gtid + p * 128;
            int d = id >> 3, c = (id & 7) * 8;
            int j = jlo + d; if (j > Kx - 1) j = Kx - 1;
            cpa16(sptr(Rs + gr * 128 * FST + d * FST + c), rbuf + (size_t)j * Ex + hoff + c);
        }
        cpcommit();
    };
    issue(gr);

    for (int idx = tid; idx < 64 * 64; idx += 256) {
        int sR = idx >> 6, i = idx & 63;
        float qv_ = __half2float(qkv[((size_t)(Mx + s0 + sR) * Bx + b) * QKV3 + hoff + i]);
        Qu[sR * FST + i] = __float2half_rn(qv_ + u[hoff + i]);
        Qv[sR * FST + i] = __float2half_rn(qv_ + v[hoff + i]);
    }
    __syncthreads();

    float m0 = -1e30f, m1 = -1e30f, l0 = 0.f, l1 = 0.f;
    float O[8][4];
#pragma unroll
    for (int i = 0; i < 8; i++)
#pragma unroll
        for (int j = 0; j < 4; j++) O[i][j] = 0.f;

    float* BDrow = BDb + (wid * 16 + g) * BDW;
    const __half* Kp = Ks + gr * 64 * FST;
    const __half* Vp = Vs + gr * 64 * FST;
    const __half* Rp = Rs + gr * 128 * FST;
    const int c_base = 48 - wg * 16;
    const int nkt = qt + 33;

    const int r_in = lane & 7;
    const int a_row8 = ((lane >> 3) & 1) * 8;
    const int a_k8 = (lane >> 4) * 8;
    const int b_nf8 = (lane >> 4) * 8;
    const int b_k8 = ((lane >> 3) & 1) * 8;
    const unsigned qu_a = sptr(Qu + (wg * 16 + r_in + a_row8) * FST + a_k8);
    const unsigned qv_a = sptr(Qv + (wg * 16 + r_in + a_row8) * FST + a_k8);
    const unsigned k_b  = sptr(Kp + (b_nf8 + r_in) * FST + b_k8);
    const unsigned r_b  = sptr(Rp + (c_base + b_nf8 + r_in) * FST + b_k8);
    const unsigned v_b  = sptr(Vp + (b_nf8 + r_in) * FST + b_k8);

    for (int kt = gr; kt < nkt; kt += 2) {
        int k0 = kt * 64;
        cpwait<0>();
        barg(gr + 1);

        // ---- BD band mma: 16 x 80 per warp -> fp32 smem
        {
            float bd[10][4];
#pragma unroll
            for (int nf = 0; nf < 10; nf++)
#pragma unroll
                for (int j = 0; j < 4; j++) bd[nf][j] = 0.f;
#pragma unroll
            for (int ks = 0; ks < 4; ks++) {
                unsigned a[4];
                ldmx4(a, qv_a + ks * 32);
#pragma unroll
                for (int pr = 0; pr < 5; pr++) {
                    unsigned bb[4];
                    ldmx4(bb, r_b + pr * PRSTRIDE + ks * 32);
                    mma16(bd[2 * pr],     a, bb);
                    mma16(bd[2 * pr + 1], a, bb + 2);
                }
            }
#pragma unroll
            for (int nf = 0; nf < 10; nf++) {
                *(float2*)(BDrow + nf * 8 + 2 * t) = make_float2(bd[nf][0], bd[nf][1]);
                *(float2*)(BDrow + 8 * BDW + nf * 8 + 2 * t) = make_float2(bd[nf][2], bd[nf][3]);
            }
        }
        __syncwarp();

        // ---- AC mma: 16 x 64 per warp
        float ac[8][4];
#pragma unroll
        for (int nf = 0; nf < 8; nf++)
#pragma unroll
            for (int j = 0; j < 4; j++) ac[nf][j] = 0.f;
#pragma unroll
        for (int ks = 0; ks < 4; ks++) {
            unsigned a[4];
            ldmx4(a, qu_a + ks * 32);
#pragma unroll
            for (int pr = 0; pr < 4; pr++) {
                unsigned bb[4];
                ldmx4(bb, k_b + pr * PRSTRIDE + ks * 32);
                mma16(ac[2 * pr],     a, bb);
                mma16(ac[2 * pr + 1], a, bb + 2);
            }
        }

        // ---- combine with BD diagonal + mask; scale into base-2 domain
        {
            int lim0 = s0 + wg * 16 + g + Mx, lim1 = lim0 + 8;
#pragma unroll
            for (int nf = 0; nf < 8; nf++) {
                int kc = nf * 8 + 2 * t;
                float v0 = (ac[nf][0] + BDrow[kc + 15 - g]) * SCL;
                float v1 = (ac[nf][1] + BDrow[kc + 16 - g]) * SCL;
                float v2 = (ac[nf][2] + BDrow[8 * BDW + kc + 7 - g]) * SCL;
                float v3 = (ac[nf][3] + BDrow[8 * BDW + kc + 8 - g]) * SCL;
                if (k0 + kc > lim0)     v0 = -1e30f;
                if (k0 + kc + 1 > lim0) v1 = -1e30f;
                if (k0 + kc > lim1)     v2 = -1e30f;
                if (k0 + kc + 1 > lim1) v3 = -1e30f;
                ac[nf][0] = v0; ac[nf][1] = v1; ac[nf][2] = v2; ac[nf][3] = v3;
            }
        }

        // ---- online softmax (base-2); P packed directly into A-fragments
        unsigned pk0[8], pk1[8];
        {
            float mx0 = -1e30f, mx1 = -1e30f;
#pragma unroll
            for (int nf = 0; nf < 8; nf++) {
                mx0 = fmaxf(mx0, fmaxf(ac[nf][0], ac[nf][1]));
                mx1 = fmaxf(mx1, fmaxf(ac[nf][2], ac[nf][3]));
            }
            mx0 = fmaxf(mx0, __shfl_xor_sync(0xffffffffu, mx0, 1));
            mx0 = fmaxf(mx0, __shfl_xor_sync(0xffffffffu, mx0, 2));
            mx1 = fmaxf(mx1, __shfl_xor_sync(0xffffffffu, mx1, 1));
            mx1 = fmaxf(mx1, __shfl_xor_sync(0xffffffffu, mx1, 2));
            float mn0 = fmaxf(m0, mx0), mn1 = fmaxf(m1, mx1);
            float c0 = ex2f(m0 - mn0), c1 = ex2f(m1 - mn1);
            float rs0 = 0.f, rs1 = 0.f;
#pragma unroll
            for (int nf = 0; nf < 8; nf++) {
                float p0 = ex2f(ac[nf][0] - mn0);
                float p1 = ex2f(ac[nf][1] - mn0);
                float p2 = ex2f(ac[nf][2] - mn1);
                float p3 = ex2f(ac[nf][3] - mn1);
                rs0 += p0 + p1; rs1 += p2 + p3;
                pk0[nf] = packh2(p0, p1);
                pk1[nf] = packh2(p2, p3);
            }
            rs0 += __shfl_xor_sync(0xffffffffu, rs0, 1);
            rs0 += __shfl_xor_sync(0xffffffffu, rs0, 2);
            rs1 += __shfl_xor_sync(0xffffffffu, rs1, 1);
            rs1 += __shfl_xor_sync(0xffffffffu, rs1, 2);
            l0 = l0 * c0 + rs0; l1 = l1 * c1 + rs1;
            m0 = mn0; m1 = mn1;
#pragma unroll
            for (int nf = 0; nf < 8; nf++) {
                O[nf][0] *= c0; O[nf][1] *= c0; O[nf][2] *= c1; O[nf][3] *= c1;
            }
        }

        // ---- P·V mma: A = P straight from registers (C-frag == A-frag)
#pragma unroll
        for (int ks = 0; ks < 4; ks++) {
            unsigned a[4] = {pk0[2 * ks], pk1[2 * ks], pk0[2 * ks + 1], pk1[2 * ks + 1]};
#pragma unroll
            for (int pr = 0; pr < 4; pr++) {
                unsigned bb[4];
                ldmx4(bb, v_b + pr * PRSTRIDE + ks * 32);
                mma16(O[2 * pr],     a, bb);
                mma16(O[2 * pr + 1], a, bb + 2);
            }
        }

        barg(gr + 1);
        if (kt + 2 < nkt) issue(kt + 2);
    }

    // ---- merge the two groups' partial softmax states, write output --------
    if (wid >= 4) {
#pragma unroll
        for (int nf = 0; nf < 8; nf++) {
            *(float2*)(BDrow + nf * 8 + 2 * t) = make_float2(O[nf][0], O[nf][1]);
            *(float2*)(BDrow + 8 * BDW + nf * 8 + 2 * t) = make_float2(O[nf][2], O[nf][3]);
        }
        if (t == 0) {
            BDrow[80] = m0; BDrow[81] = l0;
            BDrow[8 * BDW + 80] = m1; BDrow[8 * BDW + 81] = l1;
        }
    }
    __syncthreads();
    if (wid < 4) {
        const float* Peer = BDb + ((wid + 4) * 16 + g) * BDW;
        float pm0 = Peer[80], pl0 = Peer[81];
        float pm1 = Peer[8 * BDW + 80], pl1 = Peer[8 * BDW + 81];
        float M0 = fmaxf(m0, pm0), M1 = fmaxf(m1, pm1);
        float a0 = ex2f(m0 - M0), e0 = ex2f(pm0 - M0);
        float a1 = ex2f(m1 - M1), e1 = ex2f(pm1 - M1);
        float i0 = 1.0f / (l0 * a0 + pl0 * e0);
        float i1 = 1.0f / (l1 * a1 + pl1 * e1);
        int sg0 = s0 + wid * 16 + g;
#pragma unroll
        for (int nf = 0; nf < 8; nf++) {
            int c = hoff + nf * 8 + 2 * t;
            float2 po0 = *(const float2*)(Peer + nf * 8 + 2 * t);
            float2 po1 = *(const float2*)(Peer + 8 * BDW + nf * 8 + 2 * t);
            *(__half2*)(attn + ((size_t)sg0 * Bx + b) * Ex + c) =
                __floats2half2_rn((O[nf][0] * a0 + po0.x * e0) * i0,
                                  (O[nf][1] * a0 + po0.y * e0) * i0);
            *(__half2*)(attn + ((size_t)(sg0 + 8) * Bx + b) * Ex + c) =
                __floats2half2_rn((O[nf][2] * a1 + po1.x * e1) * i1,
                                  (O[nf][3] * a1 + po1.y * e1) * i1);
        }
    }
}

// ---------------- LayerNorm(X + Y); optional fp16 second copy ---------------
__global__ void ln_add_kernel(const float* __restrict__ X, const float* __restrict__ Y,
                              const float* __restrict__ g, const float* __restrict__ bb,
                              float* __restrict__ out, __half* __restrict__ out_h)
{
    __shared__ float red[4];
    int row = blockIdx.x;
    int tid = threadIdx.x;
    const float4* X4 = (const float4*)(X + (size_t)row * Ex);
    const float4* Y4 = (const float4*)(Y + (size_t)row * Ex);
    float4 x = X4[tid], y = Y4[tid];
    float4 vv = {x.x + y.x, x.y + y.y, x.z + y.z, x.w + y.w};
    float s = vv.x + vv.y + vv.z + vv.w;
#pragma unroll
    for (int off = 16; off; off >>= 1) s += __shfl_xor_sync(0xffffffffu, s, off);
    if ((tid & 31) == 0) red[tid >> 5] = s;
    __syncthreads();
    float mu = (red[0] + red[1] + red[2] + red[3]) * (1.f / 512.f);
    float d0 = vv.x - mu, d1 = vv.y - mu, d2 = vv.z - mu, d3 = vv.w - mu;
    float q = d0 * d0 + d1 * d1 + d2 * d2 + d3 * d3;
    __syncthreads();
#pragma unroll
    for (int off = 16; off; off >>= 1) q += __shfl_xor_sync(0xffffffffu, q, off);
    if ((tid & 31) == 0) red[tid >> 5] = q;
    __syncthreads();
    float var = (red[0] + red[1] + red[2] + red[3]) * (1.f / 512.f);
    float rs = rsqrtf(var + EPSF);
    float4 gg = ((const float4*)g)[tid], bv = ((const float4*)bb)[tid];
    float4 o;
    o.x = d0 * rs * gg.x + bv.x;
    o.y = d1 * rs * gg.y + bv.y;
    o.z = d2 * rs * gg.z + bv.z;
    o.w = d3 * rs * gg.w + bv.w;
    ((float4*)(out + (size_t)row * Ex))[tid] = o;
    if (out_h) {
        __half2* oh = (__half2*)(out_h + (size_t)row * Ex);
        oh[tid * 2]     = __floats2half2_rn(o.x, o.y);
        oh[tid * 2 + 1] = __floats2half2_rn(o.z, o.w);
    }
}

// ---------------------------------------------------------------------------
extern "C" void kernel_launch(void* const* d_in, const int* in_sizes, int n_in,
                              void* d_out, int out_size)
{
    const float* inputDec = (const float*)d_in[0];
    const float* posEmb   = (const float*)d_in[1];
    const float* u        = (const float*)d_in[2];
    const float* v        = (const float*)d_in[3];
    const float* memories = (const float*)d_in[4];
    const float* Wqkv     = (const float*)d_in[5];
    const float* Wr       = (const float*)d_in[6];
    const float* Wo       = (const float*)d_in[7];
    const float* ln1_g    = (const float*)d_in[8];
    const float* ln1_b    = (const float*)d_in[9];
    const float* W1       = (const float*)d_in[10];
    const float* b1       = (const float*)d_in[11];
    const float* W2       = (const float*)d_in[12];
    const float* b2       = (const float*)d_in[13];
    const float* ln2_g    = (const float*)d_in[14];
    const float* ln2_b    = (const float*)d_in[15];
    float* out = (float*)d_out;

    __half *qkv, *rb, *vt, *attn, *attnout_h, *ff1;
    __half *mem_h, *inp_h, *pos_h, *wqkv_t, *wr_t, *wo_t, *w1_t, *w2_t;
    float *tmp, *attnout, *ff2;
    cudaGetSymbolAddress((void**)&qkv,       g_qkv);
    cudaGetSymbolAddress((void**)&rb,        g_rb);
    cudaGetSymbolAddress((void**)&vt,        g_vt);
    cudaGetSymbolAddress((void**)&attn,      g_attn);
    cudaGetSymbolAddress((void**)&tmp,       g_tmp);
    cudaGetSymbolAddress((void**)&attnout,   g_attnout);
    cudaGetSymbolAddress((void**)&attnout_h, g_attnout_h);
    cudaGetSymbolAddress((void**)&ff1,       g_ff1);
    cudaGetSymbolAddress((void**)&ff2,       g_ff2);
    cudaGetSymbolAddress((void**)&mem_h,     g_mem_h);
    cudaGetSymbolAddress((void**)&inp_h,     g_inp_h);
    cudaGetSymbolAddress((void**)&pos_h,     g_pos_h);
    cudaGetSymbolAddress((void**)&wqkv_t,    g_wqkv_t);
    cudaGetSymbolAddress((void**)&wr_t,      g_wr_t);
    cudaGetSymbolAddress((void**)&wo_t,      g_wo_t);
    cudaGetSymbolAddress((void**)&w1_t,      g_w1_t);
    cudaGetSymbolAddress((void**)&w2_t,      g_w2_t);

    cudaFuncSetAttribute(flash, cudaFuncAttributeMaxDynamicSharedMemorySize, FLASH_SMEM);
    cudaFuncSetAttribute(tgemm<0,true,true>,   cudaFuncAttributeMaxDynamicSharedMemorySize, GEMM_SMEM);
    cudaFuncSetAttribute(tgemm<0,false,true>,  cudaFuncAttributeMaxDynamicSharedMemorySize, GEMM_SMEM);
    cudaFuncSetAttribute(tgemm<0,false,false>, cudaFuncAttributeMaxDynamicSharedMemorySize, GEMM_SMEM);
    cudaFuncSetAttribute(tgemm<2,false,true>,  cudaFuncAttributeMaxDynamicSharedMemorySize, GEMM_SMEM);
    cudaFuncSetAttribute(tgemm<1,false,false>, cudaFuncAttributeMaxDynamicSharedMemorySize, GEMM_SMEM);

    // 0a) activations fp32 -> fp16 (launch #1)
    {
        CSegs cs;
        cs.src[0] = (const float4*)memories; cs.dst[0] = (uint2*)mem_h;
        cs.n4[0] = (int)((size_t)Mx * Bx * Ex / 4);
        cs.src[1] = (const float4*)inputDec; cs.dst[1] = (uint2*)inp_h;
        cs.n4[1] = (int)((size_t)Sx * Bx * Ex / 4);
        cs.src[2] = (const float4*)posEmb;   cs.dst[2] = (uint2*)pos_h;
        cs.n4[2] = (int)((size_t)Kx * Ex / 4);
        int maxb = 0;
        for (int i = 0; i < 3; i++) { int bl = (cs.n4[i] + 255) / 256; if (bl > maxb) maxb = bl; }
        cvtall<<<dim3(maxb, 3), 256>>>(cs);
    }
    // 0b) all 5 weight transposes in ONE launch (launch #2)
    {
        TSegs ts;
        const float* Ws[5] = {Wqkv, Wr, Wo, W1, W2};
        __half* Wts[5] = {wqkv_t, wr_t, wo_t, w1_t, w2_t};
        int Ks[5] = {Ex, Ex, Ex, Ex, FFx};
        int Ns[5] = {QKV3, Ex, Ex, FFx, Ex};
        int c = 0;
        ts.cum[0] = 0;
        for (int i = 0; i < 5; i++) {
            ts.W[i] = Ws[i]; ts.Wt[i] = Wts[i];
            ts.K[i] = Ks[i]; ts.N[i] = Ns[i];
            ts.tilesN[i] = Ns[i] / 32;
            c += (Ks[i] / 32) * (Ns[i] / 32);
            ts.cum[i + 1] = c;
        }
        transw_all<<<c, dim3(32, 8)>>>(ts);
    }

    // 1) qkv GEMM
    tgemm<0,true,true><<<dim3(QKV3/128, KB_/128), 256, GEMM_SMEM>>>(
        mem_h, inp_h, Mx * Bx, wqkv_t, nullptr, qkv, QKV3, Ex);
    // 2) r GEMM
    tgemm<0,false,true><<<dim3(Ex/128, Kx/128), 256, GEMM_SMEM>>>(
        pos_h, nullptr, 0, wr_t, nullptr, rb, Ex, Ex);
    // 2b) V transpose
    vtrans<<<dim3(Kx/32, Ex/32, Bx), dim3(32,8)>>>(qkv, vt);
    // 3) flash attention (R7 proven kernel)
    flash<<<dim3(Sx/64, Bx*Hx), 256, FLASH_SMEM>>>(qkv, rb, vt, u, v, attn);
    // 4) attn @ Wo
    tgemm<0,false,false><<<dim3(Ex/128, ROWS/128), 256, GEMM_SMEM>>>(
        attn, nullptr, 0, wo_t, nullptr, tmp, Ex, Ex);
    // 5) attn_out = LN(inputDec + attnWo)
    ln_add_kernel<<<ROWS, 128>>>(inputDec, tmp, ln1_g, ln1_b, attnout, attnout_h);
    // 6) ff1 = relu(attn_out @ W1 + b1)
    tgemm<2,false,true><<<dim3(FFx/128, ROWS/128), 256, GEMM_SMEM>>>(
        attnout_h, nullptr, 0, w1_t, b1, ff1, FFx, Ex);
    // 7) ff2 = ff1 @ W2 + b2
    tgemm<1,false,false><<<dim3(Ex/128, ROWS/128), 256, GEMM_SMEM>>>(
        ff1, nullptr, 0, w2_t, b2, ff2, Ex, FFx);
    // 8) out = LN(attn_out + ff2)
    ln_add_kernel<<<ROWS, 128>>>(attnout, ff2, ln2_g, ln2_b, out, nullptr);
}

// round 12
// speedup vs baseline: 13.5895x; 1.0230x over previous
#include <cuda_runtime.h>
#include <cuda_fp16.h>
#include <cstdint>

#define Sx 2048
#define Bx 2
#define Ex 512
#define Hx 8
#define Mx 2048
#define Kx 4096          // M + S
#define QKV3 1536
#define FFx 2048
#define ROWS (Sx*Bx)     // 4096
#define KB_ (Kx*Bx)      // 8192
#define EPSF 1e-5f
#define SCL 0.18033688f  // 0.125 * log2(e): softmax in base-2 domain

// ---------------- scratch (static device arrays: no allocation) -------------
__device__ __align__(128) __half g_qkv[(size_t)KB_ * QKV3];
__device__ __align__(128) __half g_rb[(size_t)Kx * Ex];
__device__ __align__(128) __half g_vt[(size_t)Bx * Ex * Kx];
__device__ __align__(128) __half g_attn[(size_t)ROWS * Ex];
__device__ __align__(128) float  g_tmp[(size_t)ROWS * Ex];
__device__ __align__(128) float  g_attnout[(size_t)ROWS * Ex];
__device__ __align__(128) __half g_attnout_h[(size_t)ROWS * Ex];
__device__ __align__(128) __half g_ff1[(size_t)ROWS * FFx];
__device__ __align__(128) float  g_ff2[(size_t)ROWS * Ex];
__device__ __align__(128) __half g_mem_h[(size_t)Mx * Bx * Ex];
__device__ __align__(128) __half g_inp_h[(size_t)Sx * Bx * Ex];
__device__ __align__(128) __half g_pos_h[(size_t)Kx * Ex];
__device__ __align__(128) __half g_wqkv_t[(size_t)QKV3 * Ex];
__device__ __align__(128) __half g_wr_t[(size_t)Ex * Ex];
__device__ __align__(128) __half g_wo_t[(size_t)Ex * Ex];
__device__ __align__(128) __half g_w1_t[(size_t)FFx * Ex];
__device__ __align__(128) __half g_w2_t[(size_t)Ex * FFx];

// ---------------- helpers ---------------------------------------------------
__device__ __forceinline__ void mma16(float* d, const unsigned* a, const unsigned* b) {
    asm volatile(
        "mma.sync.aligned.m16n8k16.row.col.f32.f16.f16.f32 "
        "{%0,%1,%2,%3},{%4,%5,%6,%7},{%8,%9},{%0,%1,%2,%3};\n"
        : "+f"(d[0]), "+f"(d[1]), "+f"(d[2]), "+f"(d[3])
        : "r"(a[0]), "r"(a[1]), "r"(a[2]), "r"(a[3]), "r"(b[0]), "r"(b[1]));
}
__device__ __forceinline__ void ldmx4(unsigned* r, unsigned a) {
    asm volatile("ldmatrix.sync.aligned.m8n8.x4.shared.b16 {%0,%1,%2,%3}, [%4];"
        : "=r"(r[0]), "=r"(r[1]), "=r"(r[2]), "=r"(r[3]) : "r"(a));
}
__device__ __forceinline__ float ex2f(float x) {
    float r; asm("ex2.approx.f32 %0, %1;" : "=f"(r) : "f"(x)); return r;
}
__device__ __forceinline__ unsigned sptr(const void* p) {
    return (unsigned)__cvta_generic_to_shared(p);
}
__device__ __forceinline__ void cpa16(unsigned d, const void* s) {
    asm volatile("cp.async.cg.shared.global [%0], [%1], 16;\n" :: "r"(d), "l"(s));
}
__device__ __forceinline__ void cpcommit() { asm volatile("cp.async.commit_group;\n"); }
template<int N> __device__ __forceinline__ void cpwait() {
    asm volatile("cp.async.wait_group %0;\n" :: "n"(N));
}
__device__ __forceinline__ void barg(int id) {
    asm volatile("bar.sync %0, 128;" :: "r"(id) : "memory");
}
__device__ __forceinline__ unsigned packh2(float a, float b) {
    __half2 h = __floats2half2_rn(a, b);
    return *(unsigned*)&h;
}

// ---------------- fp32 -> fp16 conversion, 3 segments in one launch ---------
struct CSegs { const float4* src[3]; uint2* dst[3]; int n4[3]; };
__global__ void cvtall(CSegs segs) {
    int seg = blockIdx.y;
    int i = blockIdx.x * 256 + threadIdx.x;
    if (i < segs.n4[seg]) {
        float4 v = segs.src[seg][i];
        __half2 h01 = __floats2half2_rn(v.x, v.y);
        __half2 h23 = __floats2half2_rn(v.z, v.w);
        segs.dst[seg][i] = make_uint2(*(unsigned*)&h01, *(unsigned*)&h23);
    }
}

// ------- weight transpose + fp16 convert, ALL 5 weights, one launch ---------
struct TSegs { const float* W[5]; __half* Wt[5]; int K[5], N[5], tilesN[5], cum[6]; };
__global__ void transw_all(TSegs s) {
    int bid = blockIdx.x;
    int seg = 0;
#pragma unroll
    for (int i = 0; i < 5; i++) if (bid >= s.cum[i + 1]) seg = i + 1;
    int lt = bid - s.cum[seg];
    int K = s.K[seg], N = s.N[seg];
    int n0 = (lt % s.tilesN[seg]) * 32, k0 = (lt / s.tilesN[seg]) * 32;
    const float* W = s.W[seg];
    __half* Wt = s.Wt[seg];
    __shared__ float t[32][33];
    int tx = threadIdx.x, ty = threadIdx.y;   // 32 x 8
#pragma unroll
    for (int j = 0; j < 4; j++)
        t[ty + j * 8][tx] = W[(size_t)(k0 + ty + j * 8) * N + n0 + tx];
    __syncthreads();
#pragma unroll
    for (int j = 0; j < 4; j++)
        Wt[(size_t)(n0 + ty + j * 8) * K + k0 + tx] = __float2half_rn(t[tx][ty + j * 8]);
}

// ---------------- V transpose: vt[b*512+c][key] = qkv_V[key][b][c] ----------
__global__ void vtrans(const __half* __restrict__ qkv, __half* __restrict__ vt) {
    __shared__ __half t[32][40];
    int b = blockIdx.z;
    int key0 = blockIdx.x * 32, c0 = blockIdx.y * 32;
    int tx = threadIdx.x, ty = threadIdx.y;   // 32 x 8
#pragma unroll
    for (int j = 0; j < 4; j++)
        t[ty + j * 8][tx] =
            qkv[((size_t)(key0 + ty + j * 8) * Bx + b) * QKV3 + 1024 + c0 + tx];
    __syncthreads();
#pragma unroll
    for (int j = 0; j < 4; j++)
        vt[((size_t)(b * Ex + c0 + ty + j * 8)) * Kx + key0 + tx] = t[tx][ty + j * 8];
}

// ------- FP16 GEMM: C(MxN)=A(MxK)*Bt(NxK)^T, 128x128x32, 4-stage pipe ------
#define AH 40
#define GSTG 4
#define GBUF (128*AH*2)          // bytes per operand per stage
#define GEMM_SMEM (2*GSTG*GBUF)  // A stages + B stages

template<int EPI, bool SPLITA, bool OUTH>
__global__ __launch_bounds__(256, 2) void tgemm(
    const __half* __restrict__ A0, const __half* __restrict__ A1, int splitRow,
    const __half* __restrict__ Bt, const float* __restrict__ bias,
    void* __restrict__ Cv, int Nd, int Kd)
{
    extern __shared__ __align__(16) __half sh[];
    __half* As = sh;                      // [GSTG][128][AH]
    __half* Bs = sh + GSTG * 128 * AH;    // [GSTG][128][AH]
    const int tid = threadIdx.x, lane = tid & 31, wid = tid >> 5;
    const int wm = wid >> 2, wn = wid & 3, g = lane >> 2, t = lane & 3;
    const int bm = blockIdx.y * 128, bn = blockIdx.x * 128;

    const __half* asrc[2]; const __half* bsrc[2];
    unsigned adst[2], bdst[2];
#pragma unroll
    for (int p = 0; p < 2; p++) {
        int id = tid + p * 256;
        int r = id >> 2, c8 = (id & 3) * 8;
        int grow = bm + r;
        const __half* abase = (SPLITA && grow >= splitRow)
                              ? (A1 + (size_t)(grow - splitRow) * Kd)
                              : (A0 + (size_t)grow * Kd);
        asrc[p] = abase + c8;
        adst[p] = sptr(As + r * AH + c8);
        bsrc[p] = Bt + (size_t)(bn + r) * Kd + c8;
        bdst[p] = sptr(Bs + r * AH + c8);
    }

    // ldmatrix lane constants
    const int r_in = lane & 7;
    const int a_row8 = ((lane >> 3) & 1) * 8;
    const int a_k8 = (lane >> 4) * 8;
    const int b_nf8 = (lane >> 4) * 8;
    const int b_k8 = ((lane >> 3) & 1) * 8;
    const unsigned aAddr0 = sptr(As + (wm * 64 + r_in + a_row8) * AH + a_k8);
    const unsigned bAddr0 = sptr(Bs + (wn * 32 + b_nf8 + r_in) * AH + b_k8);

    float acc[4][4][4];
#pragma unroll
    for (int i = 0; i < 4; i++)
#pragma unroll
        for (int j = 0; j < 4; j++)
#pragma unroll
            for (int r = 0; r < 4; r++) acc[i][j][r] = 0.f;

    auto issue = [&](int stage) {
        unsigned off = (unsigned)(stage % GSTG) * GBUF;
        int k0 = stage << 5;
#pragma unroll
        for (int p = 0; p < 2; p++) {
            cpa16(adst[p] + off, asrc[p] + k0);
            cpa16(bdst[p] + off, bsrc[p] + k0);
        }
        cpcommit();
    };

    int nkt = Kd >> 5;   // >= 16 for all our shapes
#pragma unroll
    for (int s = 0; s < GSTG - 1; s++) issue(s);

    for (int kt = 0; kt < nkt; kt++) {
        cpwait<GSTG - 2>();
        __syncthreads();
        // prefetch into the buffer consumed at kt-1 (safe: barrier above)
        if (kt + GSTG - 1 < nkt) issue(kt + GSTG - 1);

        unsigned off = (unsigned)(kt % GSTG) * GBUF;
        unsigned aAddr = aAddr0 + off;
        unsigned bAddr = bAddr0 + off;
#pragma unroll
        for (int ks = 0; ks < 2; ks++) {
            unsigned a4[4][4], b4[2][4];
#pragma unroll
            for (int mf = 0; mf < 4; mf++)
                ldmx4(a4[mf], aAddr + mf * (16 * AH * 2) + ks * 32);
#pragma unroll
            for (int n2 = 0; n2 < 2; n2++)
                ldmx4(b4[n2], bAddr + n2 * (16 * AH * 2) + ks * 32);
#pragma unroll
            for (int mf = 0; mf < 4; mf++)
#pragma unroll
                for (int n2 = 0; n2 < 2; n2++) {
                    mma16(acc[mf][2 * n2],     a4[mf], b4[n2]);
                    mma16(acc[mf][2 * n2 + 1], a4[mf], b4[n2] + 2);
                }
        }
    }

#pragma unroll
    for (int mf = 0; mf < 4; mf++) {
        int r0 = bm + wm * 64 + mf * 16 + g;
#pragma unroll
        for (int nf = 0; nf < 4; nf++) {
            int c = bn + wn * 32 + nf * 8 + 2 * t;
            float v0 = acc[mf][nf][0], v1 = acc[mf][nf][1];
            float v2 = acc[mf][nf][2], v3 = acc[mf][nf][3];
            if (EPI >= 1) {
                float b0 = bias[c], b1v = bias[c + 1];
                v0 += b0; v1 += b1v; v2 += b0; v3 += b1v;
            }
            if (EPI == 2) {
                v0 = fmaxf(v0, 0.f); v1 = fmaxf(v1, 0.f);
                v2 = fmaxf(v2, 0.f); v3 = fmaxf(v3, 0.f);
            }
            if (OUTH) {
                __half* C = (__half*)Cv;
                *(__half2*)(C + (size_t)r0 * Nd + c)       = __floats2half2_rn(v0, v1);
                *(__half2*)(C + (size_t)(r0 + 8) * Nd + c) = __floats2half2_rn(v2, v3);
            } else {
                float* C = (float*)Cv;
                *(float2*)(C + (size_t)r0 * Nd + c)       = make_float2(v0, v1);
                *(float2*)(C + (size_t)(r0 + 8) * Nd + c) = make_float2(v2, v3);
            }
        }
    }
}

// ---------------- Flash attention: R10 structure + per-group double buffer --
// 256 threads, 2 key-split groups (4 warps each). Each group now owns TWO
// K/V/R stage buffers (slot = gr*2 + st): the load for iteration i+2 is
// issued at the end of iteration i and waited two iterations later, adding a
// full own-group compute iteration of latency slack on top of cross-group
// overlap. Launch config, arithmetic, and merge identical to R10.
#define FST 72
#define BDW 84
#define OFF_QU 0
#define OFF_QV 9216
#define OFF_K  18432       // 4 slots x 64 x FST halves
#define OFF_V  55296       // 4 slots x 64 x FST halves
#define OFF_R  92160       // 4 slots x 128 x FST halves
#define OFF_BD 165888
#define FLASH_SMEM 208896
#define PRSTRIDE 2304      // 16 * FST * 2 bytes
#define KSTB 9216          // bytes per K/V stage buffer
#define RSTB 18432         // bytes per R stage buffer

__global__ __launch_bounds__(256, 1) void flash(
    const __half* __restrict__ qkv, const __half* __restrict__ rbuf,
    const __half* __restrict__ vt,
    const float* __restrict__ u, const float* __restrict__ v,
    __half* __restrict__ attn)
{
    extern __shared__ __align__(16) char smc[];
    __half* Qu = (__half*)(smc + OFF_QU);
    __half* Qv = (__half*)(smc + OFF_QV);
    __half* Ks = (__half*)(smc + OFF_K);
    __half* Vs = (__half*)(smc + OFF_V);
    __half* Rs = (__half*)(smc + OFF_R);
    float*  BDb = (float*)(smc + OFF_BD);
    const int tid = threadIdx.x, lane = tid & 31, wid = tid >> 5;
    const int g = lane >> 2, t = lane & 3;
    const int gr = wid >> 2, wg = wid & 3;
    const int gtid = tid & 127;
    const int qt = (gridDim.x - 1) - blockIdx.x;
    const int b = blockIdx.y >> 3, h = blockIdx.y & 7;
    const int s0 = qt * 64, hoff = h * 64;
    const int nkt = qt + 33;

    auto issue = [&](int kt, int st) {
        int k0 = kt * 64;
        int slot = gr * 2 + st;
#pragma unroll
        for (int p = 0; p < 4; p++) {
            int id = gtid + p * 128;
            int row = id >> 3, c = (id & 7) * 8;
            const __half* ksrc = qkv + ((size_t)(k0 + row) * Bx + b) * QKV3 + 512 + hoff + c;
            cpa16(sptr(Ks + slot * 64 * FST + row * FST + c), ksrc);
            cpa16(sptr(Vs + slot * 64 * FST + row * FST + c),
                  vt + ((size_t)(b * Ex + hoff + row)) * Kx + k0 + c);
        }
        int jlo = k0 + (Sx - 1) - s0 - 63;
#pragma unroll
        for (int p = 0; p < 8; p++) {
            int id = gtid + p * 128;
            int d = id >> 3, c = (id & 7) * 8;
            int j = jlo + d; if (j > Kx - 1) j = Kx - 1;   // clamped cells are masked
            cpa16(sptr(Rs + slot * 128 * FST + d * FST + c), rbuf + (size_t)j * Ex + hoff + c);
        }
        cpcommit();
    };
    issue(gr, 0);
    if (gr + 2 < nkt) issue(gr + 2, 1);

    for (int idx = tid; idx < 64 * 64; idx += 256) {
        int sR = idx >> 6, i = idx & 63;
        float qv_ = __half2float(qkv[((size_t)(Mx + s0 + sR) * Bx + b) * QKV3 + hoff + i]);
        Qu[sR * FST + i] = __float2half_rn(qv_ + u[hoff + i]);
        Qv[sR * FST + i] = __float2half_rn(qv_ + v[hoff + i]);
    }
    __syncthreads();

    float m0 = -1e30f, m1 = -1e30f, l0 = 0.f, l1 = 0.f;
    float O[8][4];
#pragma unroll
    for (int i = 0; i < 8; i++)
#pragma unroll
        for (int j = 0; j < 4; j++) O[i][j] = 0.f;

    float* BDrow = BDb + (wid * 16 + g) * BDW;
    const int c_base = 48 - wg * 16;

    const int r_in = lane & 7;
    const int a_row8 = ((lane >> 3) & 1) * 8;
    const int a_k8 = (lane >> 4) * 8;
    const int b_nf8 = (lane >> 4) * 8;
    const int b_k8 = ((lane >> 3) & 1) * 8;
    const unsigned qu_a = sptr(Qu + (wg * 16 + r_in + a_row8) * FST + a_k8);
    const unsigned qv_a = sptr(Qv + (wg * 16 + r_in + a_row8) * FST + a_k8);
    const unsigned k_b0 = sptr(Ks + (gr * 2) * 64 * FST + (b_nf8 + r_in) * FST + b_k8);
    const unsigned r_b0 = sptr(Rs + (gr * 2) * 128 * FST + (c_base + b_nf8 + r_in) * FST + b_k8);
    const unsigned v_b0 = sptr(Vs + (gr * 2) * 64 * FST + (b_nf8 + r_in) * FST + b_k8);

    int st = 0;
    for (int kt = gr; kt < nkt; kt += 2, st ^= 1) {
        int k0 = kt * 64;
        if (kt + 2 < nkt) cpwait<1>(); else cpwait<0>();
        barg(gr + 1);
        const unsigned k_b = k_b0 + st * KSTB;
        const unsigned r_b = r_b0 + st * RSTB;
        const unsigned v_b = v_b0 + st * KSTB;

        // ---- BD band mma: 16 x 80 per warp -> fp32 smem
        {
            float bd[10][4];
#pragma unroll
            for (int nf = 0; nf < 10; nf++)
#pragma unroll
                for (int j = 0; j < 4; j++) bd[nf][j] = 0.f;
#pragma unroll
            for (int ks = 0; ks < 4; ks++) {
                unsigned a[4];
                ldmx4(a, qv_a + ks * 32);
#pragma unroll
                for (int pr = 0; pr < 5; pr++) {
                    unsigned bb[4];
                    ldmx4(bb, r_b + pr * PRSTRIDE + ks * 32);
                    mma16(bd[2 * pr],     a, bb);
                    mma16(bd[2 * pr + 1], a, bb + 2);
                }
            }
#pragma unroll
            for (int nf = 0; nf < 10; nf++) {
                *(float2*)(BDrow + nf * 8 + 2 * t) = make_float2(bd[nf][0], bd[nf][1]);
                *(float2*)(BDrow + 8 * BDW + nf * 8 + 2 * t) = make_float2(bd[nf][2], bd[nf][3]);
            }
        }
        __syncwarp();

        // ---- AC mma: 16 x 64 per warp
        float ac[8][4];
#pragma unroll
        for (int nf = 0; nf < 8; nf++)
#pragma unroll
            for (int j = 0; j < 4; j++) ac[nf][j] = 0.f;
#pragma unroll
        for (int ks = 0; ks < 4; ks++) {
            unsigned a[4];
            ldmx4(a, qu_a + ks * 32);
#pragma unroll
            for (int pr = 0; pr < 4; pr++) {
                unsigned bb[4];
                ldmx4(bb, k_b + pr * PRSTRIDE + ks * 32);
                mma16(ac[2 * pr],     a, bb);
                mma16(ac[2 * pr + 1], a, bb + 2);
            }
        }

        // ---- combine with BD diagonal + mask; scale into base-2 domain
        {
            int lim0 = s0 + wg * 16 + g + Mx, lim1 = lim0 + 8;
#pragma unroll
            for (int nf = 0; nf < 8; nf++) {
                int kc = nf * 8 + 2 * t;
                float v0 = (ac[nf][0] + BDrow[kc + 15 - g]) * SCL;
                float v1 = (ac[nf][1] + BDrow[kc + 16 - g]) * SCL;
                float v2 = (ac[nf][2] + BDrow[8 * BDW + kc + 7 - g]) * SCL;
                float v3 = (ac[nf][3] + BDrow[8 * BDW + kc + 8 - g]) * SCL;
                if (k0 + kc > lim0)     v0 = -1e30f;
                if (k0 + kc + 1 > lim0) v1 = -1e30f;
                if (k0 + kc > lim1)     v2 = -1e30f;
                if (k0 + kc + 1 > lim1) v3 = -1e30f;
                ac[nf][0] = v0; ac[nf][1] = v1; ac[nf][2] = v2; ac[nf][3] = v3;
            }
        }

        // ---- online softmax (base-2); P packed directly into A-fragments
        unsigned pk0[8], pk1[8];
        {
            float mx0 = -1e30f, mx1 = -1e30f;
#pragma unroll
            for (int nf = 0; nf < 8; nf++) {
                mx0 = fmaxf(mx0, fmaxf(ac[nf][0], ac[nf][1]));
                mx1 = fmaxf(mx1, fmaxf(ac[nf][2], ac[nf][3]));
            }
            mx0 = fmaxf(mx0, __shfl_xor_sync(0xffffffffu, mx0, 1));
            mx0 = fmaxf(mx0, __shfl_xor_sync(0xffffffffu, mx0, 2));
            mx1 = fmaxf(mx1, __shfl_xor_sync(0xffffffffu, mx1, 1));
            mx1 = fmaxf(mx1, __shfl_xor_sync(0xffffffffu, mx1, 2));
            float mn0 = fmaxf(m0, mx0), mn1 = fmaxf(m1, mx1);
            float c0 = ex2f(m0 - mn0), c1 = ex2f(m1 - mn1);
            float rs0 = 0.f, rs1 = 0.f;
#pragma unroll
            for (int nf = 0; nf < 8; nf++) {
                float p0 = ex2f(ac[nf][0] - mn0);
                float p1 = ex2f(ac[nf][1] - mn0);
                float p2 = ex2f(ac[nf][2] - mn1);
                float p3 = ex2f(ac[nf][3] - mn1);
                rs0 += p0 + p1; rs1 += p2 + p3;
                pk0[nf] = packh2(p0, p1);
                pk1[nf] = packh2(p2, p3);
            }
            rs0 += __shfl_xor_sync(0xffffffffu, rs0, 1);
            rs0 += __shfl_xor_sync(0xffffffffu, rs0, 2);
            rs1 += __shfl_xor_sync(0xffffffffu, rs1, 1);
            rs1 += __shfl_xor_sync(0xffffffffu, rs1, 2);
            l0 = l0 * c0 + rs0; l1 = l1 * c1 + rs1;
            m0 = mn0; m1 = mn1;
#pragma unroll
            for (int nf = 0; nf < 8; nf++) {
                O[nf][0] *= c0; O[nf][1] *= c0; O[nf][2] *= c1; O[nf][3] *= c1;
            }
        }

        // ---- P·V mma: A = P straight from registers (C-frag == A-frag)
#pragma unroll
        for (int ks = 0; ks < 4; ks++) {
            unsigned a[4] = {pk0[2 * ks], pk1[2 * ks], pk0[2 * ks + 1], pk1[2 * ks + 1]};
#pragma unroll
            for (int pr = 0; pr < 4; pr++) {
                unsigned bb[4];
                ldmx4(bb, v_b + pr * PRSTRIDE + ks * 32);
                mma16(O[2 * pr],     a, bb);
                mma16(O[2 * pr + 1], a, bb + 2);
            }
        }

        barg(gr + 1);   // group done reading stage st before it is refilled
        if (kt + 4 < nkt) issue(kt + 4, st);
    }

    // ---- merge the two groups' partial softmax states, write output --------
    __syncthreads();
    if (wid >= 4) {
#pragma unroll
        for (int nf = 0; nf < 8; nf++) {
            *(float2*)(BDrow + nf * 8 + 2 * t) = make_float2(O[nf][0], O[nf][1]);
            *(float2*)(BDrow + 8 * BDW + nf * 8 + 2 * t) = make_float2(O[nf][2], O[nf][3]);
        }
        if (t == 0) {
            BDrow[80] = m0; BDrow[81] = l0;
            BDrow[8 * BDW + 80] = m1; BDrow[8 * BDW + 81] = l1;
        }
    }
    __syncthreads();
    if (wid < 4) {
        const float* Peer = BDb + ((wid + 4) * 16 + g) * BDW;
        float pm0 = Peer[80], pl0 = Peer[81];
        float pm1 = Peer[8 * BDW + 80], pl1 = Peer[8 * BDW + 81];
        float M0 = fmaxf(m0, pm0), M1 = fmaxf(m1, pm1);
        float a0 = ex2f(m0 - M0), e0 = ex2f(pm0 - M0);
        float a1 = ex2f(m1 - M1), e1 = ex2f(pm1 - M1);
        float i0 = 1.0f / (l0 * a0 + pl0 * e0);
        float i1 = 1.0f / (l1 * a1 + pl1 * e1);
        int sg0 = s0 + wid * 16 + g;
#pragma unroll
        for (int nf = 0; nf < 8; nf++) {
            int c = hoff + nf * 8 + 2 * t;
            float2 po0 = *(const float2*)(Peer + nf * 8 + 2 * t);
            float2 po1 = *(const float2*)(Peer + 8 * BDW + nf * 8 + 2 * t);
            *(__half2*)(attn + ((size_t)sg0 * Bx + b) * Ex + c) =
                __floats2half2_rn((O[nf][0] * a0 + po0.x * e0) * i0,
                                  (O[nf][1] * a0 + po0.y * e0) * i0);
            *(__half2*)(attn + ((size_t)(sg0 + 8) * Bx + b) * Ex + c) =
                __floats2half2_rn((O[nf][2] * a1 + po1.x * e1) * i1,
                                  (O[nf][3] * a1 + po1.y * e1) * i1);
        }
    }
}

// ---------------- LayerNorm(X + Y); optional fp16 second copy ---------------
__global__ void ln_add_kernel(const float* __restrict__ X, const float* __restrict__ Y,
                              const float* __restrict__ g, const float* __restrict__ bb,
                              float* __restrict__ out, __half* __restrict__ out_h)
{
    __shared__ float red[4];
    int row = blockIdx.x;
    int tid = threadIdx.x;
    const float4* X4 = (const float4*)(X + (size_t)row * Ex);
    const float4* Y4 = (const float4*)(Y + (size_t)row * Ex);
    float4 x = X4[tid], y = Y4[tid];
    float4 vv = {x.x + y.x, x.y + y.y, x.z + y.z, x.w + y.w};
    float s = vv.x + vv.y + vv.z + vv.w;
#pragma unroll
    for (int off = 16; off; off >>= 1) s += __shfl_xor_sync(0xffffffffu, s, off);
    if ((tid & 31) == 0) red[tid >> 5] = s;
    __syncthreads();
    float mu = (red[0] + red[1] + red[2] + red[3]) * (1.f / 512.f);
    float d0 = vv.x - mu, d1 = vv.y - mu, d2 = vv.z - mu, d3 = vv.w - mu;
    float q = d0 * d0 + d1 * d1 + d2 * d2 + d3 * d3;
    __syncthreads();
#pragma unroll
    for (int off = 16; off; off >>= 1) q += __shfl_xor_sync(0xffffffffu, q, off);
    if ((tid & 31) == 0) red[tid >> 5] = q;
    __syncthreads();
    float var = (red[0] + red[1] + red[2] + red[3]) * (1.f / 512.f);
    float rs = rsqrtf(var + EPSF);
    float4 gg = ((const float4*)g)[tid], bv = ((const float4*)bb)[tid];
    float4 o;
    o.x = d0 * rs * gg.x + bv.x;
    o.y = d1 * rs * gg.y + bv.y;
    o.z = d2 * rs * gg.z + bv.z;
    o.w = d3 * rs * gg.w + bv.w;
    ((float4*)(out + (size_t)row * Ex))[tid] = o;
    if (out_h) {
        __half2* oh = (__half2*)(out_h + (size_t)row * Ex);
        oh[tid * 2]     = __floats2half2_rn(o.x, o.y);
        oh[tid * 2 + 1] = __floats2half2_rn(o.z, o.w);
    }
}

// ---------------------------------------------------------------------------
extern "C" void kernel_launch(void* const* d_in, const int* in_sizes, int n_in,
                              void* d_out, int out_size)
{
    const float* inputDec = (const float*)d_in[0];
    const float* posEmb   = (const float*)d_in[1];
    const float* u        = (const float*)d_in[2];
    const float* v        = (const float*)d_in[3];
    const float* memories = (const float*)d_in[4];
    const float* Wqkv     = (const float*)d_in[5];
    const float* Wr       = (const float*)d_in[6];
    const float* Wo       = (const float*)d_in[7];
    const float* ln1_g    = (const float*)d_in[8];
    const float* ln1_b    = (const float*)d_in[9];
    const float* W1       = (const float*)d_in[10];
    const float* b1       = (const float*)d_in[11];
    const float* W2       = (const float*)d_in[12];
    const float* b2       = (const float*)d_in[13];
    const float* ln2_g    = (const float*)d_in[14];
    const float* ln2_b    = (const float*)d_in[15];
    float* out = (float*)d_out;

    __half *qkv, *rb, *vt, *attn, *attnout_h, *ff1;
    __half *mem_h, *inp_h, *pos_h, *wqkv_t, *wr_t, *wo_t, *w1_t, *w2_t;
    float *tmp, *attnout, *ff2;
    cudaGetSymbolAddress((void**)&qkv,       g_qkv);
    cudaGetSymbolAddress((void**)&rb,        g_rb);
    cudaGetSymbolAddress((void**)&vt,        g_vt);
    cudaGetSymbolAddress((void**)&attn,      g_attn);
    cudaGetSymbolAddress((void**)&tmp,       g_tmp);
    cudaGetSymbolAddress((void**)&attnout,   g_attnout);
    cudaGetSymbolAddress((void**)&attnout_h, g_attnout_h);
    cudaGetSymbolAddress((void**)&ff1,       g_ff1);
    cudaGetSymbolAddress((void**)&ff2,       g_ff2);
    cudaGetSymbolAddress((void**)&mem_h,     g_mem_h);
    cudaGetSymbolAddress((void**)&inp_h,     g_inp_h);
    cudaGetSymbolAddress((void**)&pos_h,     g_pos_h);
    cudaGetSymbolAddress((void**)&wqkv_t,    g_wqkv_t);
    cudaGetSymbolAddress((void**)&wr_t,      g_wr_t);
    cudaGetSymbolAddress((void**)&wo_t,      g_wo_t);
    cudaGetSymbolAddress((void**)&w1_t,      g_w1_t);
    cudaGetSymbolAddress((void**)&w2_t,      g_w2_t);

    cudaFuncSetAttribute(flash, cudaFuncAttributeMaxDynamicSharedMemorySize, FLASH_SMEM);
    cudaFuncSetAttribute(tgemm<0,true,true>,   cudaFuncAttributeMaxDynamicSharedMemorySize, GEMM_SMEM);
    cudaFuncSetAttribute(tgemm<0,false,true>,  cudaFuncAttributeMaxDynamicSharedMemorySize, GEMM_SMEM);
    cudaFuncSetAttribute(tgemm<0,false,false>, cudaFuncAttributeMaxDynamicSharedMemorySize, GEMM_SMEM);
    cudaFuncSetAttribute(tgemm<2,false,true>,  cudaFuncAttributeMaxDynamicSharedMemorySize, GEMM_SMEM);
    cudaFuncSetAttribute(tgemm<1,false,false>, cudaFuncAttributeMaxDynamicSharedMemorySize, GEMM_SMEM);

    // 0a) activations fp32 -> fp16 (launch #1)
    {
        CSegs cs;
        cs.src[0] = (const float4*)memories; cs.dst[0] = (uint2*)mem_h;
        cs.n4[0] = (int)((size_t)Mx * Bx * Ex / 4);
        cs.src[1] = (const float4*)inputDec; cs.dst[1] = (uint2*)inp_h;
        cs.n4[1] = (int)((size_t)Sx * Bx * Ex / 4);
        cs.src[2] = (const float4*)posEmb;   cs.dst[2] = (uint2*)pos_h;
        cs.n4[2] = (int)((size_t)Kx * Ex / 4);
        int maxb = 0;
        for (int i = 0; i < 3; i++) { int bl = (cs.n4[i] + 255) / 256; if (bl > maxb) maxb = bl; }
        cvtall<<<dim3(maxb, 3), 256>>>(cs);
    }
    // 0b) all 5 weight transposes in ONE launch (launch #2)
    {
        TSegs ts;
        const float* Ws[5] = {Wqkv, Wr, Wo, W1, W2};
        __half* Wts[5] = {wqkv_t, wr_t, wo_t, w1_t, w2_t};
        int Ks[5] = {Ex, Ex, Ex, Ex, FFx};
        int Ns[5] = {QKV3, Ex, Ex, FFx, Ex};
        int c = 0;
        ts.cum[0] = 0;
        for (int i = 0; i < 5; i++) {
            ts.W[i] = Ws[i]; ts.Wt[i] = Wts[i];
            ts.K[i] = Ks[i]; ts.N[i] = Ns[i];
            ts.tilesN[i] = Ns[i] / 32;
            c += (Ks[i] / 32) * (Ns[i] / 32);
            ts.cum[i + 1] = c;
        }
        transw_all<<<c, dim3(32, 8)>>>(ts);
    }

    // 1) qkv GEMM
    tgemm<0,true,true><<<dim3(QKV3/128, KB_/128), 256, GEMM_SMEM>>>(
        mem_h, inp_h, Mx * Bx, wqkv_t, nullptr, qkv, QKV3, Ex);
    // 2) r GEMM
    tgemm<0,false,true><<<dim3(Ex/128, Kx/128), 256, GEMM_SMEM>>>(
        pos_h, nullptr, 0, wr_t, nullptr, rb, Ex, Ex);
    // 2b) V transpose
    vtrans<<<dim3(Kx/32, Ex/32, Bx), dim3(32,8)>>>(qkv, vt);
    // 3) flash attention (double-buffered key groups)
    flash<<<dim3(Sx/64, Bx*Hx), 256, FLASH_SMEM>>>(qkv, rb, vt, u, v, attn);
    // 4) attn @ Wo
    tgemm<0,false,false><<<dim3(Ex/128, ROWS/128), 256, GEMM_SMEM>>>(
        attn, nullptr, 0, wo_t, nullptr, tmp, Ex, Ex);
    // 5) attn_out = LN(inputDec + attnWo)
    ln_add_kernel<<<ROWS, 128>>>(inputDec, tmp, ln1_g, ln1_b, attnout, attnout_h);
    // 6) ff1 = relu(attn_out @ W1 + b1)
    tgemm<2,false,true><<<dim3(FFx/128, ROWS/128), 256, GEMM_SMEM>>>(
        attnout_h, nullptr, 0, w1_t, b1, ff1, FFx, Ex);
    // 7) ff2 = ff1 @ W2 + b2
    tgemm<1,false,false><<<dim3(Ex/128, ROWS/128), 256, GEMM_SMEM>>>(
        ff1, nullptr, 0, w2_t, b2, ff2, Ex, FFx);
    // 8) out = LN(attn_out + ff2)
    ln_add_kernel<<<ROWS, 128>>>(attnout, ff2, ln2_g, ln2_b, out, nullptr);
}

// round 13
// speedup vs baseline: 14.1983x; 1.0448x over previous
#include <cuda_runtime.h>
#include <cuda_fp16.h>
#include <cstdint>

#define Sx 2048
#define Bx 2
#define Ex 512
#define Hx 8
#define Mx 2048
#define Kx 4096          // M + S
#define QKV3 1536
#define FFx 2048
#define ROWS (Sx*Bx)     // 4096
#define KB_ (Kx*Bx)      // 8192
#define EPSF 1e-5f
#define SCL 0.18033688f  // 0.125 * log2(e): softmax in base-2 domain

// ---------------- scratch (static device arrays: no allocation) -------------
__device__ __align__(128) __half g_qkv[(size_t)KB_ * QKV3];
__device__ __align__(128) __half g_rb[(size_t)Kx * Ex];
__device__ __align__(128) __half g_vt[(size_t)Bx * Ex * Kx];
__device__ __align__(128) __half g_qu[(size_t)ROWS * Ex];
__device__ __align__(128) __half g_qv[(size_t)ROWS * Ex];
__device__ __align__(128) __half g_attn[(size_t)ROWS * Ex];
__device__ __align__(128) float  g_tmp[(size_t)2 * ROWS * Ex];   // 2 split-K partials
__device__ __align__(128) float  g_attnout[(size_t)ROWS * Ex];
__device__ __align__(128) __half g_attnout_h[(size_t)ROWS * Ex];
__device__ __align__(128) __half g_ff1[(size_t)ROWS * FFx];
__device__ __align__(128) float  g_ff2[(size_t)2 * ROWS * Ex];   // 2 split-K partials
__device__ __align__(128) __half g_mem_h[(size_t)Mx * Bx * Ex];
__device__ __align__(128) __half g_inp_h[(size_t)Sx * Bx * Ex];
__device__ __align__(128) __half g_pos_h[(size_t)Kx * Ex];
__device__ __align__(128) __half g_wqkv_t[(size_t)QKV3 * Ex];
__device__ __align__(128) __half g_wr_t[(size_t)Ex * Ex];
__device__ __align__(128) __half g_wo_t[(size_t)Ex * Ex];
__device__ __align__(128) __half g_w1_t[(size_t)FFx * Ex];
__device__ __align__(128) __half g_w2_t[(size_t)Ex * FFx];

// ---------------- helpers ---------------------------------------------------
__device__ __forceinline__ void mma16(float* d, const unsigned* a, const unsigned* b) {
    asm volatile(
        "mma.sync.aligned.m16n8k16.row.col.f32.f16.f16.f32 "
        "{%0,%1,%2,%3},{%4,%5,%6,%7},{%8,%9},{%0,%1,%2,%3};\n"
        : "+f"(d[0]), "+f"(d[1]), "+f"(d[2]), "+f"(d[3])
        : "r"(a[0]), "r"(a[1]), "r"(a[2]), "r"(a[3]), "r"(b[0]), "r"(b[1]));
}
__device__ __forceinline__ void ldmx4(unsigned* r, unsigned a) {
    asm volatile("ldmatrix.sync.aligned.m8n8.x4.shared.b16 {%0,%1,%2,%3}, [%4];"
        : "=r"(r[0]), "=r"(r[1]), "=r"(r[2]), "=r"(r[3]) : "r"(a));
}
__device__ __forceinline__ float ex2f(float x) {
    float r; asm("ex2.approx.f32 %0, %1;" : "=f"(r) : "f"(x)); return r;
}
__device__ __forceinline__ unsigned sptr(const void* p) {
    return (unsigned)__cvta_generic_to_shared(p);
}
__device__ __forceinline__ void cpa16(unsigned d, const void* s) {
    asm volatile("cp.async.cg.shared.global [%0], [%1], 16;\n" :: "r"(d), "l"(s));
}
__device__ __forceinline__ void cpcommit() { asm volatile("cp.async.commit_group;\n"); }
template<int N> __device__ __forceinline__ void cpwait() {
    asm volatile("cp.async.wait_group %0;\n" :: "n"(N));
}
__device__ __forceinline__ void barg(int id) {
    asm volatile("bar.sync %0, 128;" :: "r"(id) : "memory");
}
__device__ __forceinline__ unsigned packh2(float a, float b) {
    __half2 h = __floats2half2_rn(a, b);
    return *(unsigned*)&h;
}

// ---------------- fp32 -> fp16 conversion, 3 segments in one launch ---------
struct CSegs { const float4* src[3]; uint2* dst[3]; int n4[3]; };
__global__ void cvtall(CSegs segs) {
    int seg = blockIdx.y;
    int i = blockIdx.x * 256 + threadIdx.x;
    if (i < segs.n4[seg]) {
        float4 v = segs.src[seg][i];
        __half2 h01 = __floats2half2_rn(v.x, v.y);
        __half2 h23 = __floats2half2_rn(v.z, v.w);
        segs.dst[seg][i] = make_uint2(*(unsigned*)&h01, *(unsigned*)&h23);
    }
}

// ------- weight transpose + fp16 convert, ALL 5 weights, one launch ---------
struct TSegs { const float* W[5]; __half* Wt[5]; int K[5], N[5], tilesN[5], cum[6]; };
__global__ void transw_all(TSegs s) {
    int bid = blockIdx.x;
    int seg = 0;
#pragma unroll
    for (int i = 0; i < 5; i++) if (bid >= s.cum[i + 1]) seg = i + 1;
    int lt = bid - s.cum[seg];
    int K = s.K[seg], N = s.N[seg];
    int n0 = (lt % s.tilesN[seg]) * 32, k0 = (lt / s.tilesN[seg]) * 32;
    const float* W = s.W[seg];
    __half* Wt = s.Wt[seg];
    __shared__ float t[32][33];
    int tx = threadIdx.x, ty = threadIdx.y;   // 32 x 8
#pragma unroll
    for (int j = 0; j < 4; j++)
        t[ty + j * 8][tx] = W[(size_t)(k0 + ty + j * 8) * N + n0 + tx];
    __syncthreads();
#pragma unroll
    for (int j = 0; j < 4; j++)
        Wt[(size_t)(n0 + ty + j * 8) * K + k0 + tx] = __float2half_rn(t[tx][ty + j * 8]);
}

// ---------------- V transpose: vt[b*512+c][key] = qkv_V[key][b][c] ----------
__global__ void vtrans(const __half* __restrict__ qkv, __half* __restrict__ vt) {
    __shared__ __half t[32][40];
    int b = blockIdx.z;
    int key0 = blockIdx.x * 32, c0 = blockIdx.y * 32;
    int tx = threadIdx.x, ty = threadIdx.y;   // 32 x 8
#pragma unroll
    for (int j = 0; j < 4; j++)
        t[ty + j * 8][tx] =
            qkv[((size_t)(key0 + ty + j * 8) * Bx + b) * QKV3 + 1024 + c0 + tx];
    __syncthreads();
#pragma unroll
    for (int j = 0; j < 4; j++)
        vt[((size_t)(b * Ex + c0 + ty + j * 8)) * Kx + key0 + tx] = t[tx][ty + j * 8];
}

// ---------------- Q prep: qu/qv = fp16(q + u/v), coalesced -------------------
__global__ void qprep(const __half* __restrict__ qkv,
                      const float* __restrict__ u, const float* __restrict__ v,
                      __half* __restrict__ qu, __half* __restrict__ qv) {
    int row = blockIdx.x;            // s*Bx + b
    int c = threadIdx.x * 2;         // 256 threads x 2 halfs
    __half2 q = *(const __half2*)(qkv + ((size_t)(Mx * Bx) + row) * QKV3 + c);
    float qx = __half2float(q.x), qy = __half2float(q.y);
    float2 uu = *(const float2*)(u + c);
    float2 vv = *(const float2*)(v + c);
    *(__half2*)(qu + (size_t)row * Ex + c) = __floats2half2_rn(qx + uu.x, qy + uu.y);
    *(__half2*)(qv + (size_t)row * Ex + c) = __floats2half2_rn(qx + vv.x, qy + vv.y);
}

// ------- FP16 GEMM: C(MxN)=A(MxK)*Bt(NxK)^T, 128x128x32, 4-stage pipe ------
// Split-K: blockIdx.z selects K-chunk [z*kLen, (z+1)*kLen); each z writes its
// own output buffer at Cv + z*coffBytes. Bias applied only by z==0.
#define AH 40
#define GSTG 4
#define GBUF (128*AH*2)          // bytes per operand per stage
#define GEMM_SMEM (2*GSTG*GBUF)  // A stages + B stages

template<int EPI, bool SPLITA, bool OUTH>
__global__ __launch_bounds__(256, 2) void tgemm(
    const __half* __restrict__ A0, const __half* __restrict__ A1, int splitRow,
    const __half* __restrict__ Bt, const float* __restrict__ bias,
    void* __restrict__ Cv, int Nd, int Kd, int kLen, size_t coffBytes)
{
    extern __shared__ __align__(16) __half sh[];
    __half* As = sh;                      // [GSTG][128][AH]
    __half* Bs = sh + GSTG * 128 * AH;    // [GSTG][128][AH]
    const int tid = threadIdx.x, lane = tid & 31, wid = tid >> 5;
    const int wm = wid >> 2, wn = wid & 3, g = lane >> 2, t = lane & 3;
    const int bm = blockIdx.y * 128, bn = blockIdx.x * 128;
    const int kOff = blockIdx.z * kLen;
    const bool bz0 = (blockIdx.z == 0);
    char* Cb = (char*)Cv + (size_t)blockIdx.z * coffBytes;

    const __half* asrc[2]; const __half* bsrc[2];
    unsigned adst[2], bdst[2];
#pragma unroll
    for (int p = 0; p < 2; p++) {
        int id = tid + p * 256;
        int r = id >> 2, c8 = (id & 3) * 8;
        int grow = bm + r;
        const __half* abase = (SPLITA && grow >= splitRow)
                              ? (A1 + (size_t)(grow - splitRow) * Kd)
                              : (A0 + (size_t)grow * Kd);
        asrc[p] = abase + kOff + c8;
        adst[p] = sptr(As + r * AH + c8);
        bsrc[p] = Bt + (size_t)(bn + r) * Kd + kOff + c8;
        bdst[p] = sptr(Bs + r * AH + c8);
    }

    // ldmatrix lane constants
    const int r_in = lane & 7;
    const int a_row8 = ((lane >> 3) & 1) * 8;
    const int a_k8 = (lane >> 4) * 8;
    const int b_nf8 = (lane >> 4) * 8;
    const int b_k8 = ((lane >> 3) & 1) * 8;
    const unsigned aAddr0 = sptr(As + (wm * 64 + r_in + a_row8) * AH + a_k8);
    const unsigned bAddr0 = sptr(Bs + (wn * 32 + b_nf8 + r_in) * AH + b_k8);

    float acc[4][4][4];
#pragma unroll
    for (int i = 0; i < 4; i++)
#pragma unroll
        for (int j = 0; j < 4; j++)
#pragma unroll
            for (int r = 0; r < 4; r++) acc[i][j][r] = 0.f;

    auto issue = [&](int stage) {
        unsigned off = (unsigned)(stage % GSTG) * GBUF;
        int k0 = stage << 5;
#pragma unroll
        for (int p = 0; p < 2; p++) {
            cpa16(adst[p] + off, asrc[p] + k0);
            cpa16(bdst[p] + off, bsrc[p] + k0);
        }
        cpcommit();
    };

    int nkt = kLen >> 5;   // >= 8 for all our shapes
#pragma unroll
    for (int s = 0; s < GSTG - 1; s++) issue(s);

    for (int kt = 0; kt < nkt; kt++) {
        cpwait<GSTG - 2>();
        __syncthreads();
        // prefetch into the buffer consumed at kt-1 (safe: barrier above)
        if (kt + GSTG - 1 < nkt) issue(kt + GSTG - 1);

        unsigned off = (unsigned)(kt % GSTG) * GBUF;
        unsigned aAddr = aAddr0 + off;
        unsigned bAddr = bAddr0 + off;
#pragma unroll
        for (int ks = 0; ks < 2; ks++) {
            unsigned a4[4][4], b4[2][4];
#pragma unroll
            for (int mf = 0; mf < 4; mf++)
                ldmx4(a4[mf], aAddr + mf * (16 * AH * 2) + ks * 32);
#pragma unroll
            for (int n2 = 0; n2 < 2; n2++)
                ldmx4(b4[n2], bAddr + n2 * (16 * AH * 2) + ks * 32);
#pragma unroll
            for (int mf = 0; mf < 4; mf++)
#pragma unroll
                for (int n2 = 0; n2 < 2; n2++) {
                    mma16(acc[mf][2 * n2],     a4[mf], b4[n2]);
                    mma16(acc[mf][2 * n2 + 1], a4[mf], b4[n2] + 2);
                }
        }
    }

#pragma unroll
    for (int mf = 0; mf < 4; mf++) {
        int r0 = bm + wm * 64 + mf * 16 + g;
#pragma unroll
        for (int nf = 0; nf < 4; nf++) {
            int c = bn + wn * 32 + nf * 8 + 2 * t;
            float v0 = acc[mf][nf][0], v1 = acc[mf][nf][1];
            float v2 = acc[mf][nf][2], v3 = acc[mf][nf][3];
            if (EPI >= 1 && bz0) {
                float b0 = bias[c], b1v = bias[c + 1];
                v0 += b0; v1 += b1v; v2 += b0; v3 += b1v;
            }
            if (EPI == 2) {
                v0 = fmaxf(v0, 0.f); v1 = fmaxf(v1, 0.f);
                v2 = fmaxf(v2, 0.f); v3 = fmaxf(v3, 0.f);
            }
            if (OUTH) {
                __half* C = (__half*)Cb;
                *(__half2*)(C + (size_t)r0 * Nd + c)       = __floats2half2_rn(v0, v1);
                *(__half2*)(C + (size_t)(r0 + 8) * Nd + c) = __floats2half2_rn(v2, v3);
            } else {
                float* C = (float*)Cb;
                *(float2*)(C + (size_t)r0 * Nd + c)       = make_float2(v0, v1);
                *(float2*)(C + (size_t)(r0 + 8) * Nd + c) = make_float2(v2, v3);
            }
        }
    }
}

// ---------------- Flash attention: R12 core + cp.async Q prologue -----------
#define FST 72
#define BDW 84
#define OFF_QU 0
#define OFF_QV 9216
#define OFF_K  18432
#define OFF_V  55296
#define OFF_R  92160
#define OFF_BD 165888
#define FLASH_SMEM 208896
#define PRSTRIDE 2304      // 16 * FST * 2 bytes
#define KSTB 9216          // bytes per K/V stage buffer
#define RSTB 18432         // bytes per R stage buffer

__global__ __launch_bounds__(256, 1) void flash(
    const __half* __restrict__ qkv, const __half* __restrict__ rbuf,
    const __half* __restrict__ vt,
    const __half* __restrict__ qu_g, const __half* __restrict__ qv_g,
    __half* __restrict__ attn)
{
    extern __shared__ __align__(16) char smc[];
    __half* Qu = (__half*)(smc + OFF_QU);
    __half* Qv = (__half*)(smc + OFF_QV);
    __half* Ks = (__half*)(smc + OFF_K);
    __half* Vs = (__half*)(smc + OFF_V);
    __half* Rs = (__half*)(smc + OFF_R);
    float*  BDb = (float*)(smc + OFF_BD);
    const int tid = threadIdx.x, lane = tid & 31, wid = tid >> 5;
    const int g = lane >> 2, t = lane & 3;
    const int gr = wid >> 2, wg = wid & 3;
    const int gtid = tid & 127;
    const int qt = (gridDim.x - 1) - blockIdx.x;
    const int b = blockIdx.y >> 3, h = blockIdx.y & 7;
    const int s0 = qt * 64, hoff = h * 64;
    const int nkt = qt + 33;

    auto issue = [&](int kt, int st) {
        int k0 = kt * 64;
        int slot = gr * 2 + st;
#pragma unroll
        for (int p = 0; p < 4; p++) {
            int id = gtid + p * 128;
            int row = id >> 3, c = (id & 7) * 8;
            const __half* ksrc = qkv + ((size_t)(k0 + row) * Bx + b) * QKV3 + 512 + hoff + c;
            cpa16(sptr(Ks + slot * 64 * FST + row * FST + c), ksrc);
            cpa16(sptr(Vs + slot * 64 * FST + row * FST + c),
                  vt + ((size_t)(b * Ex + hoff + row)) * Kx + k0 + c);
        }
        int jlo = k0 + (Sx - 1) - s0 - 63;
#pragma unroll
        for (int p = 0; p < 8; p++) {
            int id = gtid + p * 128;
            int d = id >> 3, c = (id & 7) * 8;
            int j = jlo + d; if (j > Kx - 1) j = Kx - 1;   // clamped cells are masked
            cpa16(sptr(Rs + slot * 128 * FST + d * FST + c), rbuf + (size_t)j * Ex + hoff + c);
        }
        cpcommit();
    };

    // Q tiles via cp.async (group Q), then per-group stage prefetches
#pragma unroll
    for (int p = 0; p < 2; p++) {
        int id = tid + p * 256;
        int row = id >> 3, c = (id & 7) * 8;
        size_t src = ((size_t)(s0 + row) * Bx + b) * Ex + hoff + c;
        cpa16(sptr(Qu + row * FST + c), qu_g + src);
        cpa16(sptr(Qv + row * FST + c), qv_g + src);
    }
    cpcommit();
    issue(gr, 0);
    issue(gr + 2, 1);    // nkt >= 33 always
    cpwait<2>();         // retire Q group
    __syncthreads();

    float m0 = -1e30f, m1 = -1e30f, l0 = 0.f, l1 = 0.f;
    float O[8][4];
#pragma unroll
    for (int i = 0; i < 8; i++)
#pragma unroll
        for (int j = 0; j < 4; j++) O[i][j] = 0.f;

    float* BDrow = BDb + (wid * 16 + g) * BDW;
    const int c_base = 48 - wg * 16;

    const int r_in = lane & 7;
    const int a_row8 = ((lane >> 3) & 1) * 8;
    const int a_k8 = (lane >> 4) * 8;
    const int b_nf8 = (lane >> 4) * 8;
    const int b_k8 = ((lane >> 3) & 1) * 8;
    const unsigned qu_a = sptr(Qu + (wg * 16 + r_in + a_row8) * FST + a_k8);
    const unsigned qv_a = sptr(Qv + (wg * 16 + r_in + a_row8) * FST + a_k8);
    const unsigned k_b0 = sptr(Ks + (gr * 2) * 64 * FST + (b_nf8 + r_in) * FST + b_k8);
    const unsigned r_b0 = sptr(Rs + (gr * 2) * 128 * FST + (c_base + b_nf8 + r_in) * FST + b_k8);
    const unsigned v_b0 = sptr(Vs + (gr * 2) * 64 * FST + (b_nf8 + r_in) * FST + b_k8);

    int st = 0;
    for (int kt = gr; kt < nkt; kt += 2, st ^= 1) {
        int k0 = kt * 64;
        if (kt + 2 < nkt) cpwait<1>(); else cpwait<0>();
        barg(gr + 1);
        const unsigned k_b = k_b0 + st * KSTB;
        const unsigned r_b = r_b0 + st * RSTB;
        const unsigned v_b = v_b0 + st * KSTB;

        // ---- BD band mma: 16 x 80 per warp -> fp32 smem
        {
            float bd[10][4];
#pragma unroll
            for (int nf = 0; nf < 10; nf++)
#pragma unroll
                for (int j = 0; j < 4; j++) bd[nf][j] = 0.f;
#pragma unroll
            for (int ks = 0; ks < 4; ks++) {
                unsigned a[4];
                ldmx4(a, qv_a + ks * 32);
#pragma unroll
                for (int pr = 0; pr < 5; pr++) {
                    unsigned bb[4];
                    ldmx4(bb, r_b + pr * PRSTRIDE + ks * 32);
                    mma16(bd[2 * pr],     a, bb);
                    mma16(bd[2 * pr + 1], a, bb + 2);
                }
            }
#pragma unroll
            for (int nf = 0; nf < 10; nf++) {
                *(float2*)(BDrow + nf * 8 + 2 * t) = make_float2(bd[nf][0], bd[nf][1]);
                *(float2*)(BDrow + 8 * BDW + nf * 8 + 2 * t) = make_float2(bd[nf][2], bd[nf][3]);
            }
        }
        __syncwarp();

        // ---- AC mma: 16 x 64 per warp
        float ac[8][4];
#pragma unroll
        for (int nf = 0; nf < 8; nf++)
#pragma unroll
            for (int j = 0; j < 4; j++) ac[nf][j] = 0.f;
#pragma unroll
        for (int ks = 0; ks < 4; ks++) {
            unsigned a[4];
            ldmx4(a, qu_a + ks * 32);
#pragma unroll
            for (int pr = 0; pr < 4; pr++) {
                unsigned bb[4];
                ldmx4(bb, k_b + pr * PRSTRIDE + ks * 32);
                mma16(ac[2 * pr],     a, bb);
                mma16(ac[2 * pr + 1], a, bb + 2);
            }
        }

        // ---- combine with BD diagonal + mask; scale into base-2 domain
        {
            int lim0 = s0 + wg * 16 + g + Mx, lim1 = lim0 + 8;
#pragma unroll
            for (int nf = 0; nf < 8; nf++) {
                int kc = nf * 8 + 2 * t;
                float v0 = (ac[nf][0] + BDrow[kc + 15 - g]) * SCL;
                float v1 = (ac[nf][1] + BDrow[kc + 16 - g]) * SCL;
                float v2 = (ac[nf][2] + BDrow[8 * BDW + kc + 7 - g]) * SCL;
                float v3 = (ac[nf][3] + BDrow[8 * BDW + kc + 8 - g]) * SCL;
                if (k0 + kc > lim0)     v0 = -1e30f;
                if (k0 + kc + 1 > lim0) v1 = -1e30f;
                if (k0 + kc > lim1)     v2 = -1e30f;
                if (k0 + kc + 1 > lim1) v3 = -1e30f;
                ac[nf][0] = v0; ac[nf][1] = v1; ac[nf][2] = v2; ac[nf][3] = v3;
            }
        }

        // ---- online softmax (base-2); P packed directly into A-fragments
        unsigned pk0[8], pk1[8];
        {
            float mx0 = -1e30f, mx1 = -1e30f;
#pragma unroll
            for (int nf = 0; nf < 8; nf++) {
                mx0 = fmaxf(mx0, fmaxf(ac[nf][0], ac[nf][1]));
                mx1 = fmaxf(mx1, fmaxf(ac[nf][2], ac[nf][3]));
            }
            mx0 = fmaxf(mx0, __shfl_xor_sync(0xffffffffu, mx0, 1));
            mx0 = fmaxf(mx0, __shfl_xor_sync(0xffffffffu, mx0, 2));
            mx1 = fmaxf(mx1, __shfl_xor_sync(0xffffffffu, mx1, 1));
            mx1 = fmaxf(mx1, __shfl_xor_sync(0xffffffffu, mx1, 2));
            float mn0 = fmaxf(m0, mx0), mn1 = fmaxf(m1, mx1);
            float c0 = ex2f(m0 - mn0), c1 = ex2f(m1 - mn1);
            float rs0 = 0.f, rs1 = 0.f;
#pragma unroll
            for (int nf = 0; nf < 8; nf++) {
                float p0 = ex2f(ac[nf][0] - mn0);
                float p1 = ex2f(ac[nf][1] - mn0);
                float p2 = ex2f(ac[nf][2] - mn1);
                float p3 = ex2f(ac[nf][3] - mn1);
                rs0 += p0 + p1; rs1 += p2 + p3;
                pk0[nf] = packh2(p0, p1);
                pk1[nf] = packh2(p2, p3);
            }
            rs0 += __shfl_xor_sync(0xffffffffu, rs0, 1);
            rs0 += __shfl_xor_sync(0xffffffffu, rs0, 2);
            rs1 += __shfl_xor_sync(0xffffffffu, rs1, 1);
            rs1 += __shfl_xor_sync(0xffffffffu, rs1, 2);
            l0 = l0 * c0 + rs0; l1 = l1 * c1 + rs1;
            m0 = mn0; m1 = mn1;
#pragma unroll
            for (int nf = 0; nf < 8; nf++) {
                O[nf][0] *= c0; O[nf][1] *= c0; O[nf][2] *= c1; O[nf][3] *= c1;
            }
        }

        // ---- P·V mma: A = P straight from registers (C-frag == A-frag)
#pragma unroll
        for (int ks = 0; ks < 4; ks++) {
            unsigned a[4] = {pk0[2 * ks], pk1[2 * ks], pk0[2 * ks + 1], pk1[2 * ks + 1]};
#pragma unroll
            for (int pr = 0; pr < 4; pr++) {
                unsigned bb[4];
                ldmx4(bb, v_b + pr * PRSTRIDE + ks * 32);
                mma16(O[2 * pr],     a, bb);
                mma16(O[2 * pr + 1], a, bb + 2);
            }
        }

        barg(gr + 1);   // group done reading stage st before it is refilled
        if (kt + 4 < nkt) issue(kt + 4, st);
    }

    // ---- merge the two groups' partial softmax states, write output --------
    __syncthreads();
    if (wid >= 4) {
#pragma unroll
        for (int nf = 0; nf < 8; nf++) {
            *(float2*)(BDrow + nf * 8 + 2 * t) = make_float2(O[nf][0], O[nf][1]);
            *(float2*)(BDrow + 8 * BDW + nf * 8 + 2 * t) = make_float2(O[nf][2], O[nf][3]);
        }
        if (t == 0) {
            BDrow[80] = m0; BDrow[81] = l0;
            BDrow[8 * BDW + 80] = m1; BDrow[8 * BDW + 81] = l1;
        }
    }
    __syncthreads();
    if (wid < 4) {
        const float* Peer = BDb + ((wid + 4) * 16 + g) * BDW;
        float pm0 = Peer[80], pl0 = Peer[81];
        float pm1 = Peer[8 * BDW + 80], pl1 = Peer[8 * BDW + 81];
        float M0 = fmaxf(m0, pm0), M1 = fmaxf(m1, pm1);
        float a0 = ex2f(m0 - M0), e0 = ex2f(pm0 - M0);
        float a1 = ex2f(m1 - M1), e1 = ex2f(pm1 - M1);
        float i0 = 1.0f / (l0 * a0 + pl0 * e0);
        float i1 = 1.0f / (l1 * a1 + pl1 * e1);
        int sg0 = s0 + wid * 16 + g;
#pragma unroll
        for (int nf = 0; nf < 8; nf++) {
            int c = hoff + nf * 8 + 2 * t;
            float2 po0 = *(const float2*)(Peer + nf * 8 + 2 * t);
            float2 po1 = *(const float2*)(Peer + 8 * BDW + nf * 8 + 2 * t);
            *(__half2*)(attn + ((size_t)sg0 * Bx + b) * Ex + c) =
                __floats2half2_rn((O[nf][0] * a0 + po0.x * e0) * i0,
                                  (O[nf][1] * a0 + po0.y * e0) * i0);
            *(__half2*)(attn + ((size_t)(sg0 + 8) * Bx + b) * Ex + c) =
                __floats2half2_rn((O[nf][2] * a1 + po1.x * e1) * i1,
                                  (O[nf][3] * a1 + po1.y * e1) * i1);
        }
    }
}

// -------- LayerNorm(X + Y [+ Y2]); optional fp16 second copy ----------------
__global__ void ln_add_kernel(const float* __restrict__ X, const float* __restrict__ Y,
                              const float* __restrict__ Y2,
                              const float* __restrict__ g, const float* __restrict__ bb,
                              float* __restrict__ out, __half* __restrict__ out_h)
{
    __shared__ float red[4];
    int row = blockIdx.x;
    int tid = threadIdx.x;
    const float4* X4 = (const float4*)(X + (size_t)row * Ex);
    const float4* Y4 = (const float4*)(Y + (size_t)row * Ex);
    float4 x = X4[tid], y = Y4[tid];
    float4 vv = {x.x + y.x, x.y + y.y, x.z + y.z, x.w + y.w};
    if (Y2) {
        float4 y2 = ((const float4*)(Y2 + (size_t)row * Ex))[tid];
        vv.x += y2.x; vv.y += y2.y; vv.z += y2.z; vv.w += y2.w;
    }
    float s = vv.x + vv.y + vv.z + vv.w;
#pragma unroll
    for (int off = 16; off; off >>= 1) s += __shfl_xor_sync(0xffffffffu, s, off);
    if ((tid & 31) == 0) red[tid >> 5] = s;
    __syncthreads();
    float mu = (red[0] + red[1] + red[2] + red[3]) * (1.f / 512.f);
    float d0 = vv.x - mu, d1 = vv.y - mu, d2 = vv.z - mu, d3 = vv.w - mu;
    float q = d0 * d0 + d1 * d1 + d2 * d2 + d3 * d3;
    __syncthreads();
#pragma unroll
    for (int off = 16; off; off >>= 1) q += __shfl_xor_sync(0xffffffffu, q, off);
    if ((tid & 31) == 0) red[tid >> 5] = q;
    __syncthreads();
    float var = (red[0] + red[1] + red[2] + red[3]) * (1.f / 512.f);
    float rs = rsqrtf(var + EPSF);
    float4 gg = ((const float4*)g)[tid], bv = ((const float4*)bb)[tid];
    float4 o;
    o.x = d0 * rs * gg.x + bv.x;
    o.y = d1 * rs * gg.y + bv.y;
    o.z = d2 * rs * gg.z + bv.z;
    o.w = d3 * rs * gg.w + bv.w;
    ((float4*)(out + (size_t)row * Ex))[tid] = o;
    if (out_h) {
        __half2* oh = (__half2*)(out_h + (size_t)row * Ex);
        oh[tid * 2]     = __floats2half2_rn(o.x, o.y);
        oh[tid * 2 + 1] = __floats2half2_rn(o.z, o.w);
    }
}

// ---------------------------------------------------------------------------
extern "C" void kernel_launch(void* const* d_in, const int* in_sizes, int n_in,
                              void* d_out, int out_size)
{
    const float* inputDec = (const float*)d_in[0];
    const float* posEmb   = (const float*)d_in[1];
    const float* u        = (const float*)d_in[2];
    const float* v        = (const float*)d_in[3];
    const float* memories = (const float*)d_in[4];
    const float* Wqkv     = (const float*)d_in[5];
    const float* Wr       = (const float*)d_in[6];
    const float* Wo       = (const float*)d_in[7];
    const float* ln1_g    = (const float*)d_in[8];
    const float* ln1_b    = (const float*)d_in[9];
    const float* W1       = (const float*)d_in[10];
    const float* b1       = (const float*)d_in[11];
    const float* W2       = (const float*)d_in[12];
    const float* b2       = (const float*)d_in[13];
    const float* ln2_g    = (const float*)d_in[14];
    const float* ln2_b    = (const float*)d_in[15];
    float* out = (float*)d_out;

    __half *qkv, *rb, *vt, *qu, *qv, *attn, *attnout_h, *ff1;
    __half *mem_h, *inp_h, *pos_h, *wqkv_t, *wr_t, *wo_t, *w1_t, *w2_t;
    float *tmp, *attnout, *ff2;
    cudaGetSymbolAddress((void**)&qkv,       g_qkv);
    cudaGetSymbolAddress((void**)&rb,        g_rb);
    cudaGetSymbolAddress((void**)&vt,        g_vt);
    cudaGetSymbolAddress((void**)&qu,        g_qu);
    cudaGetSymbolAddress((void**)&qv,        g_qv);
    cudaGetSymbolAddress((void**)&attn,      g_attn);
    cudaGetSymbolAddress((void**)&tmp,       g_tmp);
    cudaGetSymbolAddress((void**)&attnout,   g_attnout);
    cudaGetSymbolAddress((void**)&attnout_h, g_attnout_h);
    cudaGetSymbolAddress((void**)&ff1,       g_ff1);
    cudaGetSymbolAddress((void**)&ff2,       g_ff2);
    cudaGetSymbolAddress((void**)&mem_h,     g_mem_h);
    cudaGetSymbolAddress((void**)&inp_h,     g_inp_h);
    cudaGetSymbolAddress((void**)&pos_h,     g_pos_h);
    cudaGetSymbolAddress((void**)&wqkv_t,    g_wqkv_t);
    cudaGetSymbolAddress((void**)&wr_t,      g_wr_t);
    cudaGetSymbolAddress((void**)&wo_t,      g_wo_t);
    cudaGetSymbolAddress((void**)&w1_t,      g_w1_t);
    cudaGetSymbolAddress((void**)&w2_t,      g_w2_t);

    cudaFuncSetAttribute(flash, cudaFuncAttributeMaxDynamicSharedMemorySize, FLASH_SMEM);
    cudaFuncSetAttribute(tgemm<0,true,true>,   cudaFuncAttributeMaxDynamicSharedMemorySize, GEMM_SMEM);
    cudaFuncSetAttribute(tgemm<0,false,true>,  cudaFuncAttributeMaxDynamicSharedMemorySize, GEMM_SMEM);
    cudaFuncSetAttribute(tgemm<0,false,false>, cudaFuncAttributeMaxDynamicSharedMemorySize, GEMM_SMEM);
    cudaFuncSetAttribute(tgemm<2,false,true>,  cudaFuncAttributeMaxDynamicSharedMemorySize, GEMM_SMEM);
    cudaFuncSetAttribute(tgemm<1,false,false>, cudaFuncAttributeMaxDynamicSharedMemorySize, GEMM_SMEM);

    // 0a) activations fp32 -> fp16
    {
        CSegs cs;
        cs.src[0] = (const float4*)memories; cs.dst[0] = (uint2*)mem_h;
        cs.n4[0] = (int)((size_t)Mx * Bx * Ex / 4);
        cs.src[1] = (const float4*)inputDec; cs.dst[1] = (uint2*)inp_h;
        cs.n4[1] = (int)((size_t)Sx * Bx * Ex / 4);
        cs.src[2] = (const float4*)posEmb;   cs.dst[2] = (uint2*)pos_h;
        cs.n4[2] = (int)((size_t)Kx * Ex / 4);
        int maxb = 0;
        for (int i = 0; i < 3; i++) { int bl = (cs.n4[i] + 255) / 256; if (bl > maxb) maxb = bl; }
        cvtall<<<dim3(maxb, 3), 256>>>(cs);
    }
    // 0b) all 5 weight transposes in ONE launch
    {
        TSegs ts;
        const float* Ws[5] = {Wqkv, Wr, Wo, W1, W2};
        __half* Wts[5] = {wqkv_t, wr_t, wo_t, w1_t, w2_t};
        int Ks[5] = {Ex, Ex, Ex, Ex, FFx};
        int Ns[5] = {QKV3, Ex, Ex, FFx, Ex};
        int c = 0;
        ts.cum[0] = 0;
        for (int i = 0; i < 5; i++) {
            ts.W[i] = Ws[i]; ts.Wt[i] = Wts[i];
            ts.K[i] = Ks[i]; ts.N[i] = Ns[i];
            ts.tilesN[i] = Ns[i] / 32;
            c += (Ks[i] / 32) * (Ns[i] / 32);
            ts.cum[i + 1] = c;
        }
        transw_all<<<c, dim3(32, 8)>>>(ts);
    }

    const size_t HALF_OUT = (size_t)ROWS * Ex * sizeof(float);

    // 1) qkv GEMM
    tgemm<0,true,true><<<dim3(QKV3/128, KB_/128, 1), 256, GEMM_SMEM>>>(
        mem_h, inp_h, Mx * Bx, wqkv_t, nullptr, qkv, QKV3, Ex, Ex, 0);
    // 2) r GEMM
    tgemm<0,false,true><<<dim3(Ex/128, Kx/128, 1), 256, GEMM_SMEM>>>(
        pos_h, nullptr, 0, wr_t, nullptr, rb, Ex, Ex, Ex, 0);
    // 2b) V transpose + Q prep
    vtrans<<<dim3(Kx/32, Ex/32, Bx), dim3(32,8)>>>(qkv, vt);
    qprep<<<ROWS, 256>>>(qkv, u, v, qu, qv);
    // 3) flash attention
    flash<<<dim3(Sx/64, Bx*Hx), 256, FLASH_SMEM>>>(qkv, rb, vt, qu, qv, attn);
    // 4) attn @ Wo  (split-K x2 -> two partial buffers)
    tgemm<0,false,false><<<dim3(Ex/128, ROWS/128, 2), 256, GEMM_SMEM>>>(
        attn, nullptr, 0, wo_t, nullptr, tmp, Ex, Ex, Ex/2, HALF_OUT);
    // 5) attn_out = LN(inputDec + woA + woB)
    ln_add_kernel<<<ROWS, 128>>>(inputDec, tmp, tmp + (size_t)ROWS * Ex,
                                 ln1_g, ln1_b, attnout, attnout_h);
    // 6) ff1 = relu(attn_out @ W1 + b1)
    tgemm<2,false,true><<<dim3(FFx/128, ROWS/128, 1), 256, GEMM_SMEM>>>(
        attnout_h, nullptr, 0, w1_t, b1, ff1, FFx, Ex, Ex, 0);
    // 7) ff2 = ff1 @ W2 + b2  (split-K x2)
    tgemm<1,false,false><<<dim3(Ex/128, ROWS/128, 2), 256, GEMM_SMEM>>>(
        ff1, nullptr, 0, w2_t, b2, ff2, Ex, FFx, FFx/2, HALF_OUT);
    // 8) out = LN(attn_out + ff2A + ff2B)
    ln_add_kernel<<<ROWS, 128>>>(attnout, ff2, ff2 + (size_t)ROWS * Ex,
                                 ln2_g, ln2_b, out, nullptr);
}

// round 15
// speedup vs baseline: 14.7411x; 1.0382x over previous
#include <cuda_runtime.h>
#include <cuda_fp16.h>
#include <cstdint>

#define Sx 2048
#define Bx 2
#define Ex 512
#define Hx 8
#define Mx 2048
#define Kx 4096          // M + S
#define QKV3 1536
#define FFx 2048
#define ROWS (Sx*Bx)     // 4096
#define KB_ (Kx*Bx)      // 8192
#define EPSF 1e-5f
#define SCL 0.18033688f  // 0.125 * log2(e): folded into Q at prep time

// ---------------- scratch (static device arrays: no allocation) -------------
__device__ __align__(128) __half g_qkv[(size_t)KB_ * QKV3];
__device__ __align__(128) __half g_rb[(size_t)Kx * Ex];
__device__ __align__(128) __half g_vt[(size_t)Bx * Ex * Kx];
__device__ __align__(128) __half g_qu[(size_t)ROWS * Ex];
__device__ __align__(128) __half g_qv[(size_t)ROWS * Ex];
__device__ __align__(128) __half g_attn[(size_t)ROWS * Ex];
__device__ __align__(128) float  g_tmp[(size_t)2 * ROWS * Ex];   // 2 split-K partials
__device__ __align__(128) float  g_attnout[(size_t)ROWS * Ex];
__device__ __align__(128) __half g_attnout_h[(size_t)ROWS * Ex];
__device__ __align__(128) __half g_ff1[(size_t)ROWS * FFx];
__device__ __align__(128) float  g_ff2[(size_t)2 * ROWS * Ex];   // 2 split-K partials
__device__ __align__(128) __half g_mem_h[(size_t)Mx * Bx * Ex];
__device__ __align__(128) __half g_inp_h[(size_t)Sx * Bx * Ex];
__device__ __align__(128) __half g_pos_h[(size_t)Kx * Ex];
__device__ __align__(128) __half g_wqkv_t[(size_t)QKV3 * Ex];
__device__ __align__(128) __half g_wr_t[(size_t)Ex * Ex];
__device__ __align__(128) __half g_wo_t[(size_t)Ex * Ex];
__device__ __align__(128) __half g_w1_t[(size_t)FFx * Ex];
__device__ __align__(128) __half g_w2_t[(size_t)Ex * FFx];

// ---------------- helpers ---------------------------------------------------
__device__ __forceinline__ void mma16(float* d, const unsigned* a, const unsigned* b) {
    asm volatile(
        "mma.sync.aligned.m16n8k16.row.col.f32.f16.f16.f32 "
        "{%0,%1,%2,%3},{%4,%5,%6,%7},{%8,%9},{%0,%1,%2,%3};\n"
        : "+f"(d[0]), "+f"(d[1]), "+f"(d[2]), "+f"(d[3])
        : "r"(a[0]), "r"(a[1]), "r"(a[2]), "r"(a[3]), "r"(b[0]), "r"(b[1]));
}
__device__ __forceinline__ void ldmx4(unsigned* r, unsigned a) {
    asm volatile("ldmatrix.sync.aligned.m8n8.x4.shared.b16 {%0,%1,%2,%3}, [%4];"
        : "=r"(r[0]), "=r"(r[1]), "=r"(r[2]), "=r"(r[3]) : "r"(a));
}
__device__ __forceinline__ float ex2f(float x) {
    float r; asm("ex2.approx.f32 %0, %1;" : "=f"(r) : "f"(x)); return r;
}
__device__ __forceinline__ unsigned sptr(const void* p) {
    return (unsigned)__cvta_generic_to_shared(p);
}
__device__ __forceinline__ void cpa16(unsigned d, const void* s) {
    asm volatile("cp.async.cg.shared.global [%0], [%1], 16;\n" :: "r"(d), "l"(s));
}
__device__ __forceinline__ void cpcommit() { asm volatile("cp.async.commit_group;\n"); }
template<int N> __device__ __forceinline__ void cpwait() {
    asm volatile("cp.async.wait_group %0;\n" :: "n"(N));
}
__device__ __forceinline__ void barg(int id) {
    asm volatile("bar.sync %0, 128;" :: "r"(id) : "memory");
}
__device__ __forceinline__ unsigned packh2(float a, float b) {
    __half2 h = __floats2half2_rn(a, b);
    return *(unsigned*)&h;
}

// ---------------- fp32 -> fp16 conversion, 3 segments in one launch ---------
struct CSegs { const float4* src[3]; uint2* dst[3]; int n4[3]; };
__global__ void cvtall(CSegs segs) {
    int seg = blockIdx.y;
    int i = blockIdx.x * 256 + threadIdx.x;
    if (i < segs.n4[seg]) {
        float4 v = segs.src[seg][i];
        __half2 h01 = __floats2half2_rn(v.x, v.y);
        __half2 h23 = __floats2half2_rn(v.z, v.w);
        segs.dst[seg][i] = make_uint2(*(unsigned*)&h01, *(unsigned*)&h23);
    }
}

// ------- weight transpose + fp16 convert, ALL 5 weights, one launch ---------
struct TSegs { const float* W[5]; __half* Wt[5]; int K[5], N[5], tilesN[5], cum[6]; };
__global__ void transw_all(TSegs s) {
    int bid = blockIdx.x;
    int seg = 0;
#pragma unroll
    for (int i = 0; i < 5; i++) if (bid >= s.cum[i + 1]) seg = i + 1;
    int lt = bid - s.cum[seg];
    int K = s.K[seg], N = s.N[seg];
    int n0 = (lt % s.tilesN[seg]) * 32, k0 = (lt / s.tilesN[seg]) * 32;
    const float* W = s.W[seg];
    __half* Wt = s.Wt[seg];
    __shared__ float t[32][33];
    int tx = threadIdx.x, ty = threadIdx.y;   // 32 x 8
#pragma unroll
    for (int j = 0; j < 4; j++)
        t[ty + j * 8][tx] = W[(size_t)(k0 + ty + j * 8) * N + n0 + tx];
    __syncthreads();
#pragma unroll
    for (int j = 0; j < 4; j++)
        Wt[(size_t)(n0 + ty + j * 8) * K + k0 + tx] = __float2half_rn(t[tx][ty + j * 8]);
}

// ---------------- V transpose: vt[b*512+c][key] = qkv_V[key][b][c] ----------
__global__ void vtrans(const __half* __restrict__ qkv, __half* __restrict__ vt) {
    __shared__ __half t[32][40];
    int b = blockIdx.z;
    int key0 = blockIdx.x * 32, c0 = blockIdx.y * 32;
    int tx = threadIdx.x, ty = threadIdx.y;   // 32 x 8
#pragma unroll
    for (int j = 0; j < 4; j++)
        t[ty + j * 8][tx] =
            qkv[((size_t)(key0 + ty + j * 8) * Bx + b) * QKV3 + 1024 + c0 + tx];
    __syncthreads();
#pragma unroll
    for (int j = 0; j < 4; j++)
        vt[((size_t)(b * Ex + c0 + ty + j * 8)) * Kx + key0 + tx] = t[tx][ty + j * 8];
}

// ------- Q prep: qu/qv = fp16((q + u/v) * SCL)  (softmax scale folded in) ---
__global__ void qprep(const __half* __restrict__ qkv,
                      const float* __restrict__ u, const float* __restrict__ v,
                      __half* __restrict__ qu, __half* __restrict__ qv) {
    int row = blockIdx.x;            // s*Bx + b
    int c = threadIdx.x * 2;         // 256 threads x 2 halfs
    __half2 q = *(const __half2*)(qkv + ((size_t)(Mx * Bx) + row) * QKV3 + c);
    float qx = __half2float(q.x), qy = __half2float(q.y);
    float2 uu = *(const float2*)(u + c);
    float2 vv = *(const float2*)(v + c);
    *(__half2*)(qu + (size_t)row * Ex + c) =
        __floats2half2_rn((qx + uu.x) * SCL, (qy + uu.y) * SCL);
    *(__half2*)(qv + (size_t)row * Ex + c) =
        __floats2half2_rn((qx + vv.x) * SCL, (qy + vv.y) * SCL);
}

// ------- FP16 GEMM: C(MxN)=A(MxK)*Bt(NxK)^T, 128x128x32, 4-stage pipe ------
// Split-K: blockIdx.z selects K-chunk [z*kLen, (z+1)*kLen); each z writes its
// own output buffer at Cv + z*coffBytes. Bias applied only by z==0.
#define AH 40
#define GSTG 4
#define GBUF (128*AH*2)          // bytes per operand per stage
#define GEMM_SMEM (2*GSTG*GBUF)  // A stages + B stages

template<int EPI, bool SPLITA, bool OUTH>
__global__ __launch_bounds__(256, 2) void tgemm(
    const __half* __restrict__ A0, const __half* __restrict__ A1, int splitRow,
    const __half* __restrict__ Bt, const float* __restrict__ bias,
    void* __restrict__ Cv, int Nd, int Kd, int kLen, size_t coffBytes)
{
    extern __shared__ __align__(16) __half sh[];
    __half* As = sh;                      // [GSTG][128][AH]
    __half* Bs = sh + GSTG * 128 * AH;    // [GSTG][128][AH]
    const int tid = threadIdx.x, lane = tid & 31, wid = tid >> 5;
    const int wm = wid >> 2, wn = wid & 3, g = lane >> 2, t = lane & 3;
    const int bm = blockIdx.y * 128, bn = blockIdx.x * 128;
    const int kOff = blockIdx.z * kLen;
    const bool bz0 = (blockIdx.z == 0);
    char* Cb = (char*)Cv + (size_t)blockIdx.z * coffBytes;

    const __half* asrc[2]; const __half* bsrc[2];
    unsigned adst[2], bdst[2];
#pragma unroll
    for (int p = 0; p < 2; p++) {
        int id = tid + p * 256;
        int r = id >> 2, c8 = (id & 3) * 8;
        int grow = bm + r;
        const __half* abase = (SPLITA && grow >= splitRow)
                              ? (A1 + (size_t)(grow - splitRow) * Kd)
                              : (A0 + (size_t)grow * Kd);
        asrc[p] = abase + kOff + c8;
        adst[p] = sptr(As + r * AH + c8);
        bsrc[p] = Bt + (size_t)(bn + r) * Kd + kOff + c8;
        bdst[p] = sptr(Bs + r * AH + c8);
    }

    // ldmatrix lane constants
    const int r_in = lane & 7;
    const int a_row8 = ((lane >> 3) & 1) * 8;
    const int a_k8 = (lane >> 4) * 8;
    const int b_nf8 = (lane >> 4) * 8;
    const int b_k8 = ((lane >> 3) & 1) * 8;
    const unsigned aAddr0 = sptr(As + (wm * 64 + r_in + a_row8) * AH + a_k8);
    const unsigned bAddr0 = sptr(Bs + (wn * 32 + b_nf8 + r_in) * AH + b_k8);

    float acc[4][4][4];
#pragma unroll
    for (int i = 0; i < 4; i++)
#pragma unroll
        for (int j = 0; j < 4; j++)
#pragma unroll
            for (int r = 0; r < 4; r++) acc[i][j][r] = 0.f;

    auto issue = [&](int stage) {
        unsigned off = (unsigned)(stage % GSTG) * GBUF;
        int k0 = stage << 5;
#pragma unroll
        for (int p = 0; p < 2; p++) {
            cpa16(adst[p] + off, asrc[p] + k0);
            cpa16(bdst[p] + off, bsrc[p] + k0);
        }
        cpcommit();
    };

    int nkt = kLen >> 5;   // >= 8 for all our shapes
#pragma unroll
    for (int s = 0; s < GSTG - 1; s++) issue(s);

    for (int kt = 0; kt < nkt; kt++) {
        cpwait<GSTG - 2>();
        __syncthreads();
        // prefetch into the buffer consumed at kt-1 (safe: barrier above)
        if (kt + GSTG - 1 < nkt) issue(kt + GSTG - 1);

        unsigned off = (unsigned)(kt % GSTG) * GBUF;
        unsigned aAddr = aAddr0 + off;
        unsigned bAddr = bAddr0 + off;
#pragma unroll
        for (int ks = 0; ks < 2; ks++) {
            unsigned a4[4][4], b4[2][4];
#pragma unroll
            for (int mf = 0; mf < 4; mf++)
                ldmx4(a4[mf], aAddr + mf * (16 * AH * 2) + ks * 32);
#pragma unroll
            for (int n2 = 0; n2 < 2; n2++)
                ldmx4(b4[n2], bAddr + n2 * (16 * AH * 2) + ks * 32);
#pragma unroll
            for (int mf = 0; mf < 4; mf++)
#pragma unroll
                for (int n2 = 0; n2 < 2; n2++) {
                    mma16(acc[mf][2 * n2],     a4[mf], b4[n2]);
                    mma16(acc[mf][2 * n2 + 1], a4[mf], b4[n2] + 2);
                }
        }
    }

#pragma unroll
    for (int mf = 0; mf < 4; mf++) {
        int r0 = bm + wm * 64 + mf * 16 + g;
#pragma unroll
        for (int nf = 0; nf < 4; nf++) {
            int c = bn + wn * 32 + nf * 8 + 2 * t;
            float v0 = acc[mf][nf][0], v1 = acc[mf][nf][1];
            float v2 = acc[mf][nf][2], v3 = acc[mf][nf][3];
            if (EPI >= 1 && bz0) {
                float b0 = bias[c], b1v = bias[c + 1];
                v0 += b0; v1 += b1v; v2 += b0; v3 += b1v;
            }
            if (EPI == 2) {
                v0 = fmaxf(v0, 0.f); v1 = fmaxf(v1, 0.f);
                v2 = fmaxf(v2, 0.f); v3 = fmaxf(v3, 0.f);
            }
            if (OUTH) {
                __half* C = (__half*)Cb;
                *(__half2*)(C + (size_t)r0 * Nd + c)       = __floats2half2_rn(v0, v1);
                *(__half2*)(C + (size_t)(r0 + 8) * Nd + c) = __floats2half2_rn(v2, v3);
            } else {
                float* C = (float*)Cb;
                *(float2*)(C + (size_t)r0 * Nd + c)       = make_float2(v0, v1);
                *(float2*)(C + (size_t)(r0 + 8) * Nd + c) = make_float2(v2, v3);
            }
        }
    }
}

// ---------------- Flash attention: R13 core, lean score epilogue ------------
// SCL pre-folded into Qu/Qv; AC accumulator seeded from the BD diagonal
// (combine is free); mask ops executed only on the warp-uniformly-guarded
// boundary tiles.
#define FST 72
#define BDW 84
#define OFF_QU 0
#define OFF_QV 9216
#define OFF_K  18432
#define OFF_V  55296
#define OFF_R  92160
#define OFF_BD 165888
#define FLASH_SMEM 208896
#define PRSTRIDE 2304      // 16 * FST * 2 bytes
#define KSTB 9216          // bytes per K/V stage buffer
#define RSTB 18432         // bytes per R stage buffer

__global__ __launch_bounds__(256, 1) void flash(
    const __half* __restrict__ qkv, const __half* __restrict__ rbuf,
    const __half* __restrict__ vt,
    const __half* __restrict__ qu_g, const __half* __restrict__ qv_g,
    __half* __restrict__ attn)
{
    extern __shared__ __align__(16) char smc[];
    __half* Qu = (__half*)(smc + OFF_QU);
    __half* Qv = (__half*)(smc + OFF_QV);
    __half* Ks = (__half*)(smc + OFF_K);
    __half* Vs = (__half*)(smc + OFF_V);
    __half* Rs = (__half*)(smc + OFF_R);
    float*  BDb = (float*)(smc + OFF_BD);
    const int tid = threadIdx.x, lane = tid & 31, wid = tid >> 5;
    const int g = lane >> 2, t = lane & 3;
    const int gr = wid >> 2, wg = wid & 3;
    const int gtid = tid & 127;
    const int qt = (gridDim.x - 1) - blockIdx.x;
    const int b = blockIdx.y >> 3, h = blockIdx.y & 7;
    const int s0 = qt * 64, hoff = h * 64;
    const int nkt = qt + 33;

    auto issue = [&](int kt, int st) {
        int k0 = kt * 64;
        int slot = gr * 2 + st;
#pragma unroll
        for (int p = 0; p < 4; p++) {
            int id = gtid + p * 128;
            int row = id >> 3, c = (id & 7) * 8;
            const __half* ksrc = qkv + ((size_t)(k0 + row) * Bx + b) * QKV3 + 512 + hoff + c;
            cpa16(sptr(Ks + slot * 64 * FST + row * FST + c), ksrc);
            cpa16(sptr(Vs + slot * 64 * FST + row * FST + c),
                  vt + ((size_t)(b * Ex + hoff + row)) * Kx + k0 + c);
        }
        int jlo = k0 + (Sx - 1) - s0 - 63;
#pragma unroll
        for (int p = 0; p < 8; p++) {
            int id = gtid + p * 128;
            int d = id >> 3, c = (id & 7) * 8;
            int j = jlo + d; if (j > Kx - 1) j = Kx - 1;   // clamped cells are masked
            cpa16(sptr(Rs + slot * 128 * FST + d * FST + c), rbuf + (size_t)j * Ex + hoff + c);
        }
        cpcommit();
    };

    // Q tiles via cp.async (group Q), then per-group stage prefetches
#pragma unroll
    for (int p = 0; p < 2; p++) {
        int id = tid + p * 256;
        int row = id >> 3, c = (id & 7) * 8;
        size_t src = ((size_t)(s0 + row) * Bx + b) * Ex + hoff + c;
        cpa16(sptr(Qu + row * FST + c), qu_g + src);
        cpa16(sptr(Qv + row * FST + c), qv_g + src);
    }
    cpcommit();
    issue(gr, 0);
    issue(gr + 2, 1);    // nkt >= 33 always
    cpwait<2>();         // retire Q group
    __syncthreads();

    float m0 = -1e30f, m1 = -1e30f, l0 = 0.f, l1 = 0.f;
    float O[8][4];
#pragma unroll
    for (int i = 0; i < 8; i++)
#pragma unroll
        for (int j = 0; j < 4; j++) O[i][j] = 0.f;

    float* BDrow = BDb + (wid * 16 + g) * BDW;
    const int c_base = 48 - wg * 16;
    const int limg = s0 + wg * 16 + Mx;   // min row limit in this warp

    const int r_in = lane & 7;
    const int a_row8 = ((lane >> 3) & 1) * 8;
    const int a_k8 = (lane >> 4) * 8;
    const int b_nf8 = (lane >> 4) * 8;
    const int b_k8 = ((lane >> 3) & 1) * 8;
    const unsigned qu_a = sptr(Qu + (wg * 16 + r_in + a_row8) * FST + a_k8);
    const unsigned qv_a = sptr(Qv + (wg * 16 + r_in + a_row8) * FST + a_k8);
    const unsigned k_b0 = sptr(Ks + (gr * 2) * 64 * FST + (b_nf8 + r_in) * FST + b_k8);
    const unsigned r_b0 = sptr(Rs + (gr * 2) * 128 * FST + (c_base + b_nf8 + r_in) * FST + b_k8);
    const unsigned v_b0 = sptr(Vs + (gr * 2) * 64 * FST + (b_nf8 + r_in) * FST + b_k8);

    int st = 0;
    for (int kt = gr; kt < nkt; kt += 2, st ^= 1) {
        int k0 = kt * 64;
        if (kt + 2 < nkt) cpwait<1>(); else cpwait<0>();
        barg(gr + 1);
        const unsigned k_b = k_b0 + st * KSTB;
        const unsigned r_b = r_b0 + st * RSTB;
        const unsigned v_b = v_b0 + st * KSTB;

        // ---- BD band mma: 16 x 80 per warp -> fp32 smem (pre-scaled by SCL)
        {
            float bd[10][4];
#pragma unroll
            for (int nf = 0; nf < 10; nf++)
#pragma unroll
                for (int j = 0; j < 4; j++) bd[nf][j] = 0.f;
#pragma unroll
            for (int ks = 0; ks < 4; ks++) {
                unsigned a[4];
                ldmx4(a, qv_a + ks * 32);
#pragma unroll
                for (int pr = 0; pr < 5; pr++) {
                    unsigned bb[4];
                    ldmx4(bb, r_b + pr * PRSTRIDE + ks * 32);
                    mma16(bd[2 * pr],     a, bb);
                    mma16(bd[2 * pr + 1], a, bb + 2);
                }
            }
#pragma unroll
            for (int nf = 0; nf < 10; nf++) {
                *(float2*)(BDrow + nf * 8 + 2 * t) = make_float2(bd[nf][0], bd[nf][1]);
                *(float2*)(BDrow + 8 * BDW + nf * 8 + 2 * t) = make_float2(bd[nf][2], bd[nf][3]);
            }
        }
        __syncwarp();

        // ---- AC mma seeded with the BD diagonal (combine is free) ----------
        float ac[8][4];
#pragma unroll
        for (int nf = 0; nf < 8; nf++) {
            int kc = nf * 8 + 2 * t;
            ac[nf][0] = BDrow[kc + 15 - g];
            ac[nf][1] = BDrow[kc + 16 - g];
            ac[nf][2] = BDrow[8 * BDW + kc + 7 - g];
            ac[nf][3] = BDrow[8 * BDW + kc + 8 - g];
        }
#pragma unroll
        for (int ks = 0; ks < 4; ks++) {
            unsigned a[4];
            ldmx4(a, qu_a + ks * 32);
#pragma unroll
            for (int pr = 0; pr < 4; pr++) {
                unsigned bb[4];
                ldmx4(bb, k_b + pr * PRSTRIDE + ks * 32);
                mma16(ac[2 * pr],     a, bb);
                mma16(ac[2 * pr + 1], a, bb + 2);
            }
        }

        // ---- mask only on warp-uniformly-guarded boundary tiles ------------
        if (k0 + 63 > limg) {
            int lim0 = limg + g, lim1 = lim0 + 8;
#pragma unroll
            for (int nf = 0; nf < 8; nf++) {
                int kc = nf * 8 + 2 * t;
                if (k0 + kc > lim0)     ac[nf][0] = -1e30f;
                if (k0 + kc + 1 > lim0) ac[nf][1] = -1e30f;
                if (k0 + kc > lim1)     ac[nf][2] = -1e30f;
                if (k0 + kc + 1 > lim1) ac[nf][3] = -1e30f;
            }
        }

        // ---- online softmax (base-2); P packed directly into A-fragments
        unsigned pk0[8], pk1[8];
        {
            float mx0 = -1e30f, mx1 = -1e30f;
#pragma unroll
            for (int nf = 0; nf < 8; nf++) {
                mx0 = fmaxf(mx0, fmaxf(ac[nf][0], ac[nf][1]));
                mx1 = fmaxf(mx1, fmaxf(ac[nf][2], ac[nf][3]));
            }
            mx0 = fmaxf(mx0, __shfl_xor_sync(0xffffffffu, mx0, 1));
            mx0 = fmaxf(mx0, __shfl_xor_sync(0xffffffffu, mx0, 2));
            mx1 = fmaxf(mx1, __shfl_xor_sync(0xffffffffu, mx1, 1));
            mx1 = fmaxf(mx1, __shfl_xor_sync(0xffffffffu, mx1, 2));
            float mn0 = fmaxf(m0, mx0), mn1 = fmaxf(m1, mx1);
            float c0 = ex2f(m0 - mn0), c1 = ex2f(m1 - mn1);
            float rs0 = 0.f, rs1 = 0.f;
#pragma unroll
            for (int nf = 0; nf < 8; nf++) {
                float p0 = ex2f(ac[nf][0] - mn0);
                float p1 = ex2f(ac[nf][1] - mn0);
                float p2 = ex2f(ac[nf][2] - mn1);
                float p3 = ex2f(ac[nf][3] - mn1);
                rs0 += p0 + p1; rs1 += p2 + p3;
                pk0[nf] = packh2(p0, p1);
                pk1[nf] = packh2(p2, p3);
            }
            rs0 += __shfl_xor_sync(0xffffffffu, rs0, 1);
            rs0 += __shfl_xor_sync(0xffffffffu, rs0, 2);
            rs1 += __shfl_xor_sync(0xffffffffu, rs1, 1);
            rs1 += __shfl_xor_sync(0xffffffffu, rs1, 2);
            l0 = l0 * c0 + rs0; l1 = l1 * c1 + rs1;
            m0 = mn0; m1 = mn1;
#pragma unroll
            for (int nf = 0; nf < 8; nf++) {
                O[nf][0] *= c0; O[nf][1] *= c0; O[nf][2] *= c1; O[nf][3] *= c1;
            }
        }

        // ---- P·V mma: A = P straight from registers (C-frag == A-frag)
#pragma unroll
        for (int ks = 0; ks < 4; ks++) {
            unsigned a[4] = {pk0[2 * ks], pk1[2 * ks], pk0[2 * ks + 1], pk1[2 * ks + 1]};
#pragma unroll
            for (int pr = 0; pr < 4; pr++) {
                unsigned bb[4];
                ldmx4(bb, v_b + pr * PRSTRIDE + ks * 32);
                mma16(O[2 * pr],     a, bb);
                mma16(O[2 * pr + 1], a, bb + 2);
            }
        }

        barg(gr + 1);   // group done reading stage st before it is refilled
        if (kt + 4 < nkt) issue(kt + 4, st);
    }

    // ---- merge the two groups' partial softmax states, write output --------
    __syncthreads();
    if (wid >= 4) {
#pragma unroll
        for (int nf = 0; nf < 8; nf++) {
            *(float2*)(BDrow + nf * 8 + 2 * t) = make_float2(O[nf][0], O[nf][1]);
            *(float2*)(BDrow + 8 * BDW + nf * 8 + 2 * t) = make_float2(O[nf][2], O[nf][3]);
        }
        if (t == 0) {
            BDrow[80] = m0; BDrow[81] = l0;
            BDrow[8 * BDW + 80] = m1; BDrow[8 * BDW + 81] = l1;
        }
    }
    __syncthreads();
    if (wid < 4) {
        const float* Peer = BDb + ((wid + 4) * 16 + g) * BDW;
        float pm0 = Peer[80], pl0 = Peer[81];
        float pm1 = Peer[8 * BDW + 80], pl1 = Peer[8 * BDW + 81];
        float M0 = fmaxf(m0, pm0), M1 = fmaxf(m1, pm1);
        float a0 = ex2f(m0 - M0), e0 = ex2f(pm0 - M0);
        float a1 = ex2f(m1 - M1), e1 = ex2f(pm1 - M1);
        float i0 = 1.0f / (l0 * a0 + pl0 * e0);
        float i1 = 1.0f / (l1 * a1 + pl1 * e1);
        int sg0 = s0 + wid * 16 + g;
#pragma unroll
        for (int nf = 0; nf < 8; nf++) {
            int c = hoff + nf * 8 + 2 * t;
            float2 po0 = *(const float2*)(Peer + nf * 8 + 2 * t);
            float2 po1 = *(const float2*)(Peer + 8 * BDW + nf * 8 + 2 * t);
            *(__half2*)(attn + ((size_t)sg0 * Bx + b) * Ex + c) =
                __floats2half2_rn((O[nf][0] * a0 + po0.x * e0) * i0,
                                  (O[nf][1] * a0 + po0.y * e0) * i0);
            *(__half2*)(attn + ((size_t)(sg0 + 8) * Bx + b) * Ex + c) =
                __floats2half2_rn((O[nf][2] * a1 + po1.x * e1) * i1,
                                  (O[nf][3] * a1 + po1.y * e1) * i1);
        }
    }
}

// -------- LayerNorm(X + Y [+ Y2]); optional fp16 second copy ----------------
__global__ void ln_add_kernel(const float* __restrict__ X, const float* __restrict__ Y,
                              const float* __restrict__ Y2,
                              const float* __restrict__ g, const float* __restrict__ bb,
                              float* __restrict__ out, __half* __restrict__ out_h)
{
    __shared__ float red[4];
    int row = blockIdx.x;
    int tid = threadIdx.x;
    const float4* X4 = (const float4*)(X + (size_t)row * Ex);
    const float4* Y4 = (const float4*)(Y + (size_t)row * Ex);
    float4 x = X4[tid], y = Y4[tid];
    float4 vv = {x.x + y.x, x.y + y.y, x.z + y.z, x.w + y.w};
    if (Y2) {
        float4 y2 = ((const float4*)(Y2 + (size_t)row * Ex))[tid];
        vv.x += y2.x; vv.y += y2.y; vv.z += y2.z; vv.w += y2.w;
    }
    float s = vv.x + vv.y + vv.z + vv.w;
#pragma unroll
    for (int off = 16; off; off >>= 1) s += __shfl_xor_sync(0xffffffffu, s, off);
    if ((tid & 31) == 0) red[tid >> 5] = s;
    __syncthreads();
    float mu = (red[0] + red[1] + red[2] + red[3]) * (1.f / 512.f);
    float d0 = vv.x - mu, d1 = vv.y - mu, d2 = vv.z - mu, d3 = vv.w - mu;
    float q = d0 * d0 + d1 * d1 + d2 * d2 + d3 * d3;
    __syncthreads();
#pragma unroll
    for (int off = 16; off; off >>= 1) q += __shfl_xor_sync(0xffffffffu, q, off);
    if ((tid & 31) == 0) red[tid >> 5] = q;
    __syncthreads();
    float var = (red[0] + red[1] + red[2] + red[3]) * (1.f / 512.f);
    float rs = rsqrtf(var + EPSF);
    float4 gg = ((const float4*)g)[tid], bv = ((const float4*)bb)[tid];
    float4 o;
    o.x = d0 * rs * gg.x + bv.x;
    o.y = d1 * rs * gg.y + bv.y;
    o.z = d2 * rs * gg.z + bv.z;
    o.w = d3 * rs * gg.w + bv.w;
    ((float4*)(out + (size_t)row * Ex))[tid] = o;
    if (out_h) {
        __half2* oh = (__half2*)(out_h + (size_t)row * Ex);
        oh[tid * 2]     = __floats2half2_rn(o.x, o.y);
        oh[tid * 2 + 1] = __floats2half2_rn(o.z, o.w);
    }
}

// ---------------------------------------------------------------------------
extern "C" void kernel_launch(void* const* d_in, const int* in_sizes, int n_in,
                              void* d_out, int out_size)
{
    const float* inputDec = (const float*)d_in[0];
    const float* posEmb   = (const float*)d_in[1];
    const float* u        = (const float*)d_in[2];
    const float* v        = (const float*)d_in[3];
    const float* memories = (const float*)d_in[4];
    const float* Wqkv     = (const float*)d_in[5];
    const float* Wr       = (const float*)d_in[6];
    const float* Wo       = (const float*)d_in[7];
    const float* ln1_g    = (const float*)d_in[8];
    const float* ln1_b    = (const float*)d_in[9];
    const float* W1       = (const float*)d_in[10];
    const float* b1       = (const float*)d_in[11];
    const float* W2       = (const float*)d_in[12];
    const float* b2       = (const float*)d_in[13];
    const float* ln2_g    = (const float*)d_in[14];
    const float* ln2_b    = (const float*)d_in[15];
    float* out = (float*)d_out;

    __half *qkv, *rb, *vt, *qu, *qv, *attn, *attnout_h, *ff1;
    __half *mem_h, *inp_h, *pos_h, *wqkv_t, *wr_t, *wo_t, *w1_t, *w2_t;
    float *tmp, *attnout, *ff2;
    cudaGetSymbolAddress((void**)&qkv,       g_qkv);
    cudaGetSymbolAddress((void**)&rb,        g_rb);
    cudaGetSymbolAddress((void**)&vt,        g_vt);
    cudaGetSymbolAddress((void**)&qu,        g_qu);
    cudaGetSymbolAddress((void**)&qv,        g_qv);
    cudaGetSymbolAddress((void**)&attn,      g_attn);
    cudaGetSymbolAddress((void**)&tmp,       g_tmp);
    cudaGetSymbolAddress((void**)&attnout,   g_attnout);
    cudaGetSymbolAddress((void**)&attnout_h, g_attnout_h);
    cudaGetSymbolAddress((void**)&ff1,       g_ff1);
    cudaGetSymbolAddress((void**)&ff2,       g_ff2);
    cudaGetSymbolAddress((void**)&mem_h,     g_mem_h);
    cudaGetSymbolAddress((void**)&inp_h,     g_inp_h);
    cudaGetSymbolAddress((void**)&pos_h,     g_pos_h);
    cudaGetSymbolAddress((void**)&wqkv_t,    g_wqkv_t);
    cudaGetSymbolAddress((void**)&wr_t,      g_wr_t);
    cudaGetSymbolAddress((void**)&wo_t,      g_wo_t);
    cudaGetSymbolAddress((void**)&w1_t,      g_w1_t);
    cudaGetSymbolAddress((void**)&w2_t,      g_w2_t);

    cudaFuncSetAttribute(flash, cudaFuncAttributeMaxDynamicSharedMemorySize, FLASH_SMEM);
    cudaFuncSetAttribute(tgemm<0,true,true>,   cudaFuncAttributeMaxDynamicSharedMemorySize, GEMM_SMEM);
    cudaFuncSetAttribute(tgemm<0,false,true>,  cudaFuncAttributeMaxDynamicSharedMemorySize, GEMM_SMEM);
    cudaFuncSetAttribute(tgemm<0,false,false>, cudaFuncAttributeMaxDynamicSharedMemorySize, GEMM_SMEM);
    cudaFuncSetAttribute(tgemm<2,false,true>,  cudaFuncAttributeMaxDynamicSharedMemorySize, GEMM_SMEM);
    cudaFuncSetAttribute(tgemm<1,false,false>, cudaFuncAttributeMaxDynamicSharedMemorySize, GEMM_SMEM);

    // 0a) activations fp32 -> fp16
    {
        CSegs cs;
        cs.src[0] = (const float4*)memories; cs.dst[0] = (uint2*)mem_h;
        cs.n4[0] = (int)((size_t)Mx * Bx * Ex / 4);
        cs.src[1] = (const float4*)inputDec; cs.dst[1] = (uint2*)inp_h;
        cs.n4[1] = (int)((size_t)Sx * Bx * Ex / 4);
        cs.src[2] = (const float4*)posEmb;   cs.dst[2] = (uint2*)pos_h;
        cs.n4[2] = (int)((size_t)Kx * Ex / 4);
        int maxb = 0;
        for (int i = 0; i < 3; i++) { int bl = (cs.n4[i] + 255) / 256; if (bl > maxb) maxb = bl; }
        cvtall<<<dim3(maxb, 3), 256>>>(cs);
    }
    // 0b) all 5 weight transposes in ONE launch
    {
        TSegs ts;
        const float* Ws[5] = {Wqkv, Wr, Wo, W1, W2};
        __half* Wts[5] = {wqkv_t, wr_t, wo_t, w1_t, w2_t};
        int Ks[5] = {Ex, Ex, Ex, Ex, FFx};
        int Ns[5] = {QKV3, Ex, Ex, FFx, Ex};
        int c = 0;
        ts.cum[0] = 0;
        for (int i = 0; i < 5; i++) {
            ts.W[i] = Ws[i]; ts.Wt[i] = Wts[i];
            ts.K[i] = Ks[i]; ts.N[i] = Ns[i];
            ts.tilesN[i] = Ns[i] / 32;
            c += (Ks[i] / 32) * (Ns[i] / 32);
            ts.cum[i + 1] = c;
        }
        transw_all<<<c, dim3(32, 8)>>>(ts);
    }

    const size_t HALF_OUT = (size_t)ROWS * Ex * sizeof(float);

    // 1) qkv GEMM
    tgemm<0,true,true><<<dim3(QKV3/128, KB_/128, 1), 256, GEMM_SMEM>>>(
        mem_h, inp_h, Mx * Bx, wqkv_t, nullptr, qkv, QKV3, Ex, Ex, 0);
    // 2) r GEMM
    tgemm<0,false,true><<<dim3(Ex/128, Kx/128, 1), 256, GEMM_SMEM>>>(
        pos_h, nullptr, 0, wr_t, nullptr, rb, Ex, Ex, Ex, 0);
    // 2b) V transpose + Q prep (SCL folded)
    vtrans<<<dim3(Kx/32, Ex/32, Bx), dim3(32,8)>>>(qkv, vt);
    qprep<<<ROWS, 256>>>(qkv, u, v, qu, qv);
    // 3) flash attention
    flash<<<dim3(Sx/64, Bx*Hx), 256, FLASH_SMEM>>>(qkv, rb, vt, qu, qv, attn);
    // 4) attn @ Wo  (split-K x2 -> two partial buffers)
    tgemm<0,false,false><<<dim3(Ex/128, ROWS/128, 2), 256, GEMM_SMEM>>>(
        attn, nullptr, 0, wo_t, nullptr, tmp, Ex, Ex, Ex/2, HALF_OUT);
    // 5) attn_out = LN(inputDec + woA + woB)
    ln_add_kernel<<<ROWS, 128>>>(inputDec, tmp, tmp + (size_t)ROWS * Ex,
                                 ln1_g, ln1_b, attnout, attnout_h);
    // 6) ff1 = relu(attn_out @ W1 + b1)
    tgemm<2,false,true><<<dim3(FFx/128, ROWS/128, 1), 256, GEMM_SMEM>>>(
        attnout_h, nullptr, 0, w1_t, b1, ff1, FFx, Ex, Ex, 0);
    // 7) ff2 = ff1 @ W2 + b2  (split-K x2)
    tgemm<1,false,false><<<dim3(Ex/128, ROWS/128, 2), 256, GEMM_SMEM>>>(
        ff1, nullptr, 0, w2_t, b2, ff2, Ex, FFx, FFx/2, HALF_OUT);
    // 8) out = LN(attn_out + ff2A + ff2B)
    ln_add_kernel<<<ROWS, 128>>>(attnout, ff2, ff2 + (size_t)ROWS * Ex,
                                 ln2_g, ln2_b, out, nullptr);
}